// round 1
// baseline (speedup 1.0000x reference)
#include <cuda_runtime.h>
#include <cuda_bf16.h>
#include <math.h>

#define SEQ 2048
#define DIM 4096
#define NH 32
#define NKV 8
#define HD 128
#define KVDIM 1024

// Scratch (allocation-free rule: device globals)
__device__ float g_Q[SEQ * DIM];
__device__ float g_K[SEQ * KVDIM];
__device__ float g_V[SEQ * KVDIM];
__device__ float g_attn[SEQ * DIM];

// ---------------------------------------------------------------------------
// Tiled FP32 SGEMM: C[M,N] = A[M,K] @ B[K,N], all row-major.
// BM=BN=64, BK=16, 256 threads, 4x4 microtile per thread.
// Requires M%64==0, N%64==0, K%16==0 (true for all calls here).
// ---------------------------------------------------------------------------
#define BM 64
#define BN 64
#define BK 16
#define ASTR 68   // padded smem row stride (floats)

__global__ __launch_bounds__(256) void sgemm_kernel(
    const float* __restrict__ A, const float* __restrict__ B,
    float* __restrict__ C, int M, int N, int K)
{
    __shared__ float As[BK * ASTR];   // As[k][m]
    __shared__ float Bs[BK * ASTR];   // Bs[k][n]

    int tid = threadIdx.x;
    int tx = tid & 15, ty = tid >> 4;
    int m0 = blockIdx.y * BM, n0 = blockIdx.x * BN;

    int am = tid >> 2, ak = (tid & 3) << 2;      // A loader: row am, 4 k's
    int bk = tid >> 4, bn = (tid & 15) << 2;     // B loader: row bk, 4 n's

    float acc[4][4] = {};

    for (int k0 = 0; k0 < K; k0 += BK) {
        float4 av = *(const float4*)&A[(size_t)(m0 + am) * K + k0 + ak];
        As[(ak + 0) * ASTR + am] = av.x;
        As[(ak + 1) * ASTR + am] = av.y;
        As[(ak + 2) * ASTR + am] = av.z;
        As[(ak + 3) * ASTR + am] = av.w;
        *(float4*)&Bs[bk * ASTR + bn] =
            *(const float4*)&B[(size_t)(k0 + bk) * N + n0 + bn];
        __syncthreads();

        #pragma unroll
        for (int kk = 0; kk < BK; kk++) {
            float4 a4 = *(const float4*)&As[kk * ASTR + ty * 4];
            float4 b4 = *(const float4*)&Bs[kk * ASTR + tx * 4];
            float a[4] = {a4.x, a4.y, a4.z, a4.w};
            float b[4] = {b4.x, b4.y, b4.z, b4.w};
            #pragma unroll
            for (int r = 0; r < 4; r++)
                #pragma unroll
                for (int c = 0; c < 4; c++)
                    acc[r][c] = fmaf(a[r], b[c], acc[r][c]);
        }
        __syncthreads();
    }

    #pragma unroll
    for (int r = 0; r < 4; r++) {
        float4 v = make_float4(acc[r][0], acc[r][1], acc[r][2], acc[r][3]);
        *(float4*)&C[(size_t)(m0 + ty * 4 + r) * N + n0 + tx * 4] = v;
    }
}

// ---------------------------------------------------------------------------
// RoPE (interleaved pairs), in place. One thread per (s, h, i) pair.
// ---------------------------------------------------------------------------
__global__ void rope_kernel(float* __restrict__ t, const float* __restrict__ cs,
                            const float* __restrict__ sn, int H, int rowstride,
                            int total)
{
    int idx = blockIdx.x * blockDim.x + threadIdx.x;
    if (idx >= total) return;
    int i = idx & 63;
    int tmp = idx >> 6;
    int h = tmp % H;
    int s = tmp / H;
    float c = cs[s * 64 + i];
    float si = sn[s * 64 + i];
    float* p = t + (size_t)s * rowstride + h * HD + 2 * i;
    float re = p[0], im = p[1];
    p[0] = re * c - im * si;
    p[1] = re * si + im * c;
}

// ---------------------------------------------------------------------------
// Flash attention, fp32, online softmax. 64x64 tiles, causal, GQA.
// Block: 256 threads (16x16). Row tile = blockIdx.x, head = blockIdx.y.
// Thread owns rows i = ty + 16r (r<4), S-cols j = tx + 16c (c<4),
// O-cols d = tx + 16c (c<8).
// ---------------------------------------------------------------------------
#define QSTR 132   // padded stride for Q/K/V 128-wide tiles
#define SSTR 68    // padded stride for 64-wide P tile

__global__ __launch_bounds__(256, 2) void flash_kernel(
    const float* __restrict__ Q, const float* __restrict__ K,
    const float* __restrict__ V, float* __restrict__ O)
{
    extern __shared__ float sm[];
    float* Qs  = sm;                  // [64][QSTR]
    float* KVs = sm + 64 * QSTR;      // [64][QSTR]  (K tile, then reused for V)
    float* Ss  = KVs + 64 * QSTR;     // [64][SSTR]  (probabilities)

    int tid = threadIdx.x;
    int tx = tid & 15, ty = tid >> 4;
    int r0 = blockIdx.x * 64;
    int h = blockIdx.y;
    int kvh = h >> 2;
    const float scale = 0.08838834764831845f;  // 1/sqrt(128)

    // Load Q tile (pre-scaled)
    for (int t = tid; t < 64 * HD / 4; t += 256) {
        int row = t >> 5, c4 = (t & 31) << 2;
        float4 v = *(const float4*)&Q[(size_t)(r0 + row) * DIM + h * HD + c4];
        v.x *= scale; v.y *= scale; v.z *= scale; v.w *= scale;
        *(float4*)&Qs[row * QSTR + c4] = v;
    }

    float m[4], l[4], o[4][8];
    #pragma unroll
    for (int r = 0; r < 4; r++) {
        m[r] = -1e30f; l[r] = 0.f;
        #pragma unroll
        for (int c = 0; c < 8; c++) o[r][c] = 0.f;
    }

    int diag = blockIdx.x;
    for (int kt = 0; kt <= diag; kt++) {
        int c0 = kt * 64;
        __syncthreads();   // previous PV done with KVs/Ss
        for (int t = tid; t < 64 * HD / 4; t += 256) {
            int row = t >> 5, c4 = (t & 31) << 2;
            *(float4*)&KVs[row * QSTR + c4] =
                *(const float4*)&K[(size_t)(c0 + row) * KVDIM + kvh * HD + c4];
        }
        __syncthreads();

        // S = Qs @ Ks^T (already scaled)
        float s[4][4];
        #pragma unroll
        for (int r = 0; r < 4; r++)
            #pragma unroll
            for (int c = 0; c < 4; c++) s[r][c] = 0.f;

        #pragma unroll 4
        for (int d = 0; d < HD; d += 4) {
            float4 qa[4], kb[4];
            #pragma unroll
            for (int r = 0; r < 4; r++)
                qa[r] = *(const float4*)&Qs[(ty + 16 * r) * QSTR + d];
            #pragma unroll
            for (int c = 0; c < 4; c++)
                kb[c] = *(const float4*)&KVs[(tx + 16 * c) * QSTR + d];
            #pragma unroll
            for (int r = 0; r < 4; r++)
                #pragma unroll
                for (int c = 0; c < 4; c++) {
                    s[r][c] = fmaf(qa[r].x, kb[c].x, s[r][c]);
                    s[r][c] = fmaf(qa[r].y, kb[c].y, s[r][c]);
                    s[r][c] = fmaf(qa[r].z, kb[c].z, s[r][c]);
                    s[r][c] = fmaf(qa[r].w, kb[c].w, s[r][c]);
                }
        }

        // Causal mask on the diagonal tile (r0 == c0 there)
        if (kt == diag) {
            #pragma unroll
            for (int r = 0; r < 4; r++)
                #pragma unroll
                for (int c = 0; c < 4; c++)
                    if (tx + 16 * c > ty + 16 * r) s[r][c] = -1e30f;
        }

        // Online softmax (row groups = 16 lanes sharing ty; xor<=8 stays in-group)
        #pragma unroll
        for (int r = 0; r < 4; r++) {
            float mx = fmaxf(fmaxf(s[r][0], s[r][1]), fmaxf(s[r][2], s[r][3]));
            #pragma unroll
            for (int off = 8; off >= 1; off >>= 1)
                mx = fmaxf(mx, __shfl_xor_sync(0xffffffffu, mx, off));
            float mnew = fmaxf(m[r], mx);
            float corr = __expf(m[r] - mnew);
            float psum = 0.f;
            #pragma unroll
            for (int c = 0; c < 4; c++) {
                s[r][c] = __expf(s[r][c] - mnew);
                psum += s[r][c];
            }
            #pragma unroll
            for (int off = 8; off >= 1; off >>= 1)
                psum += __shfl_xor_sync(0xffffffffu, psum, off);
            l[r] = l[r] * corr + psum;
            m[r] = mnew;
            #pragma unroll
            for (int c = 0; c < 8; c++) o[r][c] *= corr;
            #pragma unroll
            for (int c = 0; c < 4; c++)
                Ss[(ty + 16 * r) * SSTR + tx + 16 * c] = s[r][c];
        }

        __syncthreads();   // P written, everyone done reading K tile
        for (int t = tid; t < 64 * HD / 4; t += 256) {
            int row = t >> 5, c4 = (t & 31) << 2;
            *(float4*)&KVs[row * QSTR + c4] =
                *(const float4*)&V[(size_t)(c0 + row) * KVDIM + kvh * HD + c4];
        }
        __syncthreads();

        // O += P @ V
        #pragma unroll 4
        for (int j = 0; j < 64; j++) {
            float pr[4];
            #pragma unroll
            for (int r = 0; r < 4; r++)
                pr[r] = Ss[(ty + 16 * r) * SSTR + j];
            #pragma unroll
            for (int c = 0; c < 8; c++) {
                float vv = KVs[j * QSTR + tx + 16 * c];
                #pragma unroll
                for (int r = 0; r < 4; r++)
                    o[r][c] = fmaf(pr[r], vv, o[r][c]);
            }
        }
    }

    // Finalize and store: attn[s][h*128 + d]
    #pragma unroll
    for (int r = 0; r < 4; r++) {
        float inv = 1.f / l[r];
        #pragma unroll
        for (int c = 0; c < 8; c++)
            O[(size_t)(r0 + ty + 16 * r) * DIM + h * HD + tx + 16 * c] =
                o[r][c] * inv;
    }
}

// ---------------------------------------------------------------------------
// Launch
// ---------------------------------------------------------------------------
extern "C" void kernel_launch(void* const* d_in, const int* in_sizes, int n_in,
                              void* d_out, int out_size)
{
    const float* x  = (const float*)d_in[0];
    const float* wq = (const float*)d_in[1];
    const float* wk = (const float*)d_in[2];
    const float* wv = (const float*)d_in[3];
    const float* wo = (const float*)d_in[4];
    const float* fc = (const float*)d_in[5];
    const float* fs = (const float*)d_in[6];
    // d_in[7] = mask (causal, known), d_in[8] = start_pos (0) -- unused

    float *Qp, *Kp, *Vp, *Ap;
    cudaGetSymbolAddress((void**)&Qp, g_Q);
    cudaGetSymbolAddress((void**)&Kp, g_K);
    cudaGetSymbolAddress((void**)&Vp, g_V);
    cudaGetSymbolAddress((void**)&Ap, g_attn);

    // Projections
    sgemm_kernel<<<dim3(DIM / BN, SEQ / BM), 256>>>(x, wq, Qp, SEQ, DIM, DIM);
    sgemm_kernel<<<dim3(KVDIM / BN, SEQ / BM), 256>>>(x, wk, Kp, SEQ, KVDIM, DIM);
    sgemm_kernel<<<dim3(KVDIM / BN, SEQ / BM), 256>>>(x, wv, Vp, SEQ, KVDIM, DIM);

    // RoPE on Q and K
    int totQ = SEQ * NH * 64, totK = SEQ * NKV * 64;
    rope_kernel<<<(totQ + 255) / 256, 256>>>(Qp, fc, fs, NH, DIM, totQ);
    rope_kernel<<<(totK + 255) / 256, 256>>>(Kp, fc, fs, NKV, KVDIM, totK);

    // Flash attention
    int smem = (64 * QSTR * 2 + 64 * SSTR) * (int)sizeof(float);
    cudaFuncSetAttribute(flash_kernel,
                         cudaFuncAttributeMaxDynamicSharedMemorySize, smem);
    flash_kernel<<<dim3(SEQ / 64, NH), 256, smem>>>(Qp, Kp, Vp, Ap);

    // Output projection -> d_out
    sgemm_kernel<<<dim3(DIM / BN, SEQ / BM), 256>>>(Ap, wo, (float*)d_out,
                                                    SEQ, DIM, DIM);
}

// round 2
// speedup vs baseline: 2.1529x; 2.1529x over previous
#include <cuda_runtime.h>
#include <cuda_bf16.h>
#include <math.h>
#include <stdint.h>

#define SEQ 2048
#define DIM 4096
#define NH 32
#define NKV 8
#define HD 128
#define KVDIM 1024

// Scratch (allocation-free rule: device globals)
__device__ float g_Q[SEQ * DIM];
__device__ float g_K[SEQ * KVDIM];
__device__ float g_V[SEQ * KVDIM];
__device__ float g_attn[SEQ * DIM];

// ---------------------------------------------------------------------------
// TF32 tensor-core GEMM: C[M,N] = A[M,K] @ B[K,N], row-major fp32 in/out.
// CTA tile 128x128x32, 8 warps (4x2), warp tile 32x64, mma.m16n8k8.tf32.
// Requires M%128==0, N%128==0, K%32==0 (true for all calls here).
// ---------------------------------------------------------------------------
#define GBM 128
#define GBN 128
#define GBK 32
#define ASTR 36    // As[m][k] stride (floats) -> conflict-free frag loads
#define BSTR 136   // Bs[k][n] stride (floats) -> conflict-free frag loads

__device__ __forceinline__ uint32_t f2tf32(float x) {
    uint32_t u;
    asm("cvt.rna.tf32.f32 %0, %1;" : "=r"(u) : "f"(x));
    return u;
}

__device__ __forceinline__ void mma_tf32(float c[4], const uint32_t a[4],
                                         const uint32_t b[2]) {
    asm volatile(
        "mma.sync.aligned.m16n8k8.row.col.f32.tf32.tf32.f32 "
        "{%0,%1,%2,%3}, {%4,%5,%6,%7}, {%8,%9}, {%0,%1,%2,%3};"
        : "+f"(c[0]), "+f"(c[1]), "+f"(c[2]), "+f"(c[3])
        : "r"(a[0]), "r"(a[1]), "r"(a[2]), "r"(a[3]), "r"(b[0]), "r"(b[1]));
}

__global__ __launch_bounds__(256, 2) void gemm_tf32_kernel(
    const float* __restrict__ A, const float* __restrict__ B,
    float* __restrict__ C, int M, int N, int K)
{
    __shared__ uint32_t As[GBM * ASTR];   // [m][k]
    __shared__ uint32_t Bs[GBK * BSTR];   // [k][n]

    int tid = threadIdx.x;
    int wid = tid >> 5, lane = tid & 31;
    int g = lane >> 2, tg = lane & 3;
    int warp_m = (wid >> 1) * 32;
    int warp_n = (wid & 1) * 64;
    int m0 = blockIdx.y * GBM, n0 = blockIdx.x * GBN;

    float acc[2][8][4];
    #pragma unroll
    for (int mt = 0; mt < 2; mt++)
        #pragma unroll
        for (int nt = 0; nt < 8; nt++)
            #pragma unroll
            for (int i = 0; i < 4; i++) acc[mt][nt][i] = 0.f;

    for (int kc = 0; kc < K; kc += GBK) {
        // Load A tile 128x32 (4 float4 per thread), convert to tf32
        #pragma unroll
        for (int i = 0; i < 4; i++) {
            int lin = tid + i * 256;            // 0..1023 float4 slots
            int m = lin >> 3, k4 = (lin & 7) << 2;
            float4 v = *(const float4*)&A[(size_t)(m0 + m) * K + kc + k4];
            uint32_t* p = &As[m * ASTR + k4];
            p[0] = f2tf32(v.x); p[1] = f2tf32(v.y);
            p[2] = f2tf32(v.z); p[3] = f2tf32(v.w);
        }
        // Load B tile 32x128
        #pragma unroll
        for (int i = 0; i < 4; i++) {
            int lin = tid + i * 256;
            int kk = lin >> 5, n4 = (lin & 31) << 2;
            float4 v = *(const float4*)&B[(size_t)(kc + kk) * N + n0 + n4];
            uint32_t* p = &Bs[kk * BSTR + n4];
            p[0] = f2tf32(v.x); p[1] = f2tf32(v.y);
            p[2] = f2tf32(v.z); p[3] = f2tf32(v.w);
        }
        __syncthreads();

        #pragma unroll
        for (int ks = 0; ks < 4; ks++) {
            int k0 = ks * 8;
            uint32_t aR[2][4];
            #pragma unroll
            for (int mt = 0; mt < 2; mt++) {
                int m = warp_m + mt * 16 + g;
                aR[mt][0] = As[m * ASTR + k0 + tg];
                aR[mt][1] = As[(m + 8) * ASTR + k0 + tg];
                aR[mt][2] = As[m * ASTR + k0 + tg + 4];
                aR[mt][3] = As[(m + 8) * ASTR + k0 + tg + 4];
            }
            uint32_t bR[8][2];
            #pragma unroll
            for (int nt = 0; nt < 8; nt++) {
                int n = warp_n + nt * 8 + g;
                bR[nt][0] = Bs[(k0 + tg) * BSTR + n];
                bR[nt][1] = Bs[(k0 + tg + 4) * BSTR + n];
            }
            #pragma unroll
            for (int mt = 0; mt < 2; mt++)
                #pragma unroll
                for (int nt = 0; nt < 8; nt++)
                    mma_tf32(acc[mt][nt], aR[mt], bR[nt]);
        }
        __syncthreads();
    }

    // Store C: c0/c1 at (row, 2*tg), c2/c3 at (row+8, 2*tg)
    #pragma unroll
    for (int mt = 0; mt < 2; mt++) {
        int m = m0 + warp_m + mt * 16 + g;
        #pragma unroll
        for (int nt = 0; nt < 8; nt++) {
            int n = n0 + warp_n + nt * 8 + 2 * tg;
            *(float2*)&C[(size_t)m * N + n] =
                make_float2(acc[mt][nt][0], acc[mt][nt][1]);
            *(float2*)&C[(size_t)(m + 8) * N + n] =
                make_float2(acc[mt][nt][2], acc[mt][nt][3]);
        }
    }
}

// ---------------------------------------------------------------------------
// RoPE (interleaved pairs), in place. One thread per (s, h, i) pair.
// ---------------------------------------------------------------------------
__global__ void rope_kernel(float* __restrict__ t, const float* __restrict__ cs,
                            const float* __restrict__ sn, int H, int rowstride,
                            int total)
{
    int idx = blockIdx.x * blockDim.x + threadIdx.x;
    if (idx >= total) return;
    int i = idx & 63;
    int tmp = idx >> 6;
    int h = tmp % H;
    int s = tmp / H;
    float c = cs[s * 64 + i];
    float si = sn[s * 64 + i];
    float* p = t + (size_t)s * rowstride + h * HD + 2 * i;
    float re = p[0], im = p[1];
    p[0] = re * c - im * si;
    p[1] = re * si + im * c;
}

// ---------------------------------------------------------------------------
// Flash attention, fp32, online softmax. 64x64 tiles, causal, GQA.
// ---------------------------------------------------------------------------
#define QSTR 132   // padded stride for Q/K/V 128-wide tiles
#define SSTR 68    // padded stride for 64-wide P tile

__global__ __launch_bounds__(256, 2) void flash_kernel(
    const float* __restrict__ Q, const float* __restrict__ K,
    const float* __restrict__ V, float* __restrict__ O)
{
    extern __shared__ float sm[];
    float* Qs  = sm;                  // [64][QSTR]
    float* KVs = sm + 64 * QSTR;      // [64][QSTR]  (K tile, then reused for V)
    float* Ss  = KVs + 64 * QSTR;     // [64][SSTR]  (probabilities)

    int tid = threadIdx.x;
    int tx = tid & 15, ty = tid >> 4;
    int r0 = blockIdx.x * 64;
    int h = blockIdx.y;
    int kvh = h >> 2;
    const float scale = 0.08838834764831845f;  // 1/sqrt(128)

    for (int t = tid; t < 64 * HD / 4; t += 256) {
        int row = t >> 5, c4 = (t & 31) << 2;
        float4 v = *(const float4*)&Q[(size_t)(r0 + row) * DIM + h * HD + c4];
        v.x *= scale; v.y *= scale; v.z *= scale; v.w *= scale;
        *(float4*)&Qs[row * QSTR + c4] = v;
    }

    float m[4], l[4], o[4][8];
    #pragma unroll
    for (int r = 0; r < 4; r++) {
        m[r] = -1e30f; l[r] = 0.f;
        #pragma unroll
        for (int c = 0; c < 8; c++) o[r][c] = 0.f;
    }

    int diag = blockIdx.x;
    for (int kt = 0; kt <= diag; kt++) {
        int c0 = kt * 64;
        __syncthreads();
        for (int t = tid; t < 64 * HD / 4; t += 256) {
            int row = t >> 5, c4 = (t & 31) << 2;
            *(float4*)&KVs[row * QSTR + c4] =
                *(const float4*)&K[(size_t)(c0 + row) * KVDIM + kvh * HD + c4];
        }
        __syncthreads();

        float s[4][4];
        #pragma unroll
        for (int r = 0; r < 4; r++)
            #pragma unroll
            for (int c = 0; c < 4; c++) s[r][c] = 0.f;

        #pragma unroll 4
        for (int d = 0; d < HD; d += 4) {
            float4 qa[4], kb[4];
            #pragma unroll
            for (int r = 0; r < 4; r++)
                qa[r] = *(const float4*)&Qs[(ty + 16 * r) * QSTR + d];
            #pragma unroll
            for (int c = 0; c < 4; c++)
                kb[c] = *(const float4*)&KVs[(tx + 16 * c) * QSTR + d];
            #pragma unroll
            for (int r = 0; r < 4; r++)
                #pragma unroll
                for (int c = 0; c < 4; c++) {
                    s[r][c] = fmaf(qa[r].x, kb[c].x, s[r][c]);
                    s[r][c] = fmaf(qa[r].y, kb[c].y, s[r][c]);
                    s[r][c] = fmaf(qa[r].z, kb[c].z, s[r][c]);
                    s[r][c] = fmaf(qa[r].w, kb[c].w, s[r][c]);
                }
        }

        if (kt == diag) {
            #pragma unroll
            for (int r = 0; r < 4; r++)
                #pragma unroll
                for (int c = 0; c < 4; c++)
                    if (tx + 16 * c > ty + 16 * r) s[r][c] = -1e30f;
        }

        #pragma unroll
        for (int r = 0; r < 4; r++) {
            float mx = fmaxf(fmaxf(s[r][0], s[r][1]), fmaxf(s[r][2], s[r][3]));
            #pragma unroll
            for (int off = 8; off >= 1; off >>= 1)
                mx = fmaxf(mx, __shfl_xor_sync(0xffffffffu, mx, off));
            float mnew = fmaxf(m[r], mx);
            float corr = __expf(m[r] - mnew);
            float psum = 0.f;
            #pragma unroll
            for (int c = 0; c < 4; c++) {
                s[r][c] = __expf(s[r][c] - mnew);
                psum += s[r][c];
            }
            #pragma unroll
            for (int off = 8; off >= 1; off >>= 1)
                psum += __shfl_xor_sync(0xffffffffu, psum, off);
            l[r] = l[r] * corr + psum;
            m[r] = mnew;
            #pragma unroll
            for (int c = 0; c < 8; c++) o[r][c] *= corr;
            #pragma unroll
            for (int c = 0; c < 4; c++)
                Ss[(ty + 16 * r) * SSTR + tx + 16 * c] = s[r][c];
        }

        __syncthreads();
        for (int t = tid; t < 64 * HD / 4; t += 256) {
            int row = t >> 5, c4 = (t & 31) << 2;
            *(float4*)&KVs[row * QSTR + c4] =
                *(const float4*)&V[(size_t)(c0 + row) * KVDIM + kvh * HD + c4];
        }
        __syncthreads();

        #pragma unroll 4
        for (int j = 0; j < 64; j++) {
            float pr[4];
            #pragma unroll
            for (int r = 0; r < 4; r++)
                pr[r] = Ss[(ty + 16 * r) * SSTR + j];
            #pragma unroll
            for (int c = 0; c < 8; c++) {
                float vv = KVs[j * QSTR + tx + 16 * c];
                #pragma unroll
                for (int r = 0; r < 4; r++)
                    o[r][c] = fmaf(pr[r], vv, o[r][c]);
            }
        }
    }

    #pragma unroll
    for (int r = 0; r < 4; r++) {
        float inv = 1.f / l[r];
        #pragma unroll
        for (int c = 0; c < 8; c++)
            O[(size_t)(r0 + ty + 16 * r) * DIM + h * HD + tx + 16 * c] =
                o[r][c] * inv;
    }
}

// ---------------------------------------------------------------------------
// Launch
// ---------------------------------------------------------------------------
extern "C" void kernel_launch(void* const* d_in, const int* in_sizes, int n_in,
                              void* d_out, int out_size)
{
    const float* x  = (const float*)d_in[0];
    const float* wq = (const float*)d_in[1];
    const float* wk = (const float*)d_in[2];
    const float* wv = (const float*)d_in[3];
    const float* wo = (const float*)d_in[4];
    const float* fc = (const float*)d_in[5];
    const float* fs = (const float*)d_in[6];

    float *Qp, *Kp, *Vp, *Ap;
    cudaGetSymbolAddress((void**)&Qp, g_Q);
    cudaGetSymbolAddress((void**)&Kp, g_K);
    cudaGetSymbolAddress((void**)&Vp, g_V);
    cudaGetSymbolAddress((void**)&Ap, g_attn);

    // Projections (TF32 tensor cores)
    gemm_tf32_kernel<<<dim3(DIM / GBN, SEQ / GBM), 256>>>(x, wq, Qp, SEQ, DIM, DIM);
    gemm_tf32_kernel<<<dim3(KVDIM / GBN, SEQ / GBM), 256>>>(x, wk, Kp, SEQ, KVDIM, DIM);
    gemm_tf32_kernel<<<dim3(KVDIM / GBN, SEQ / GBM), 256>>>(x, wv, Vp, SEQ, KVDIM, DIM);

    // RoPE on Q and K
    int totQ = SEQ * NH * 64, totK = SEQ * NKV * 64;
    rope_kernel<<<(totQ + 255) / 256, 256>>>(Qp, fc, fs, NH, DIM, totQ);
    rope_kernel<<<(totK + 255) / 256, 256>>>(Kp, fc, fs, NKV, KVDIM, totK);

    // Flash attention (fp32)
    int smem = (64 * QSTR * 2 + 64 * SSTR) * (int)sizeof(float);
    cudaFuncSetAttribute(flash_kernel,
                         cudaFuncAttributeMaxDynamicSharedMemorySize, smem);
    flash_kernel<<<dim3(SEQ / 64, NH), 256, smem>>>(Qp, Kp, Vp, Ap);

    // Output projection -> d_out (TF32 tensor cores)
    gemm_tf32_kernel<<<dim3(DIM / GBN, SEQ / GBM), 256>>>(Ap, wo, (float*)d_out,
                                                          SEQ, DIM, DIM);
}

// round 3
// speedup vs baseline: 2.9262x; 1.3592x over previous
#include <cuda_runtime.h>
#include <cuda_bf16.h>
#include <math.h>
#include <stdint.h>

#define SEQ 2048
#define DIM 4096
#define NH 32
#define NKV 8
#define HD 128
#define KVDIM 1024

// Scratch (allocation-free rule: device globals)
__device__ float g_Q[SEQ * DIM];
__device__ float g_K[SEQ * KVDIM];
__device__ float g_V[SEQ * KVDIM];
__device__ float g_attn[SEQ * DIM];

__device__ __forceinline__ uint32_t f2tf32(float x) {
    uint32_t u;
    asm("cvt.rna.tf32.f32 %0, %1;" : "=r"(u) : "f"(x));
    return u;
}

__device__ __forceinline__ void mma_tf32(float c[4], const uint32_t a[4],
                                         const uint32_t b[2]) {
    asm volatile(
        "mma.sync.aligned.m16n8k8.row.col.f32.tf32.tf32.f32 "
        "{%0,%1,%2,%3}, {%4,%5,%6,%7}, {%8,%9}, {%0,%1,%2,%3};"
        : "+f"(c[0]), "+f"(c[1]), "+f"(c[2]), "+f"(c[3])
        : "r"(a[0]), "r"(a[1]), "r"(a[2]), "r"(a[3]), "r"(b[0]), "r"(b[1]));
}

// ---------------------------------------------------------------------------
// TF32 tensor-core GEMM: C[M,N] = A[M,K] @ B[K,N], row-major fp32 in/out.
// CTA tile 128x128x32, 8 warps, warp tile 32x64.
// ---------------------------------------------------------------------------
#define GBM 128
#define GBN 128
#define GBK 32
#define ASTR 36
#define BSTR 136

__global__ __launch_bounds__(256, 2) void gemm_tf32_kernel(
    const float* __restrict__ A, const float* __restrict__ B,
    float* __restrict__ C, int M, int N, int K)
{
    __shared__ uint32_t As[GBM * ASTR];   // [m][k]
    __shared__ uint32_t Bs[GBK * BSTR];   // [k][n]

    int tid = threadIdx.x;
    int wid = tid >> 5, lane = tid & 31;
    int g = lane >> 2, tg = lane & 3;
    int warp_m = (wid >> 1) * 32;
    int warp_n = (wid & 1) * 64;
    int m0 = blockIdx.y * GBM, n0 = blockIdx.x * GBN;

    float acc[2][8][4];
    #pragma unroll
    for (int mt = 0; mt < 2; mt++)
        #pragma unroll
        for (int nt = 0; nt < 8; nt++)
            #pragma unroll
            for (int i = 0; i < 4; i++) acc[mt][nt][i] = 0.f;

    for (int kc = 0; kc < K; kc += GBK) {
        #pragma unroll
        for (int i = 0; i < 4; i++) {
            int lin = tid + i * 256;
            int m = lin >> 3, k4 = (lin & 7) << 2;
            float4 v = *(const float4*)&A[(size_t)(m0 + m) * K + kc + k4];
            uint32_t* p = &As[m * ASTR + k4];
            p[0] = f2tf32(v.x); p[1] = f2tf32(v.y);
            p[2] = f2tf32(v.z); p[3] = f2tf32(v.w);
        }
        #pragma unroll
        for (int i = 0; i < 4; i++) {
            int lin = tid + i * 256;
            int kk = lin >> 5, n4 = (lin & 31) << 2;
            float4 v = *(const float4*)&B[(size_t)(kc + kk) * N + n0 + n4];
            uint32_t* p = &Bs[kk * BSTR + n4];
            p[0] = f2tf32(v.x); p[1] = f2tf32(v.y);
            p[2] = f2tf32(v.z); p[3] = f2tf32(v.w);
        }
        __syncthreads();

        #pragma unroll
        for (int ks = 0; ks < 4; ks++) {
            int k0 = ks * 8;
            uint32_t aR[2][4];
            #pragma unroll
            for (int mt = 0; mt < 2; mt++) {
                int m = warp_m + mt * 16 + g;
                aR[mt][0] = As[m * ASTR + k0 + tg];
                aR[mt][1] = As[(m + 8) * ASTR + k0 + tg];
                aR[mt][2] = As[m * ASTR + k0 + tg + 4];
                aR[mt][3] = As[(m + 8) * ASTR + k0 + tg + 4];
            }
            uint32_t bR[8][2];
            #pragma unroll
            for (int nt = 0; nt < 8; nt++) {
                int n = warp_n + nt * 8 + g;
                bR[nt][0] = Bs[(k0 + tg) * BSTR + n];
                bR[nt][1] = Bs[(k0 + tg + 4) * BSTR + n];
            }
            #pragma unroll
            for (int mt = 0; mt < 2; mt++)
                #pragma unroll
                for (int nt = 0; nt < 8; nt++)
                    mma_tf32(acc[mt][nt], aR[mt], bR[nt]);
        }
        __syncthreads();
    }

    #pragma unroll
    for (int mt = 0; mt < 2; mt++) {
        int m = m0 + warp_m + mt * 16 + g;
        #pragma unroll
        for (int nt = 0; nt < 8; nt++) {
            int n = n0 + warp_n + nt * 8 + 2 * tg;
            *(float2*)&C[(size_t)m * N + n] =
                make_float2(acc[mt][nt][0], acc[mt][nt][1]);
            *(float2*)&C[(size_t)(m + 8) * N + n] =
                make_float2(acc[mt][nt][2], acc[mt][nt][3]);
        }
    }
}

// ---------------------------------------------------------------------------
// RoPE (interleaved pairs), in place.
// ---------------------------------------------------------------------------
__global__ void rope_kernel(float* __restrict__ t, const float* __restrict__ cs,
                            const float* __restrict__ sn, int H, int rowstride,
                            int total)
{
    int idx = blockIdx.x * blockDim.x + threadIdx.x;
    if (idx >= total) return;
    int i = idx & 63;
    int tmp = idx >> 6;
    int h = tmp % H;
    int s = tmp / H;
    float c = cs[s * 64 + i];
    float si = sn[s * 64 + i];
    float* p = t + (size_t)s * rowstride + h * HD + 2 * i;
    float re = p[0], im = p[1];
    p[0] = re * c - im * si;
    p[1] = re * si + im * c;
}

// ---------------------------------------------------------------------------
// Flash attention with TF32 tensor cores.
// Br=Bc=64, 4 warps (128 threads), warp owns 16 q-rows.
// S = Qs @ Ks^T via mma.m16n8k8; probs round-trip smem as tf32; O += P @ V.
// ---------------------------------------------------------------------------
#define FBR 64
#define FBC 64
#define FSTR 132   // stride for 128-wide tf32 tiles (4g+tg mod 32 -> cf)
#define PSTR 68    // stride for 64-wide P tile

__global__ __launch_bounds__(128, 2) void flash_tf32_kernel(
    const float* __restrict__ Q, const float* __restrict__ K,
    const float* __restrict__ V, float* __restrict__ O)
{
    extern __shared__ uint32_t smu[];
    uint32_t* Qs  = smu;                       // [64][FSTR] tf32
    uint32_t* KVs = smu + FBR * FSTR;          // [64][FSTR] tf32 (K then V)
    uint32_t* Ps  = smu + 2 * FBR * FSTR;      // [64][PSTR] tf32 probs

    int tid = threadIdx.x;
    int w = tid >> 5, lane = tid & 31;
    int g = lane >> 2, tg = lane & 3;
    int r0 = blockIdx.x * FBR;
    int h = blockIdx.y, kvh = h >> 2;
    const float scale = 0.08838834764831845f;  // 1/sqrt(128)

    // Load Q tile (scaled, tf32)
    for (int t = tid; t < FBR * HD / 4; t += 128) {
        int row = t >> 5, c4 = (t & 31) << 2;
        float4 v = *(const float4*)&Q[(size_t)(r0 + row) * DIM + h * HD + c4];
        uint4 u;
        u.x = f2tf32(v.x * scale); u.y = f2tf32(v.y * scale);
        u.z = f2tf32(v.z * scale); u.w = f2tf32(v.w * scale);
        *(uint4*)&Qs[row * FSTR + c4] = u;
    }

    float m0 = -1e30f, m1 = -1e30f, l0 = 0.f, l1 = 0.f;
    float o[16][4];
    #pragma unroll
    for (int nt = 0; nt < 16; nt++)
        #pragma unroll
        for (int i = 0; i < 4; i++) o[nt][i] = 0.f;

    int qrow_g = r0 + 16 * w + g;       // this lane's row (and +8)
    int diag = blockIdx.x;

    for (int kt = 0; kt <= diag; kt++) {
        int c0 = kt * FBC;
        __syncthreads();   // prev iter's PV done with KVs
        // Load K tile (tf32)
        for (int t = tid; t < FBC * HD / 4; t += 128) {
            int row = t >> 5, c4 = (t & 31) << 2;
            float4 v = *(const float4*)&K[(size_t)(c0 + row) * KVDIM + kvh * HD + c4];
            uint4 u;
            u.x = f2tf32(v.x); u.y = f2tf32(v.y);
            u.z = f2tf32(v.z); u.w = f2tf32(v.w);
            *(uint4*)&KVs[row * FSTR + c4] = u;
        }
        __syncthreads();

        // ---- S = Q @ K^T (warp rows 16w..16w+15, cols 0..63) ----
        float sacc[8][4];
        #pragma unroll
        for (int nt = 0; nt < 8; nt++)
            #pragma unroll
            for (int i = 0; i < 4; i++) sacc[nt][i] = 0.f;

        #pragma unroll
        for (int ks = 0; ks < 16; ks++) {
            int k0 = ks * 8;
            uint32_t a[4];
            int mrow = (16 * w + g) * FSTR;
            a[0] = Qs[mrow + k0 + tg];
            a[1] = Qs[mrow + 8 * FSTR + k0 + tg];
            a[2] = Qs[mrow + k0 + tg + 4];
            a[3] = Qs[mrow + 8 * FSTR + k0 + tg + 4];
            #pragma unroll
            for (int nt = 0; nt < 8; nt++) {
                uint32_t b[2];
                int nrow = (8 * nt + g) * FSTR;
                b[0] = KVs[nrow + k0 + tg];
                b[1] = KVs[nrow + k0 + tg + 4];
                mma_tf32(sacc[nt], a, b);
            }
        }

        // Causal mask on diagonal tile
        if (kt == diag) {
            #pragma unroll
            for (int nt = 0; nt < 8; nt++) {
                int col = c0 + 8 * nt + 2 * tg;
                if (col > qrow_g)          sacc[nt][0] = -1e30f;
                if (col + 1 > qrow_g)      sacc[nt][1] = -1e30f;
                if (col > qrow_g + 8)      sacc[nt][2] = -1e30f;
                if (col + 1 > qrow_g + 8)  sacc[nt][3] = -1e30f;
            }
        }

        // ---- online softmax (row g in [0],[1]; row g+8 in [2],[3]) ----
        float mx0 = -1e30f, mx1 = -1e30f;
        #pragma unroll
        for (int nt = 0; nt < 8; nt++) {
            mx0 = fmaxf(mx0, fmaxf(sacc[nt][0], sacc[nt][1]));
            mx1 = fmaxf(mx1, fmaxf(sacc[nt][2], sacc[nt][3]));
        }
        #pragma unroll
        for (int off = 2; off >= 1; off >>= 1) {
            mx0 = fmaxf(mx0, __shfl_xor_sync(0xffffffffu, mx0, off));
            mx1 = fmaxf(mx1, __shfl_xor_sync(0xffffffffu, mx1, off));
        }
        float mn0 = fmaxf(m0, mx0), mn1 = fmaxf(m1, mx1);
        float cor0 = __expf(m0 - mn0), cor1 = __expf(m1 - mn1);
        float ps0 = 0.f, ps1 = 0.f;
        #pragma unroll
        for (int nt = 0; nt < 8; nt++) {
            sacc[nt][0] = __expf(sacc[nt][0] - mn0);
            sacc[nt][1] = __expf(sacc[nt][1] - mn0);
            sacc[nt][2] = __expf(sacc[nt][2] - mn1);
            sacc[nt][3] = __expf(sacc[nt][3] - mn1);
            ps0 += sacc[nt][0] + sacc[nt][1];
            ps1 += sacc[nt][2] + sacc[nt][3];
        }
        #pragma unroll
        for (int off = 2; off >= 1; off >>= 1) {
            ps0 += __shfl_xor_sync(0xffffffffu, ps0, off);
            ps1 += __shfl_xor_sync(0xffffffffu, ps1, off);
        }
        l0 = l0 * cor0 + ps0;  m0 = mn0;
        l1 = l1 * cor1 + ps1;  m1 = mn1;
        #pragma unroll
        for (int nt = 0; nt < 16; nt++) {
            o[nt][0] *= cor0; o[nt][1] *= cor0;
            o[nt][2] *= cor1; o[nt][3] *= cor1;
        }
        // Write probs to smem as tf32
        #pragma unroll
        for (int nt = 0; nt < 8; nt++) {
            int col = 8 * nt + 2 * tg;
            uint2 p0 = make_uint2(f2tf32(sacc[nt][0]), f2tf32(sacc[nt][1]));
            uint2 p1 = make_uint2(f2tf32(sacc[nt][2]), f2tf32(sacc[nt][3]));
            *(uint2*)&Ps[(16 * w + g) * PSTR + col] = p0;
            *(uint2*)&Ps[(16 * w + g + 8) * PSTR + col] = p1;
        }

        __syncthreads();   // S-mma readers done with K; load V over it
        for (int t = tid; t < FBC * HD / 4; t += 128) {
            int row = t >> 5, c4 = (t & 31) << 2;
            float4 v = *(const float4*)&V[(size_t)(c0 + row) * KVDIM + kvh * HD + c4];
            uint4 u;
            u.x = f2tf32(v.x); u.y = f2tf32(v.y);
            u.z = f2tf32(v.z); u.w = f2tf32(v.w);
            *(uint4*)&KVs[row * FSTR + c4] = u;
        }
        __syncthreads();

        // ---- O += P @ V ----
        #pragma unroll
        for (int ks = 0; ks < 8; ks++) {
            int k0 = ks * 8;
            uint32_t a[4];
            int mrow = (16 * w + g) * PSTR;
            a[0] = Ps[mrow + k0 + tg];
            a[1] = Ps[mrow + 8 * PSTR + k0 + tg];
            a[2] = Ps[mrow + k0 + tg + 4];
            a[3] = Ps[mrow + 8 * PSTR + k0 + tg + 4];
            #pragma unroll
            for (int nt = 0; nt < 16; nt++) {
                uint32_t b[2];
                b[0] = KVs[(k0 + tg) * FSTR + 8 * nt + g];
                b[1] = KVs[(k0 + tg + 4) * FSTR + 8 * nt + g];
                mma_tf32(o[nt], a, b);
            }
        }
    }

    // Finalize and store
    float i0 = 1.f / l0, i1 = 1.f / l1;
    #pragma unroll
    for (int nt = 0; nt < 16; nt++) {
        int col = h * HD + 8 * nt + 2 * tg;
        *(float2*)&O[(size_t)qrow_g * DIM + col] =
            make_float2(o[nt][0] * i0, o[nt][1] * i0);
        *(float2*)&O[(size_t)(qrow_g + 8) * DIM + col] =
            make_float2(o[nt][2] * i1, o[nt][3] * i1);
    }
}

// ---------------------------------------------------------------------------
// Launch
// ---------------------------------------------------------------------------
extern "C" void kernel_launch(void* const* d_in, const int* in_sizes, int n_in,
                              void* d_out, int out_size)
{
    const float* x  = (const float*)d_in[0];
    const float* wq = (const float*)d_in[1];
    const float* wk = (const float*)d_in[2];
    const float* wv = (const float*)d_in[3];
    const float* wo = (const float*)d_in[4];
    const float* fc = (const float*)d_in[5];
    const float* fs = (const float*)d_in[6];

    float *Qp, *Kp, *Vp, *Ap;
    cudaGetSymbolAddress((void**)&Qp, g_Q);
    cudaGetSymbolAddress((void**)&Kp, g_K);
    cudaGetSymbolAddress((void**)&Vp, g_V);
    cudaGetSymbolAddress((void**)&Ap, g_attn);

    // Projections (TF32 tensor cores)
    gemm_tf32_kernel<<<dim3(DIM / GBN, SEQ / GBM), 256>>>(x, wq, Qp, SEQ, DIM, DIM);
    gemm_tf32_kernel<<<dim3(KVDIM / GBN, SEQ / GBM), 256>>>(x, wk, Kp, SEQ, KVDIM, DIM);
    gemm_tf32_kernel<<<dim3(KVDIM / GBN, SEQ / GBM), 256>>>(x, wv, Vp, SEQ, KVDIM, DIM);

    // RoPE on Q and K
    int totQ = SEQ * NH * 64, totK = SEQ * NKV * 64;
    rope_kernel<<<(totQ + 255) / 256, 256>>>(Qp, fc, fs, NH, DIM, totQ);
    rope_kernel<<<(totK + 255) / 256, 256>>>(Kp, fc, fs, NKV, KVDIM, totK);

    // Flash attention (TF32 tensor cores)
    int smem = (2 * FBR * FSTR + FBR * PSTR) * (int)sizeof(uint32_t);
    cudaFuncSetAttribute(flash_tf32_kernel,
                         cudaFuncAttributeMaxDynamicSharedMemorySize, smem);
    flash_tf32_kernel<<<dim3(SEQ / FBR, NH), 128, smem>>>(Qp, Kp, Vp, Ap);

    // Output projection -> d_out (TF32 tensor cores)
    gemm_tf32_kernel<<<dim3(DIM / GBN, SEQ / GBM), 256>>>(Ap, wo, (float*)d_out,
                                                          SEQ, DIM, DIM);
}

// round 4
// speedup vs baseline: 3.3989x; 1.1615x over previous
#include <cuda_runtime.h>
#include <cuda_bf16.h>
#include <math.h>
#include <stdint.h>

#define SEQ 2048
#define DIM 4096
#define NH 32
#define NKV 8
#define HD 128
#define KVDIM 1024

// Scratch (allocation-free rule: device globals)
__device__ float g_Q[SEQ * DIM];
__device__ float g_K[SEQ * KVDIM];
__device__ float g_V[SEQ * KVDIM];
__device__ float g_attn[SEQ * DIM];
// tf32-rounded copies of inputs (for cp.async GEMM path)
__device__ float g_x[SEQ * DIM];
__device__ float g_wq[DIM * DIM];
__device__ float g_wk[DIM * KVDIM];
__device__ float g_wv[DIM * KVDIM];
__device__ float g_wo[DIM * DIM];

__device__ __forceinline__ uint32_t f2tf32(float x) {
    uint32_t u;
    asm("cvt.rna.tf32.f32 %0, %1;" : "=r"(u) : "f"(x));
    return u;
}

__device__ __forceinline__ void mma_tf32(float c[4], const uint32_t a[4],
                                         const uint32_t b[2]) {
    asm volatile(
        "mma.sync.aligned.m16n8k8.row.col.f32.tf32.tf32.f32 "
        "{%0,%1,%2,%3}, {%4,%5,%6,%7}, {%8,%9}, {%0,%1,%2,%3};"
        : "+f"(c[0]), "+f"(c[1]), "+f"(c[2]), "+f"(c[3])
        : "r"(a[0]), "r"(a[1]), "r"(a[2]), "r"(a[3]), "r"(b[0]), "r"(b[1]));
}

__device__ __forceinline__ void cpa16(uint32_t smem_addr, const void* gptr) {
    asm volatile("cp.async.cg.shared.global [%0], [%1], 16;"
                 :: "r"(smem_addr), "l"(gptr));
}
__device__ __forceinline__ void cpa_commit() {
    asm volatile("cp.async.commit_group;");
}
template <int N>
__device__ __forceinline__ void cpa_wait() {
    asm volatile("cp.async.wait_group %0;" :: "n"(N));
}

// ---------------------------------------------------------------------------
// tf32 rounding pre-pass (RNA): out[i] = tf32(in[i]). n % 1024 == 0 here.
// ---------------------------------------------------------------------------
__global__ void round_tf32_kernel(const float* __restrict__ in,
                                  float* __restrict__ out, int n)
{
    int i = (blockIdx.x * blockDim.x + threadIdx.x) * 4;
    if (i >= n) return;
    float4 v = *(const float4*)&in[i];
    uint4 u;
    u.x = f2tf32(v.x); u.y = f2tf32(v.y);
    u.z = f2tf32(v.z); u.w = f2tf32(v.w);
    *(uint4*)&out[i] = u;
}

// ---------------------------------------------------------------------------
// TF32 tensor-core GEMM, cp.async 2-stage pipeline.
// Inputs MUST be pre-rounded to tf32 (low 13 bits zero).
// C[M,N] = A[M,K] @ B[K,N], row-major. CTA 128x128x32, 8 warps, warp 32x64.
// ---------------------------------------------------------------------------
#define GBM 128
#define GBN 128
#define GBK 32
#define ASTR 36
#define BSTR 136
#define A_WORDS (GBM * ASTR)
#define B_WORDS (GBK * BSTR)

__global__ __launch_bounds__(256, 2) void gemm_tf32_pipe(
    const float* __restrict__ A, const float* __restrict__ B,
    float* __restrict__ C, int M, int N, int K)
{
    extern __shared__ uint32_t smg[];
    // layout: As0 | As1 | Bs0 | Bs1
    uint32_t sbase = (uint32_t)__cvta_generic_to_shared(smg);

    int tid = threadIdx.x;
    int wid = tid >> 5, lane = tid & 31;
    int g = lane >> 2, tg = lane & 3;
    int warp_m = (wid >> 1) * 32;
    int warp_n = (wid & 1) * 64;
    int m0 = blockIdx.y * GBM, n0 = blockIdx.x * GBN;

    // Per-thread copy coords (fixed)
    int am = (tid) >> 1;                    // pairs: 2 chunks/row? no:
    // A tile: 128 rows x 32 floats = 1024 x 16B chunks; thread does 4.
    // chunk c: m = c>>3, k4 = (c&7)<<2
    // B tile: 32 rows x 128 floats = 1024 chunks; kk = c>>5, n4 = (c&31)<<2

    float acc[2][8][4];
    #pragma unroll
    for (int mt = 0; mt < 2; mt++)
        #pragma unroll
        for (int nt = 0; nt < 8; nt++)
            #pragma unroll
            for (int i = 0; i < 4; i++) acc[mt][nt][i] = 0.f;

    int niter = K / GBK;

    // --- copy issue helper (inlined twice) ---
    #define ISSUE_COPY(IT, STG)                                               \
    do {                                                                      \
        uint32_t aOff = sbase + (uint32_t)(STG) * A_WORDS * 4;                \
        uint32_t bOff = sbase + (2 * A_WORDS + (uint32_t)(STG) * B_WORDS) * 4;\
        const float* Ab = A + (size_t)m0 * K + (IT) * GBK;                    \
        const float* Bb = B + (size_t)(IT) * GBK * N + n0;                    \
        _Pragma("unroll")                                                     \
        for (int i = 0; i < 4; i++) {                                         \
            int c = tid + i * 256;                                            \
            int m = c >> 3, k4 = (c & 7) << 2;                                \
            cpa16(aOff + (m * ASTR + k4) * 4, Ab + (size_t)m * K + k4);       \
        }                                                                     \
        _Pragma("unroll")                                                     \
        for (int i = 0; i < 4; i++) {                                         \
            int c = tid + i * 256;                                            \
            int kk = c >> 5, n4 = (c & 31) << 2;                              \
            cpa16(bOff + (kk * BSTR + n4) * 4, Bb + (size_t)kk * N + n4);     \
        }                                                                     \
        cpa_commit();                                                         \
    } while (0)

    ISSUE_COPY(0, 0);

    for (int it = 0; it < niter; it++) {
        int cur = it & 1;
        if (it + 1 < niter) {
            ISSUE_COPY(it + 1, (it + 1) & 1);
            cpa_wait<1>();
        } else {
            cpa_wait<0>();
        }
        __syncthreads();

        const uint32_t* As = smg + (size_t)cur * A_WORDS;
        const uint32_t* Bs = smg + 2 * A_WORDS + (size_t)cur * B_WORDS;

        #pragma unroll
        for (int ks = 0; ks < 4; ks++) {
            int k0 = ks * 8;
            uint32_t aR[2][4];
            #pragma unroll
            for (int mt = 0; mt < 2; mt++) {
                int m = warp_m + mt * 16 + g;
                aR[mt][0] = As[m * ASTR + k0 + tg];
                aR[mt][1] = As[(m + 8) * ASTR + k0 + tg];
                aR[mt][2] = As[m * ASTR + k0 + tg + 4];
                aR[mt][3] = As[(m + 8) * ASTR + k0 + tg + 4];
            }
            uint32_t bR[8][2];
            #pragma unroll
            for (int nt = 0; nt < 8; nt++) {
                int n = warp_n + nt * 8 + g;
                bR[nt][0] = Bs[(k0 + tg) * BSTR + n];
                bR[nt][1] = Bs[(k0 + tg + 4) * BSTR + n];
            }
            #pragma unroll
            for (int mt = 0; mt < 2; mt++)
                #pragma unroll
                for (int nt = 0; nt < 8; nt++)
                    mma_tf32(acc[mt][nt], aR[mt], bR[nt]);
        }
        __syncthreads();
    }

    #pragma unroll
    for (int mt = 0; mt < 2; mt++) {
        int m = m0 + warp_m + mt * 16 + g;
        #pragma unroll
        for (int nt = 0; nt < 8; nt++) {
            int n = n0 + warp_n + nt * 8 + 2 * tg;
            *(float2*)&C[(size_t)m * N + n] =
                make_float2(acc[mt][nt][0], acc[mt][nt][1]);
            *(float2*)&C[(size_t)(m + 8) * N + n] =
                make_float2(acc[mt][nt][2], acc[mt][nt][3]);
        }
    }
}

// ---------------------------------------------------------------------------
// RoPE (interleaved pairs), in place.
// ---------------------------------------------------------------------------
__global__ void rope_kernel(float* __restrict__ t, const float* __restrict__ cs,
                            const float* __restrict__ sn, int H, int rowstride,
                            int total)
{
    int idx = blockIdx.x * blockDim.x + threadIdx.x;
    if (idx >= total) return;
    int i = idx & 63;
    int tmp = idx >> 6;
    int h = tmp % H;
    int s = tmp / H;
    float c = cs[s * 64 + i];
    float si = sn[s * 64 + i];
    float* p = t + (size_t)s * rowstride + h * HD + 2 * i;
    float re = p[0], im = p[1];
    p[0] = re * c - im * si;
    p[1] = re * si + im * c;
}

// ---------------------------------------------------------------------------
// Flash attention with TF32 tensor cores (as round 3, + tf32-rounded output).
// ---------------------------------------------------------------------------
#define FBR 64
#define FBC 64
#define FSTR 132
#define PSTR 68

__global__ __launch_bounds__(128, 2) void flash_tf32_kernel(
    const float* __restrict__ Q, const float* __restrict__ K,
    const float* __restrict__ V, float* __restrict__ O)
{
    extern __shared__ uint32_t smu[];
    uint32_t* Qs  = smu;
    uint32_t* KVs = smu + FBR * FSTR;
    uint32_t* Ps  = smu + 2 * FBR * FSTR;

    int tid = threadIdx.x;
    int w = tid >> 5, lane = tid & 31;
    int g = lane >> 2, tg = lane & 3;
    int r0 = blockIdx.x * FBR;
    int h = blockIdx.y, kvh = h >> 2;
    const float scale = 0.08838834764831845f;

    for (int t = tid; t < FBR * HD / 4; t += 128) {
        int row = t >> 5, c4 = (t & 31) << 2;
        float4 v = *(const float4*)&Q[(size_t)(r0 + row) * DIM + h * HD + c4];
        uint4 u;
        u.x = f2tf32(v.x * scale); u.y = f2tf32(v.y * scale);
        u.z = f2tf32(v.z * scale); u.w = f2tf32(v.w * scale);
        *(uint4*)&Qs[row * FSTR + c4] = u;
    }

    float m0 = -1e30f, m1 = -1e30f, l0 = 0.f, l1 = 0.f;
    float o[16][4];
    #pragma unroll
    for (int nt = 0; nt < 16; nt++)
        #pragma unroll
        for (int i = 0; i < 4; i++) o[nt][i] = 0.f;

    int qrow_g = r0 + 16 * w + g;
    int diag = blockIdx.x;

    for (int kt = 0; kt <= diag; kt++) {
        int c0 = kt * FBC;
        __syncthreads();
        for (int t = tid; t < FBC * HD / 4; t += 128) {
            int row = t >> 5, c4 = (t & 31) << 2;
            float4 v = *(const float4*)&K[(size_t)(c0 + row) * KVDIM + kvh * HD + c4];
            uint4 u;
            u.x = f2tf32(v.x); u.y = f2tf32(v.y);
            u.z = f2tf32(v.z); u.w = f2tf32(v.w);
            *(uint4*)&KVs[row * FSTR + c4] = u;
        }
        __syncthreads();

        float sacc[8][4];
        #pragma unroll
        for (int nt = 0; nt < 8; nt++)
            #pragma unroll
            for (int i = 0; i < 4; i++) sacc[nt][i] = 0.f;

        #pragma unroll
        for (int ks = 0; ks < 16; ks++) {
            int k0 = ks * 8;
            uint32_t a[4];
            int mrow = (16 * w + g) * FSTR;
            a[0] = Qs[mrow + k0 + tg];
            a[1] = Qs[mrow + 8 * FSTR + k0 + tg];
            a[2] = Qs[mrow + k0 + tg + 4];
            a[3] = Qs[mrow + 8 * FSTR + k0 + tg + 4];
            #pragma unroll
            for (int nt = 0; nt < 8; nt++) {
                uint32_t b[2];
                int nrow = (8 * nt + g) * FSTR;
                b[0] = KVs[nrow + k0 + tg];
                b[1] = KVs[nrow + k0 + tg + 4];
                mma_tf32(sacc[nt], a, b);
            }
        }

        if (kt == diag) {
            #pragma unroll
            for (int nt = 0; nt < 8; nt++) {
                int col = c0 + 8 * nt + 2 * tg;
                if (col > qrow_g)          sacc[nt][0] = -1e30f;
                if (col + 1 > qrow_g)      sacc[nt][1] = -1e30f;
                if (col > qrow_g + 8)      sacc[nt][2] = -1e30f;
                if (col + 1 > qrow_g + 8)  sacc[nt][3] = -1e30f;
            }
        }

        float mx0 = -1e30f, mx1 = -1e30f;
        #pragma unroll
        for (int nt = 0; nt < 8; nt++) {
            mx0 = fmaxf(mx0, fmaxf(sacc[nt][0], sacc[nt][1]));
            mx1 = fmaxf(mx1, fmaxf(sacc[nt][2], sacc[nt][3]));
        }
        #pragma unroll
        for (int off = 2; off >= 1; off >>= 1) {
            mx0 = fmaxf(mx0, __shfl_xor_sync(0xffffffffu, mx0, off));
            mx1 = fmaxf(mx1, __shfl_xor_sync(0xffffffffu, mx1, off));
        }
        float mn0 = fmaxf(m0, mx0), mn1 = fmaxf(m1, mx1);
        float cor0 = __expf(m0 - mn0), cor1 = __expf(m1 - mn1);
        float ps0 = 0.f, ps1 = 0.f;
        #pragma unroll
        for (int nt = 0; nt < 8; nt++) {
            sacc[nt][0] = __expf(sacc[nt][0] - mn0);
            sacc[nt][1] = __expf(sacc[nt][1] - mn0);
            sacc[nt][2] = __expf(sacc[nt][2] - mn1);
            sacc[nt][3] = __expf(sacc[nt][3] - mn1);
            ps0 += sacc[nt][0] + sacc[nt][1];
            ps1 += sacc[nt][2] + sacc[nt][3];
        }
        #pragma unroll
        for (int off = 2; off >= 1; off >>= 1) {
            ps0 += __shfl_xor_sync(0xffffffffu, ps0, off);
            ps1 += __shfl_xor_sync(0xffffffffu, ps1, off);
        }
        l0 = l0 * cor0 + ps0;  m0 = mn0;
        l1 = l1 * cor1 + ps1;  m1 = mn1;
        #pragma unroll
        for (int nt = 0; nt < 16; nt++) {
            o[nt][0] *= cor0; o[nt][1] *= cor0;
            o[nt][2] *= cor1; o[nt][3] *= cor1;
        }
        #pragma unroll
        for (int nt = 0; nt < 8; nt++) {
            int col = 8 * nt + 2 * tg;
            uint2 p0 = make_uint2(f2tf32(sacc[nt][0]), f2tf32(sacc[nt][1]));
            uint2 p1 = make_uint2(f2tf32(sacc[nt][2]), f2tf32(sacc[nt][3]));
            *(uint2*)&Ps[(16 * w + g) * PSTR + col] = p0;
            *(uint2*)&Ps[(16 * w + g + 8) * PSTR + col] = p1;
        }

        __syncthreads();
        for (int t = tid; t < FBC * HD / 4; t += 128) {
            int row = t >> 5, c4 = (t & 31) << 2;
            float4 v = *(const float4*)&V[(size_t)(c0 + row) * KVDIM + kvh * HD + c4];
            uint4 u;
            u.x = f2tf32(v.x); u.y = f2tf32(v.y);
            u.z = f2tf32(v.z); u.w = f2tf32(v.w);
            *(uint4*)&KVs[row * FSTR + c4] = u;
        }
        __syncthreads();

        #pragma unroll
        for (int ks = 0; ks < 8; ks++) {
            int k0 = ks * 8;
            uint32_t a[4];
            int mrow = (16 * w + g) * PSTR;
            a[0] = Ps[mrow + k0 + tg];
            a[1] = Ps[mrow + 8 * PSTR + k0 + tg];
            a[2] = Ps[mrow + k0 + tg + 4];
            a[3] = Ps[mrow + 8 * PSTR + k0 + tg + 4];
            #pragma unroll
            for (int nt = 0; nt < 16; nt++) {
                uint32_t b[2];
                b[0] = KVs[(k0 + tg) * FSTR + 8 * nt + g];
                b[1] = KVs[(k0 + tg + 4) * FSTR + 8 * nt + g];
                mma_tf32(o[nt], a, b);
            }
        }
    }

    // Finalize and store, pre-rounded to tf32 (feeds the final GEMM directly)
    float i0 = 1.f / l0, i1 = 1.f / l1;
    #pragma unroll
    for (int nt = 0; nt < 16; nt++) {
        int col = h * HD + 8 * nt + 2 * tg;
        uint2 u0 = make_uint2(f2tf32(o[nt][0] * i0), f2tf32(o[nt][1] * i0));
        uint2 u1 = make_uint2(f2tf32(o[nt][2] * i1), f2tf32(o[nt][3] * i1));
        *(uint2*)&O[(size_t)qrow_g * DIM + col] = u0;
        *(uint2*)&O[(size_t)(qrow_g + 8) * DIM + col] = u1;
    }
}

// ---------------------------------------------------------------------------
// Launch
// ---------------------------------------------------------------------------
extern "C" void kernel_launch(void* const* d_in, const int* in_sizes, int n_in,
                              void* d_out, int out_size)
{
    const float* x  = (const float*)d_in[0];
    const float* wq = (const float*)d_in[1];
    const float* wk = (const float*)d_in[2];
    const float* wv = (const float*)d_in[3];
    const float* wo = (const float*)d_in[4];
    const float* fc = (const float*)d_in[5];
    const float* fs = (const float*)d_in[6];

    float *Qp, *Kp, *Vp, *Ap, *Xp, *Wqp, *Wkp, *Wvp, *Wop;
    cudaGetSymbolAddress((void**)&Qp, g_Q);
    cudaGetSymbolAddress((void**)&Kp, g_K);
    cudaGetSymbolAddress((void**)&Vp, g_V);
    cudaGetSymbolAddress((void**)&Ap, g_attn);
    cudaGetSymbolAddress((void**)&Xp, g_x);
    cudaGetSymbolAddress((void**)&Wqp, g_wq);
    cudaGetSymbolAddress((void**)&Wkp, g_wk);
    cudaGetSymbolAddress((void**)&Wvp, g_wv);
    cudaGetSymbolAddress((void**)&Wop, g_wo);

    // tf32 pre-rounding (RNA)
    const int RB = 256;
    round_tf32_kernel<<<(SEQ * DIM / 4 + RB - 1) / RB, RB>>>(x, Xp, SEQ * DIM);
    round_tf32_kernel<<<(DIM * DIM / 4 + RB - 1) / RB, RB>>>(wq, Wqp, DIM * DIM);
    round_tf32_kernel<<<(DIM * KVDIM / 4 + RB - 1) / RB, RB>>>(wk, Wkp, DIM * KVDIM);
    round_tf32_kernel<<<(DIM * KVDIM / 4 + RB - 1) / RB, RB>>>(wv, Wvp, DIM * KVDIM);
    round_tf32_kernel<<<(DIM * DIM / 4 + RB - 1) / RB, RB>>>(wo, Wop, DIM * DIM);

    int gsm = (2 * A_WORDS + 2 * B_WORDS) * (int)sizeof(uint32_t);
    cudaFuncSetAttribute(gemm_tf32_pipe,
                         cudaFuncAttributeMaxDynamicSharedMemorySize, gsm);

    // Projections (TF32 tensor cores, pipelined)
    gemm_tf32_pipe<<<dim3(DIM / GBN, SEQ / GBM), 256, gsm>>>(Xp, Wqp, Qp, SEQ, DIM, DIM);
    gemm_tf32_pipe<<<dim3(KVDIM / GBN, SEQ / GBM), 256, gsm>>>(Xp, Wkp, Kp, SEQ, KVDIM, DIM);
    gemm_tf32_pipe<<<dim3(KVDIM / GBN, SEQ / GBM), 256, gsm>>>(Xp, Wvp, Vp, SEQ, KVDIM, DIM);

    // RoPE on Q and K
    int totQ = SEQ * NH * 64, totK = SEQ * NKV * 64;
    rope_kernel<<<(totQ + 255) / 256, 256>>>(Qp, fc, fs, NH, DIM, totQ);
    rope_kernel<<<(totK + 255) / 256, 256>>>(Kp, fc, fs, NKV, KVDIM, totK);

    // Flash attention (TF32 tensor cores)
    int fsm = (2 * FBR * FSTR + FBR * PSTR) * (int)sizeof(uint32_t);
    cudaFuncSetAttribute(flash_tf32_kernel,
                         cudaFuncAttributeMaxDynamicSharedMemorySize, fsm);
    flash_tf32_kernel<<<dim3(SEQ / FBR, NH), 128, fsm>>>(Qp, Kp, Vp, Ap);

    // Output projection -> d_out
    gemm_tf32_pipe<<<dim3(DIM / GBN, SEQ / GBM), 256, gsm>>>(Ap, Wop, (float*)d_out,
                                                             SEQ, DIM, DIM);
}

// round 5
// speedup vs baseline: 3.6001x; 1.0592x over previous
#include <cuda_runtime.h>
#include <cuda_bf16.h>
#include <math.h>
#include <stdint.h>

#define SEQ 2048
#define DIM 4096
#define NH 32
#define NKV 8
#define HD 128
#define KVDIM 1024

// Scratch (allocation-free rule: device globals)
__device__ float g_Q[SEQ * DIM];
__device__ float g_K[SEQ * KVDIM];
__device__ float g_V[SEQ * KVDIM];
__device__ float g_attn[SEQ * DIM];
// tf32-rounded copies of inputs (for cp.async GEMM path)
__device__ float g_x[SEQ * DIM];
__device__ float g_wq[DIM * DIM];
__device__ float g_wk[DIM * KVDIM];
__device__ float g_wv[DIM * KVDIM];
__device__ float g_wo[DIM * DIM];

__device__ __forceinline__ uint32_t f2tf32(float x) {
    uint32_t u;
    asm("cvt.rna.tf32.f32 %0, %1;" : "=r"(u) : "f"(x));
    return u;
}

__device__ __forceinline__ void mma_tf32(float c[4], const uint32_t a[4],
                                         const uint32_t b[2]) {
    asm volatile(
        "mma.sync.aligned.m16n8k8.row.col.f32.tf32.tf32.f32 "
        "{%0,%1,%2,%3}, {%4,%5,%6,%7}, {%8,%9}, {%0,%1,%2,%3};"
        : "+f"(c[0]), "+f"(c[1]), "+f"(c[2]), "+f"(c[3])
        : "r"(a[0]), "r"(a[1]), "r"(a[2]), "r"(a[3]), "r"(b[0]), "r"(b[1]));
}

__device__ __forceinline__ void cpa16(uint32_t smem_addr, const void* gptr) {
    asm volatile("cp.async.cg.shared.global [%0], [%1], 16;"
                 :: "r"(smem_addr), "l"(gptr));
}
__device__ __forceinline__ void cpa_commit() {
    asm volatile("cp.async.commit_group;");
}
template <int N>
__device__ __forceinline__ void cpa_wait() {
    asm volatile("cp.async.wait_group %0;" :: "n"(N));
}

// ---------------------------------------------------------------------------
// tf32 rounding pre-pass (RNA)
// ---------------------------------------------------------------------------
__global__ void round_tf32_kernel(const float* __restrict__ in,
                                  float* __restrict__ out, int n)
{
    int i = (blockIdx.x * blockDim.x + threadIdx.x) * 4;
    if (i >= n) return;
    float4 v = *(const float4*)&in[i];
    uint4 u;
    u.x = f2tf32(v.x); u.y = f2tf32(v.y);
    u.z = f2tf32(v.z); u.w = f2tf32(v.w);
    *(uint4*)&out[i] = u;
}

// ---------------------------------------------------------------------------
// TF32 GEMM v3: cp.async 2-stage, CTA 128x128x32, 4 warps, warp tile 64x64.
// Inputs pre-rounded to tf32. C = A @ B row-major.
// ---------------------------------------------------------------------------
#define GBM 128
#define GBN 128
#define GBK 32
#define ASTR 36
#define BSTR 136
#define A_WORDS (GBM * ASTR)
#define B_WORDS (GBK * BSTR)

__global__ __launch_bounds__(128, 2) void gemm_tf32_pipe(
    const float* __restrict__ A, const float* __restrict__ B,
    float* __restrict__ C, int M, int N, int K)
{
    extern __shared__ uint32_t smg[];
    uint32_t sbase = (uint32_t)__cvta_generic_to_shared(smg);

    int tid = threadIdx.x;
    int wid = tid >> 5, lane = tid & 31;
    int g = lane >> 2, tg = lane & 3;
    int warp_m = (wid >> 1) * 64;
    int warp_n = (wid & 1) * 64;
    int m0 = blockIdx.y * GBM, n0 = blockIdx.x * GBN;

    float acc[4][8][4];
    #pragma unroll
    for (int mt = 0; mt < 4; mt++)
        #pragma unroll
        for (int nt = 0; nt < 8; nt++)
            #pragma unroll
            for (int i = 0; i < 4; i++) acc[mt][nt][i] = 0.f;

    int niter = K / GBK;

    // A tile: 1024 16B chunks, 8 per thread. B tile: same.
    #define ISSUE_COPY(IT, STG)                                               \
    do {                                                                      \
        uint32_t aOff = sbase + (uint32_t)(STG) * A_WORDS * 4;                \
        uint32_t bOff = sbase + (2 * A_WORDS + (uint32_t)(STG) * B_WORDS) * 4;\
        const float* Ab = A + (size_t)m0 * K + (IT) * GBK;                    \
        const float* Bb = B + (size_t)(IT) * GBK * N + n0;                    \
        _Pragma("unroll")                                                     \
        for (int i = 0; i < 8; i++) {                                         \
            int c = tid + i * 128;                                            \
            int m = c >> 3, k4 = (c & 7) << 2;                                \
            cpa16(aOff + (m * ASTR + k4) * 4, Ab + (size_t)m * K + k4);       \
        }                                                                     \
        _Pragma("unroll")                                                     \
        for (int i = 0; i < 8; i++) {                                         \
            int c = tid + i * 128;                                            \
            int kk = c >> 5, n4 = (c & 31) << 2;                              \
            cpa16(bOff + (kk * BSTR + n4) * 4, Bb + (size_t)kk * N + n4);     \
        }                                                                     \
        cpa_commit();                                                         \
    } while (0)

    ISSUE_COPY(0, 0);

    for (int it = 0; it < niter; it++) {
        int cur = it & 1;
        if (it + 1 < niter) {
            ISSUE_COPY(it + 1, (it + 1) & 1);
            cpa_wait<1>();
        } else {
            cpa_wait<0>();
        }
        __syncthreads();

        const uint32_t* As = smg + (size_t)cur * A_WORDS;
        const uint32_t* Bs = smg + 2 * A_WORDS + (size_t)cur * B_WORDS;

        #pragma unroll
        for (int ks = 0; ks < 4; ks++) {
            int k0 = ks * 8;
            uint32_t aR[4][4];
            #pragma unroll
            for (int mt = 0; mt < 4; mt++) {
                int m = warp_m + mt * 16 + g;
                aR[mt][0] = As[m * ASTR + k0 + tg];
                aR[mt][1] = As[(m + 8) * ASTR + k0 + tg];
                aR[mt][2] = As[m * ASTR + k0 + tg + 4];
                aR[mt][3] = As[(m + 8) * ASTR + k0 + tg + 4];
            }
            uint32_t bR[8][2];
            #pragma unroll
            for (int nt = 0; nt < 8; nt++) {
                int n = warp_n + nt * 8 + g;
                bR[nt][0] = Bs[(k0 + tg) * BSTR + n];
                bR[nt][1] = Bs[(k0 + tg + 4) * BSTR + n];
            }
            #pragma unroll
            for (int mt = 0; mt < 4; mt++)
                #pragma unroll
                for (int nt = 0; nt < 8; nt++)
                    mma_tf32(acc[mt][nt], aR[mt], bR[nt]);
        }
        __syncthreads();
    }

    #pragma unroll
    for (int mt = 0; mt < 4; mt++) {
        int m = m0 + warp_m + mt * 16 + g;
        #pragma unroll
        for (int nt = 0; nt < 8; nt++) {
            int n = n0 + warp_n + nt * 8 + 2 * tg;
            *(float2*)&C[(size_t)m * N + n] =
                make_float2(acc[mt][nt][0], acc[mt][nt][1]);
            *(float2*)&C[(size_t)(m + 8) * N + n] =
                make_float2(acc[mt][nt][2], acc[mt][nt][3]);
        }
    }
}

// ---------------------------------------------------------------------------
// RoPE (interleaved pairs), in place.
// ---------------------------------------------------------------------------
__global__ void rope_kernel(float* __restrict__ t, const float* __restrict__ cs,
                            const float* __restrict__ sn, int H, int rowstride,
                            int total)
{
    int idx = blockIdx.x * blockDim.x + threadIdx.x;
    if (idx >= total) return;
    int i = idx & 63;
    int tmp = idx >> 6;
    int h = tmp % H;
    int s = tmp / H;
    float c = cs[s * 64 + i];
    float si = sn[s * 64 + i];
    float* p = t + (size_t)s * rowstride + h * HD + 2 * i;
    float re = p[0], im = p[1];
    p[0] = re * c - im * si;
    p[1] = re * si + im * c;
}

// ---------------------------------------------------------------------------
// Flash attention, TF32 tensor cores, Q fragments register-cached.
// Br=Bc=64, 4 warps. Ps overlays the dead Qs smem region.
// ---------------------------------------------------------------------------
#define FBR 64
#define FBC 64
#define FSTR 132
#define PSTR 68

__global__ __launch_bounds__(128, 2) void flash_tf32_kernel(
    const float* __restrict__ Q, const float* __restrict__ K,
    const float* __restrict__ V, float* __restrict__ O)
{
    extern __shared__ uint32_t smu[];
    uint32_t* Qs  = smu;                   // [64][FSTR] tf32 (Q staging)
    uint32_t* KVs = smu + FBR * FSTR;      // [64][FSTR] tf32 (K then V)
    uint32_t* Ps  = smu;                   // overlays Qs after frag load

    int tid = threadIdx.x;
    int w = tid >> 5, lane = tid & 31;
    int g = lane >> 2, tg = lane & 3;
    int r0 = blockIdx.x * FBR;
    int h = blockIdx.y, kvh = h >> 2;
    const float scale = 0.08838834764831845f;

    // Stage Q tile into smem (scaled, tf32)
    for (int t = tid; t < FBR * HD / 4; t += 128) {
        int row = t >> 5, c4 = (t & 31) << 2;
        float4 v = *(const float4*)&Q[(size_t)(r0 + row) * DIM + h * HD + c4];
        uint4 u;
        u.x = f2tf32(v.x * scale); u.y = f2tf32(v.y * scale);
        u.z = f2tf32(v.z * scale); u.w = f2tf32(v.w * scale);
        *(uint4*)&Qs[row * FSTR + c4] = u;
    }
    __syncthreads();

    // Cache all Q a-fragments in registers (loop-invariant)
    uint32_t qa[16][4];
    {
        int mrow = (16 * w + g) * FSTR;
        #pragma unroll
        for (int ks = 0; ks < 16; ks++) {
            int k0 = ks * 8;
            qa[ks][0] = Qs[mrow + k0 + tg];
            qa[ks][1] = Qs[mrow + 8 * FSTR + k0 + tg];
            qa[ks][2] = Qs[mrow + k0 + tg + 4];
            qa[ks][3] = Qs[mrow + 8 * FSTR + k0 + tg + 4];
        }
    }
    __syncthreads();   // everyone done reading Qs; Ps may overlay it

    float m0 = -1e30f, m1 = -1e30f, l0 = 0.f, l1 = 0.f;
    float o[16][4];
    #pragma unroll
    for (int nt = 0; nt < 16; nt++)
        #pragma unroll
        for (int i = 0; i < 4; i++) o[nt][i] = 0.f;

    int qrow_g = r0 + 16 * w + g;
    int diag = blockIdx.x;

    for (int kt = 0; kt <= diag; kt++) {
        int c0 = kt * FBC;
        __syncthreads();   // prev PV done with KVs
        for (int t = tid; t < FBC * HD / 4; t += 128) {
            int row = t >> 5, c4 = (t & 31) << 2;
            float4 v = *(const float4*)&K[(size_t)(c0 + row) * KVDIM + kvh * HD + c4];
            uint4 u;
            u.x = f2tf32(v.x); u.y = f2tf32(v.y);
            u.z = f2tf32(v.z); u.w = f2tf32(v.w);
            *(uint4*)&KVs[row * FSTR + c4] = u;
        }
        __syncthreads();

        float sacc[8][4];
        #pragma unroll
        for (int nt = 0; nt < 8; nt++)
            #pragma unroll
            for (int i = 0; i < 4; i++) sacc[nt][i] = 0.f;

        #pragma unroll
        for (int ks = 0; ks < 16; ks++) {
            int k0 = ks * 8;
            #pragma unroll
            for (int nt = 0; nt < 8; nt++) {
                uint32_t b[2];
                int nrow = (8 * nt + g) * FSTR;
                b[0] = KVs[nrow + k0 + tg];
                b[1] = KVs[nrow + k0 + tg + 4];
                mma_tf32(sacc[nt], qa[ks], b);
            }
        }

        if (kt == diag) {
            #pragma unroll
            for (int nt = 0; nt < 8; nt++) {
                int col = c0 + 8 * nt + 2 * tg;
                if (col > qrow_g)          sacc[nt][0] = -1e30f;
                if (col + 1 > qrow_g)      sacc[nt][1] = -1e30f;
                if (col > qrow_g + 8)      sacc[nt][2] = -1e30f;
                if (col + 1 > qrow_g + 8)  sacc[nt][3] = -1e30f;
            }
        }

        float mx0 = -1e30f, mx1 = -1e30f;
        #pragma unroll
        for (int nt = 0; nt < 8; nt++) {
            mx0 = fmaxf(mx0, fmaxf(sacc[nt][0], sacc[nt][1]));
            mx1 = fmaxf(mx1, fmaxf(sacc[nt][2], sacc[nt][3]));
        }
        #pragma unroll
        for (int off = 2; off >= 1; off >>= 1) {
            mx0 = fmaxf(mx0, __shfl_xor_sync(0xffffffffu, mx0, off));
            mx1 = fmaxf(mx1, __shfl_xor_sync(0xffffffffu, mx1, off));
        }
        float mn0 = fmaxf(m0, mx0), mn1 = fmaxf(m1, mx1);
        float cor0 = __expf(m0 - mn0), cor1 = __expf(m1 - mn1);
        float ps0 = 0.f, ps1 = 0.f;
        #pragma unroll
        for (int nt = 0; nt < 8; nt++) {
            sacc[nt][0] = __expf(sacc[nt][0] - mn0);
            sacc[nt][1] = __expf(sacc[nt][1] - mn0);
            sacc[nt][2] = __expf(sacc[nt][2] - mn1);
            sacc[nt][3] = __expf(sacc[nt][3] - mn1);
            ps0 += sacc[nt][0] + sacc[nt][1];
            ps1 += sacc[nt][2] + sacc[nt][3];
        }
        #pragma unroll
        for (int off = 2; off >= 1; off >>= 1) {
            ps0 += __shfl_xor_sync(0xffffffffu, ps0, off);
            ps1 += __shfl_xor_sync(0xffffffffu, ps1, off);
        }
        l0 = l0 * cor0 + ps0;  m0 = mn0;
        l1 = l1 * cor1 + ps1;  m1 = mn1;
        #pragma unroll
        for (int nt = 0; nt < 16; nt++) {
            o[nt][0] *= cor0; o[nt][1] *= cor0;
            o[nt][2] *= cor1; o[nt][3] *= cor1;
        }
        #pragma unroll
        for (int nt = 0; nt < 8; nt++) {
            int col = 8 * nt + 2 * tg;
            uint2 p0 = make_uint2(f2tf32(sacc[nt][0]), f2tf32(sacc[nt][1]));
            uint2 p1 = make_uint2(f2tf32(sacc[nt][2]), f2tf32(sacc[nt][3]));
            *(uint2*)&Ps[(16 * w + g) * PSTR + col] = p0;
            *(uint2*)&Ps[(16 * w + g + 8) * PSTR + col] = p1;
        }

        __syncthreads();
        for (int t = tid; t < FBC * HD / 4; t += 128) {
            int row = t >> 5, c4 = (t & 31) << 2;
            float4 v = *(const float4*)&V[(size_t)(c0 + row) * KVDIM + kvh * HD + c4];
            uint4 u;
            u.x = f2tf32(v.x); u.y = f2tf32(v.y);
            u.z = f2tf32(v.z); u.w = f2tf32(v.w);
            *(uint4*)&KVs[row * FSTR + c4] = u;
        }
        __syncthreads();

        #pragma unroll
        for (int ks = 0; ks < 8; ks++) {
            int k0 = ks * 8;
            uint32_t a[4];
            int mrow = (16 * w + g) * PSTR;
            a[0] = Ps[mrow + k0 + tg];
            a[1] = Ps[mrow + 8 * PSTR + k0 + tg];
            a[2] = Ps[mrow + k0 + tg + 4];
            a[3] = Ps[mrow + 8 * PSTR + k0 + tg + 4];
            #pragma unroll
            for (int nt = 0; nt < 16; nt++) {
                uint32_t b[2];
                b[0] = KVs[(k0 + tg) * FSTR + 8 * nt + g];
                b[1] = KVs[(k0 + tg + 4) * FSTR + 8 * nt + g];
                mma_tf32(o[nt], a, b);
            }
        }
    }

    float i0 = 1.f / l0, i1 = 1.f / l1;
    #pragma unroll
    for (int nt = 0; nt < 16; nt++) {
        int col = h * HD + 8 * nt + 2 * tg;
        uint2 u0 = make_uint2(f2tf32(o[nt][0] * i0), f2tf32(o[nt][1] * i0));
        uint2 u1 = make_uint2(f2tf32(o[nt][2] * i1), f2tf32(o[nt][3] * i1));
        *(uint2*)&O[(size_t)qrow_g * DIM + col] = u0;
        *(uint2*)&O[(size_t)(qrow_g + 8) * DIM + col] = u1;
    }
}

// ---------------------------------------------------------------------------
// Launch
// ---------------------------------------------------------------------------
extern "C" void kernel_launch(void* const* d_in, const int* in_sizes, int n_in,
                              void* d_out, int out_size)
{
    const float* x  = (const float*)d_in[0];
    const float* wq = (const float*)d_in[1];
    const float* wk = (const float*)d_in[2];
    const float* wv = (const float*)d_in[3];
    const float* wo = (const float*)d_in[4];
    const float* fc = (const float*)d_in[5];
    const float* fs = (const float*)d_in[6];

    float *Qp, *Kp, *Vp, *Ap, *Xp, *Wqp, *Wkp, *Wvp, *Wop;
    cudaGetSymbolAddress((void**)&Qp, g_Q);
    cudaGetSymbolAddress((void**)&Kp, g_K);
    cudaGetSymbolAddress((void**)&Vp, g_V);
    cudaGetSymbolAddress((void**)&Ap, g_attn);
    cudaGetSymbolAddress((void**)&Xp, g_x);
    cudaGetSymbolAddress((void**)&Wqp, g_wq);
    cudaGetSymbolAddress((void**)&Wkp, g_wk);
    cudaGetSymbolAddress((void**)&Wvp, g_wv);
    cudaGetSymbolAddress((void**)&Wop, g_wo);

    const int RB = 256;
    round_tf32_kernel<<<(SEQ * DIM / 4 + RB - 1) / RB, RB>>>(x, Xp, SEQ * DIM);
    round_tf32_kernel<<<(DIM * DIM / 4 + RB - 1) / RB, RB>>>(wq, Wqp, DIM * DIM);
    round_tf32_kernel<<<(DIM * KVDIM / 4 + RB - 1) / RB, RB>>>(wk, Wkp, DIM * KVDIM);
    round_tf32_kernel<<<(DIM * KVDIM / 4 + RB - 1) / RB, RB>>>(wv, Wvp, DIM * KVDIM);
    round_tf32_kernel<<<(DIM * DIM / 4 + RB - 1) / RB, RB>>>(wo, Wop, DIM * DIM);

    int gsm = (2 * A_WORDS + 2 * B_WORDS) * (int)sizeof(uint32_t);
    cudaFuncSetAttribute(gemm_tf32_pipe,
                         cudaFuncAttributeMaxDynamicSharedMemorySize, gsm);

    gemm_tf32_pipe<<<dim3(DIM / GBN, SEQ / GBM), 128, gsm>>>(Xp, Wqp, Qp, SEQ, DIM, DIM);
    gemm_tf32_pipe<<<dim3(KVDIM / GBN, SEQ / GBM), 128, gsm>>>(Xp, Wkp, Kp, SEQ, KVDIM, DIM);
    gemm_tf32_pipe<<<dim3(KVDIM / GBN, SEQ / GBM), 128, gsm>>>(Xp, Wvp, Vp, SEQ, KVDIM, DIM);

    int totQ = SEQ * NH * 64, totK = SEQ * NKV * 64;
    rope_kernel<<<(totQ + 255) / 256, 256>>>(Qp, fc, fs, NH, DIM, totQ);
    rope_kernel<<<(totK + 255) / 256, 256>>>(Kp, fc, fs, NKV, KVDIM, totK);

    int fsm = (2 * FBR * FSTR) * (int)sizeof(uint32_t);
    cudaFuncSetAttribute(flash_tf32_kernel,
                         cudaFuncAttributeMaxDynamicSharedMemorySize, fsm);
    flash_tf32_kernel<<<dim3(SEQ / FBR, NH), 128, fsm>>>(Qp, Kp, Vp, Ap);

    gemm_tf32_pipe<<<dim3(DIM / GBN, SEQ / GBM), 128, gsm>>>(Ap, Wop, (float*)d_out,
                                                             SEQ, DIM, DIM);
}

// round 8
// speedup vs baseline: 5.4645x; 1.5179x over previous
#include <cuda_runtime.h>
#include <cuda_fp16.h>
#include <math.h>
#include <stdint.h>

#define SEQ 2048
#define DIM 4096
#define NH 32
#define NKV 8
#define HD 128
#define KVDIM 1024

// Scratch (allocation-free rule: device globals)
__device__ float  g_Q[SEQ * DIM];
__device__ float  g_K[SEQ * KVDIM];
__device__ float  g_V[SEQ * KVDIM];
__device__ __half g_attn16[SEQ * DIM];     // flash output, fp16
__device__ __half g_x16[SEQ * DIM];        // x, fp16
__device__ __half g_wqT[DIM * DIM];        // Wq^T [N][K] fp16
__device__ __half g_wkT[DIM * KVDIM];
__device__ __half g_wvT[DIM * KVDIM];
__device__ __half g_woT[DIM * DIM];

// ---------------------------------------------------------------------------
// Helpers
// ---------------------------------------------------------------------------
__device__ __forceinline__ uint32_t f2tf32(float x) {
    uint32_t u;
    asm("cvt.rna.tf32.f32 %0, %1;" : "=r"(u) : "f"(x));
    return u;
}

__device__ __forceinline__ void mma_f16(float c[4], const uint32_t a[4],
                                        const uint32_t b[2]) {
    asm volatile(
        "mma.sync.aligned.m16n8k16.row.col.f32.f16.f16.f32 "
        "{%0,%1,%2,%3}, {%4,%5,%6,%7}, {%8,%9}, {%0,%1,%2,%3};"
        : "+f"(c[0]), "+f"(c[1]), "+f"(c[2]), "+f"(c[3])
        : "r"(a[0]), "r"(a[1]), "r"(a[2]), "r"(a[3]), "r"(b[0]), "r"(b[1]));
}

__device__ __forceinline__ void mma_tf32(float c[4], const uint32_t a[4],
                                         const uint32_t b[2]) {
    asm volatile(
        "mma.sync.aligned.m16n8k8.row.col.f32.tf32.tf32.f32 "
        "{%0,%1,%2,%3}, {%4,%5,%6,%7}, {%8,%9}, {%0,%1,%2,%3};"
        : "+f"(c[0]), "+f"(c[1]), "+f"(c[2]), "+f"(c[3])
        : "r"(a[0]), "r"(a[1]), "r"(a[2]), "r"(a[3]), "r"(b[0]), "r"(b[1]));
}

__device__ __forceinline__ void cpa16(uint32_t smem_addr, const void* gptr) {
    asm volatile("cp.async.cg.shared.global [%0], [%1], 16;"
                 :: "r"(smem_addr), "l"(gptr));
}
__device__ __forceinline__ void cpa_commit() {
    asm volatile("cp.async.commit_group;");
}
template <int N>
__device__ __forceinline__ void cpa_wait() {
    asm volatile("cp.async.wait_group %0;" :: "n"(N));
}

// ---------------------------------------------------------------------------
// Pre-passes: fp32 -> fp16 convert; fp32 [R][C] -> fp16 [C][R] transpose
// ---------------------------------------------------------------------------
__global__ void convert_half_kernel(const float* __restrict__ in,
                                    __half* __restrict__ out, int n)
{
    int i = (blockIdx.x * blockDim.x + threadIdx.x) * 4;
    if (i >= n) return;
    float4 v = *(const float4*)&in[i];
    __half2 h0 = __floats2half2_rn(v.x, v.y);
    __half2 h1 = __floats2half2_rn(v.z, v.w);
    *(uint2*)&out[i] = make_uint2(*(uint32_t*)&h0, *(uint32_t*)&h1);
}

__global__ void transpose_half_kernel(const float* __restrict__ in,
                                      __half* __restrict__ out, int R, int C)
{
    __shared__ float tile[32][33];
    int c0 = blockIdx.x * 32, r0 = blockIdx.y * 32;
    int tx = threadIdx.x, ty = threadIdx.y;
    #pragma unroll
    for (int j = 0; j < 32; j += 8)
        tile[ty + j][tx] = in[(size_t)(r0 + ty + j) * C + c0 + tx];
    __syncthreads();
    #pragma unroll
    for (int j = 0; j < 32; j += 8)
        out[(size_t)(c0 + ty + j) * R + r0 + tx] = __float2half(tile[tx][ty + j]);
}

// ---------------------------------------------------------------------------
// FP16 GEMM: C[M,N] = A[M,K] @ BT[N,K]^T, fp32 accumulate.
// A, BT fp16 K-major. CTA 128x128, K-chunk 64, 4 warps, warp tile 64x64,
// mma.m16n8k16, cp.async 2-stage.
// ---------------------------------------------------------------------------
#define GBM 128
#define GBN 128
#define GKC 64                 // K elements per chunk
#define HSTR 36                // u32 (half2) words per row: 32 + 4 pad
#define TILE_WORDS (128 * HSTR)

__global__ __launch_bounds__(128, 2) void gemm_f16_kernel(
    const __half* __restrict__ A, const __half* __restrict__ BT,
    float* __restrict__ C, int M, int N, int K)
{
    extern __shared__ uint32_t smg[];
    uint32_t sbase = (uint32_t)__cvta_generic_to_shared(smg);

    int tid = threadIdx.x;
    int wid = tid >> 5, lane = tid & 31;
    int g = lane >> 2, tg = lane & 3;
    int warp_m = (wid >> 1) * 64;
    int warp_n = (wid & 1) * 64;
    int m0 = blockIdx.y * GBM, n0 = blockIdx.x * GBN;

    float acc[4][8][4];
    #pragma unroll
    for (int mt = 0; mt < 4; mt++)
        #pragma unroll
        for (int nt = 0; nt < 8; nt++)
            #pragma unroll
            for (int i = 0; i < 4; i++) acc[mt][nt][i] = 0.f;

    int niter = K / GKC;

    // Each tile: 128 rows x 64 halfs = 1024 x 16B granules; 8 per thread.
    #define ISSUE_COPY(IT, STG)                                               \
    do {                                                                      \
        uint32_t aOff = sbase + (uint32_t)(STG) * (2 * TILE_WORDS) * 4;       \
        uint32_t bOff = aOff + TILE_WORDS * 4;                                \
        const __half* Ab = A + (size_t)m0 * K + (IT) * GKC;                   \
        const __half* Bb = BT + (size_t)n0 * K + (IT) * GKC;                  \
        _Pragma("unroll")                                                     \
        for (int i = 0; i < 8; i++) {                                         \
            int c = tid + i * 128;                                            \
            int r = c >> 3, cc = c & 7;                                       \
            cpa16(aOff + r * 144 + cc * 16, Ab + (size_t)r * K + cc * 8);     \
        }                                                                     \
        _Pragma("unroll")                                                     \
        for (int i = 0; i < 8; i++) {                                         \
            int c = tid + i * 128;                                            \
            int r = c >> 3, cc = c & 7;                                       \
            cpa16(bOff + r * 144 + cc * 16, Bb + (size_t)r * K + cc * 8);     \
        }                                                                     \
        cpa_commit();                                                         \
    } while (0)

    ISSUE_COPY(0, 0);

    for (int it = 0; it < niter; it++) {
        int cur = it & 1;
        if (it + 1 < niter) {
            ISSUE_COPY(it + 1, (it + 1) & 1);
            cpa_wait<1>();
        } else {
            cpa_wait<0>();
        }
        __syncthreads();

        const uint32_t* As = smg + (size_t)cur * 2 * TILE_WORDS;
        const uint32_t* Bs = As + TILE_WORDS;

        #pragma unroll
        for (int ks = 0; ks < 4; ks++) {          // 4 x k16
            int k0 = ks * 8;                       // word offset
            uint32_t aR[4][4];
            #pragma unroll
            for (int mt = 0; mt < 4; mt++) {
                int m = warp_m + mt * 16 + g;
                aR[mt][0] = As[m * HSTR + k0 + tg];
                aR[mt][1] = As[(m + 8) * HSTR + k0 + tg];
                aR[mt][2] = As[m * HSTR + k0 + tg + 4];
                aR[mt][3] = As[(m + 8) * HSTR + k0 + tg + 4];
            }
            uint32_t bR[8][2];
            #pragma unroll
            for (int nt = 0; nt < 8; nt++) {
                int n = warp_n + nt * 8 + g;
                bR[nt][0] = Bs[n * HSTR + k0 + tg];
                bR[nt][1] = Bs[n * HSTR + k0 + tg + 4];
            }
            #pragma unroll
            for (int mt = 0; mt < 4; mt++)
                #pragma unroll
                for (int nt = 0; nt < 8; nt++)
                    mma_f16(acc[mt][nt], aR[mt], bR[nt]);
        }
        __syncthreads();
    }

    #pragma unroll
    for (int mt = 0; mt < 4; mt++) {
        int m = m0 + warp_m + mt * 16 + g;
        #pragma unroll
        for (int nt = 0; nt < 8; nt++) {
            int n = n0 + warp_n + nt * 8 + 2 * tg;
            *(float2*)&C[(size_t)m * N + n] =
                make_float2(acc[mt][nt][0], acc[mt][nt][1]);
            *(float2*)&C[(size_t)(m + 8) * N + n] =
                make_float2(acc[mt][nt][2], acc[mt][nt][3]);
        }
    }
}

// ---------------------------------------------------------------------------
// RoPE (interleaved pairs), in place, fp32.
// ---------------------------------------------------------------------------
__global__ void rope_kernel(float* __restrict__ t, const float* __restrict__ cs,
                            const float* __restrict__ sn, int H, int rowstride,
                            int total)
{
    int idx = blockIdx.x * blockDim.x + threadIdx.x;
    if (idx >= total) return;
    int i = idx & 63;
    int tmp = idx >> 6;
    int h = tmp % H;
    int s = tmp / H;
    float c = cs[s * 64 + i];
    float si = sn[s * 64 + i];
    float* p = t + (size_t)s * rowstride + h * HD + 2 * i;
    float re = p[0], im = p[1];
    p[0] = re * c - im * si;
    p[1] = re * si + im * c;
}

// ---------------------------------------------------------------------------
// Flash attention: S = QK^T in fp16 (m16n8k16), PV in tf32 (m16n8k8).
// Br=Bc=64, 4 warps. Output written as fp16 (A operand of final GEMM).
// fp16 Q/K rows are HD=128 halfs = 64 u32 words -> stride 68 (64 + 4 pad).
// smem: region0 = Qh (fp16, 64x68 w) overlaid by Ps (fp32 P, 64x68 w);
//       region1 = Kh (fp16, 64x68 w) overlaid by Vf (tf32, 64x132 w).
// ---------------------------------------------------------------------------
#define FBR 64
#define QKSTR 68     // u32 words per Q/K row: 64 + 4 pad (mod 32 == 4)
#define FSTR 132     // fp32 V tile stride
#define PSTR 68      // fp32 P tile stride
#define REGION0_W (64 * QKSTR)                 // 4352 (== 64*PSTR)
#define FLASH_SMEM_W (REGION0_W + 64 * FSTR)   // 4352 + 8448 = 12800 words

__global__ __launch_bounds__(128, 2) void flash_kernel(
    const float* __restrict__ Q, const float* __restrict__ K,
    const float* __restrict__ V, __half* __restrict__ O)
{
    extern __shared__ uint32_t smu[];
    uint32_t* Qh  = smu;                   // fp16 Q tile (half2 words)
    uint32_t* Ps  = smu;                   // fp32 P tile (overlays Qh)
    uint32_t* Kh  = smu + REGION0_W;       // fp16 K tile
    uint32_t* Vf  = smu + REGION0_W;       // fp32 V tile (overlays Kh)

    int tid = threadIdx.x;
    int w = tid >> 5, lane = tid & 31;
    int g = lane >> 2, tg = lane & 3;
    int r0 = blockIdx.x * FBR;
    int h = blockIdx.y, kvh = h >> 2;
    const float scale = 0.08838834764831845f;

    // Stage Q tile as fp16 (scaled)
    for (int t = tid; t < FBR * HD / 4; t += 128) {
        int row = t >> 5, c4 = (t & 31) << 2;
        float4 v = *(const float4*)&Q[(size_t)(r0 + row) * DIM + h * HD + c4];
        __half2 h0 = __floats2half2_rn(v.x * scale, v.y * scale);
        __half2 h1 = __floats2half2_rn(v.z * scale, v.w * scale);
        *(uint2*)&Qh[row * QKSTR + (c4 >> 1)] =
            make_uint2(*(uint32_t*)&h0, *(uint32_t*)&h1);
    }
    __syncthreads();

    // Cache Q a-fragments (8 k16-steps x 4 half2 regs), loop-invariant
    uint32_t qa[8][4];
    {
        int mrow = (16 * w + g) * QKSTR;
        #pragma unroll
        for (int ks = 0; ks < 8; ks++) {
            int k0 = ks * 8;
            qa[ks][0] = Qh[mrow + k0 + tg];
            qa[ks][1] = Qh[mrow + 8 * QKSTR + k0 + tg];
            qa[ks][2] = Qh[mrow + k0 + tg + 4];
            qa[ks][3] = Qh[mrow + 8 * QKSTR + k0 + tg + 4];
        }
    }
    __syncthreads();   // Qh dead; Ps may overlay

    float m0 = -1e30f, m1 = -1e30f, l0 = 0.f, l1 = 0.f;
    float o[16][4];
    #pragma unroll
    for (int nt = 0; nt < 16; nt++)
        #pragma unroll
        for (int i = 0; i < 4; i++) o[nt][i] = 0.f;

    int qrow_g = r0 + 16 * w + g;
    int diag = blockIdx.x;

    for (int kt = 0; kt <= diag; kt++) {
        int c0 = kt * FBR;
        __syncthreads();   // prev PV done with V region
        // Load K tile as fp16
        for (int t = tid; t < FBR * HD / 4; t += 128) {
            int row = t >> 5, c4 = (t & 31) << 2;
            float4 v = *(const float4*)&K[(size_t)(c0 + row) * KVDIM + kvh * HD + c4];
            __half2 h0 = __floats2half2_rn(v.x, v.y);
            __half2 h1 = __floats2half2_rn(v.z, v.w);
            *(uint2*)&Kh[row * QKSTR + (c4 >> 1)] =
                make_uint2(*(uint32_t*)&h0, *(uint32_t*)&h1);
        }
        __syncthreads();

        // ---- S = Q @ K^T (fp16 mma, 8 k16-steps) ----
        float sacc[8][4];
        #pragma unroll
        for (int nt = 0; nt < 8; nt++)
            #pragma unroll
            for (int i = 0; i < 4; i++) sacc[nt][i] = 0.f;

        #pragma unroll
        for (int ks = 0; ks < 8; ks++) {
            int k0 = ks * 8;
            #pragma unroll
            for (int nt = 0; nt < 8; nt++) {
                uint32_t b[2];
                int nrow = (8 * nt + g) * QKSTR;
                b[0] = Kh[nrow + k0 + tg];
                b[1] = Kh[nrow + k0 + tg + 4];
                mma_f16(sacc[nt], qa[ks], b);
            }
        }

        if (kt == diag) {
            #pragma unroll
            for (int nt = 0; nt < 8; nt++) {
                int col = c0 + 8 * nt + 2 * tg;
                if (col > qrow_g)          sacc[nt][0] = -1e30f;
                if (col + 1 > qrow_g)      sacc[nt][1] = -1e30f;
                if (col > qrow_g + 8)      sacc[nt][2] = -1e30f;
                if (col + 1 > qrow_g + 8)  sacc[nt][3] = -1e30f;
            }
        }

        // ---- online softmax ----
        float mx0 = -1e30f, mx1 = -1e30f;
        #pragma unroll
        for (int nt = 0; nt < 8; nt++) {
            mx0 = fmaxf(mx0, fmaxf(sacc[nt][0], sacc[nt][1]));
            mx1 = fmaxf(mx1, fmaxf(sacc[nt][2], sacc[nt][3]));
        }
        #pragma unroll
        for (int off = 2; off >= 1; off >>= 1) {
            mx0 = fmaxf(mx0, __shfl_xor_sync(0xffffffffu, mx0, off));
            mx1 = fmaxf(mx1, __shfl_xor_sync(0xffffffffu, mx1, off));
        }
        float mn0 = fmaxf(m0, mx0), mn1 = fmaxf(m1, mx1);
        float cor0 = __expf(m0 - mn0), cor1 = __expf(m1 - mn1);
        float ps0 = 0.f, ps1 = 0.f;
        #pragma unroll
        for (int nt = 0; nt < 8; nt++) {
            sacc[nt][0] = __expf(sacc[nt][0] - mn0);
            sacc[nt][1] = __expf(sacc[nt][1] - mn0);
            sacc[nt][2] = __expf(sacc[nt][2] - mn1);
            sacc[nt][3] = __expf(sacc[nt][3] - mn1);
            ps0 += sacc[nt][0] + sacc[nt][1];
            ps1 += sacc[nt][2] + sacc[nt][3];
        }
        #pragma unroll
        for (int off = 2; off >= 1; off >>= 1) {
            ps0 += __shfl_xor_sync(0xffffffffu, ps0, off);
            ps1 += __shfl_xor_sync(0xffffffffu, ps1, off);
        }
        l0 = l0 * cor0 + ps0;  m0 = mn0;
        l1 = l1 * cor1 + ps1;  m1 = mn1;
        #pragma unroll
        for (int nt = 0; nt < 16; nt++) {
            o[nt][0] *= cor0; o[nt][1] *= cor0;
            o[nt][2] *= cor1; o[nt][3] *= cor1;
        }
        // P -> smem as tf32
        #pragma unroll
        for (int nt = 0; nt < 8; nt++) {
            int col = 8 * nt + 2 * tg;
            uint2 p0 = make_uint2(f2tf32(sacc[nt][0]), f2tf32(sacc[nt][1]));
            uint2 p1 = make_uint2(f2tf32(sacc[nt][2]), f2tf32(sacc[nt][3]));
            *(uint2*)&Ps[(16 * w + g) * PSTR + col] = p0;
            *(uint2*)&Ps[(16 * w + g + 8) * PSTR + col] = p1;
        }

        __syncthreads();   // K reads done; load V (fp32/tf32) over it
        for (int t = tid; t < FBR * HD / 4; t += 128) {
            int row = t >> 5, c4 = (t & 31) << 2;
            float4 v = *(const float4*)&V[(size_t)(c0 + row) * KVDIM + kvh * HD + c4];
            uint4 u;
            u.x = f2tf32(v.x); u.y = f2tf32(v.y);
            u.z = f2tf32(v.z); u.w = f2tf32(v.w);
            *(uint4*)&Vf[row * FSTR + c4] = u;
        }
        __syncthreads();

        // ---- O += P @ V (tf32 mma) ----
        #pragma unroll
        for (int ks = 0; ks < 8; ks++) {
            int k0 = ks * 8;
            uint32_t a[4];
            int mrow = (16 * w + g) * PSTR;
            a[0] = Ps[mrow + k0 + tg];
            a[1] = Ps[mrow + 8 * PSTR + k0 + tg];
            a[2] = Ps[mrow + k0 + tg + 4];
            a[3] = Ps[mrow + 8 * PSTR + k0 + tg + 4];
            #pragma unroll
            for (int nt = 0; nt < 16; nt++) {
                uint32_t b[2];
                b[0] = Vf[(k0 + tg) * FSTR + 8 * nt + g];
                b[1] = Vf[(k0 + tg + 4) * FSTR + 8 * nt + g];
                mma_tf32(o[nt], a, b);
            }
        }
    }

    // Finalize; store as fp16 (feeds final fp16 GEMM)
    float i0 = 1.f / l0, i1 = 1.f / l1;
    #pragma unroll
    for (int nt = 0; nt < 16; nt++) {
        int col = h * HD + 8 * nt + 2 * tg;
        __half2 h0 = __floats2half2_rn(o[nt][0] * i0, o[nt][1] * i0);
        __half2 h1 = __floats2half2_rn(o[nt][2] * i1, o[nt][3] * i1);
        *(uint32_t*)&O[(size_t)qrow_g * DIM + col] = *(uint32_t*)&h0;
        *(uint32_t*)&O[(size_t)(qrow_g + 8) * DIM + col] = *(uint32_t*)&h1;
    }
}

// ---------------------------------------------------------------------------
// Launch
// ---------------------------------------------------------------------------
extern "C" void kernel_launch(void* const* d_in, const int* in_sizes, int n_in,
                              void* d_out, int out_size)
{
    const float* x  = (const float*)d_in[0];
    const float* wq = (const float*)d_in[1];
    const float* wk = (const float*)d_in[2];
    const float* wv = (const float*)d_in[3];
    const float* wo = (const float*)d_in[4];
    const float* fc = (const float*)d_in[5];
    const float* fs = (const float*)d_in[6];

    float *Qp, *Kp, *Vp;
    __half *A16, *X16, *WqT, *WkT, *WvT, *WoT;
    cudaGetSymbolAddress((void**)&Qp, g_Q);
    cudaGetSymbolAddress((void**)&Kp, g_K);
    cudaGetSymbolAddress((void**)&Vp, g_V);
    cudaGetSymbolAddress((void**)&A16, g_attn16);
    cudaGetSymbolAddress((void**)&X16, g_x16);
    cudaGetSymbolAddress((void**)&WqT, g_wqT);
    cudaGetSymbolAddress((void**)&WkT, g_wkT);
    cudaGetSymbolAddress((void**)&WvT, g_wvT);
    cudaGetSymbolAddress((void**)&WoT, g_woT);

    // Pre-passes
    convert_half_kernel<<<SEQ * DIM / 4 / 256, 256>>>(x, X16, SEQ * DIM);
    dim3 tb(32, 8);
    transpose_half_kernel<<<dim3(DIM / 32, DIM / 32), tb>>>(wq, WqT, DIM, DIM);
    transpose_half_kernel<<<dim3(KVDIM / 32, DIM / 32), tb>>>(wk, WkT, DIM, KVDIM);
    transpose_half_kernel<<<dim3(KVDIM / 32, DIM / 32), tb>>>(wv, WvT, DIM, KVDIM);
    transpose_half_kernel<<<dim3(DIM / 32, DIM / 32), tb>>>(wo, WoT, DIM, DIM);

    int gsm = 4 * TILE_WORDS * (int)sizeof(uint32_t);   // 2 stages x (A+B)
    cudaFuncSetAttribute(gemm_f16_kernel,
                         cudaFuncAttributeMaxDynamicSharedMemorySize, gsm);

    // Projections (fp16 tensor cores)
    gemm_f16_kernel<<<dim3(DIM / GBN, SEQ / GBM), 128, gsm>>>(
        X16, WqT, Qp, SEQ, DIM, DIM);
    gemm_f16_kernel<<<dim3(KVDIM / GBN, SEQ / GBM), 128, gsm>>>(
        X16, WkT, Kp, SEQ, KVDIM, DIM);
    gemm_f16_kernel<<<dim3(KVDIM / GBN, SEQ / GBM), 128, gsm>>>(
        X16, WvT, Vp, SEQ, KVDIM, DIM);

    // RoPE (fp32, in place)
    int totQ = SEQ * NH * 64, totK = SEQ * NKV * 64;
    rope_kernel<<<(totQ + 255) / 256, 256>>>(Qp, fc, fs, NH, DIM, totQ);
    rope_kernel<<<(totK + 255) / 256, 256>>>(Kp, fc, fs, NKV, KVDIM, totK);

    // Flash attention (fp16 S, tf32 PV) -> fp16 attn
    int fsm = FLASH_SMEM_W * (int)sizeof(uint32_t);
    cudaFuncSetAttribute(flash_kernel,
                         cudaFuncAttributeMaxDynamicSharedMemorySize, fsm);
    flash_kernel<<<dim3(SEQ / FBR, NH), 128, fsm>>>(Qp, Kp, Vp, A16);

    // Output projection (fp16) -> d_out (fp32)
    gemm_f16_kernel<<<dim3(DIM / GBN, SEQ / GBM), 128, gsm>>>(
        A16, WoT, (float*)d_out, SEQ, DIM, DIM);
}

// round 10
// speedup vs baseline: 6.5887x; 1.2057x over previous
#include <cuda_runtime.h>
#include <cuda_fp16.h>
#include <math.h>
#include <stdint.h>

#define SEQ 2048
#define DIM 4096
#define NH 32
#define NKV 8
#define HD 128
#define KVDIM 1024

// Scratch (allocation-free rule: device globals)
__device__ float  g_Q[SEQ * DIM];          // fp32 Q projection
__device__ float  g_K[SEQ * KVDIM];        // fp32 K projection
__device__ float  g_V[SEQ * KVDIM];        // fp32 V projection
__device__ __half g_Q16[SEQ * DIM];        // roped+scaled Q, fp16
__device__ __half g_K16[SEQ * KVDIM];      // roped K, fp16
__device__ __half g_vT[KVDIM * SEQ];       // V^T fp16 [KVDIM][SEQ]
__device__ __half g_attn16[SEQ * DIM];     // flash output, fp16
__device__ __half g_x16[SEQ * DIM];        // x, fp16
__device__ __half g_wqT[DIM * DIM];        // Wq^T [N][K] fp16
__device__ __half g_wkT[DIM * KVDIM];
__device__ __half g_wvT[DIM * KVDIM];
__device__ __half g_woT[DIM * DIM];

// ---------------------------------------------------------------------------
// Helpers
// ---------------------------------------------------------------------------
__device__ __forceinline__ void mma_f16(float c[4], const uint32_t a[4],
                                        const uint32_t b[2]) {
    asm volatile(
        "mma.sync.aligned.m16n8k16.row.col.f32.f16.f16.f32 "
        "{%0,%1,%2,%3}, {%4,%5,%6,%7}, {%8,%9}, {%0,%1,%2,%3};"
        : "+f"(c[0]), "+f"(c[1]), "+f"(c[2]), "+f"(c[3])
        : "r"(a[0]), "r"(a[1]), "r"(a[2]), "r"(a[3]), "r"(b[0]), "r"(b[1]));
}

__device__ __forceinline__ void cpa16(uint32_t smem_addr, const void* gptr) {
    asm volatile("cp.async.cg.shared.global [%0], [%1], 16;"
                 :: "r"(smem_addr), "l"(gptr));
}
__device__ __forceinline__ void cpa_commit() {
    asm volatile("cp.async.commit_group;");
}
template <int N>
__device__ __forceinline__ void cpa_wait() {
    asm volatile("cp.async.wait_group %0;" :: "n"(N));
}

// ---------------------------------------------------------------------------
// Pre-passes
// ---------------------------------------------------------------------------
__global__ void convert_half_kernel(const float* __restrict__ in,
                                    __half* __restrict__ out, int n)
{
    int i = (blockIdx.x * blockDim.x + threadIdx.x) * 4;
    if (i >= n) return;
    float4 v = *(const float4*)&in[i];
    __half2 h0 = __floats2half2_rn(v.x, v.y);
    __half2 h1 = __floats2half2_rn(v.z, v.w);
    *(uint2*)&out[i] = make_uint2(*(uint32_t*)&h0, *(uint32_t*)&h1);
}

// in [R][C] fp32 -> out [C][R] fp16
__global__ void transpose_half_kernel(const float* __restrict__ in,
                                      __half* __restrict__ out, int R, int C)
{
    __shared__ float tile[32][33];
    int c0 = blockIdx.x * 32, r0 = blockIdx.y * 32;
    int tx = threadIdx.x, ty = threadIdx.y;
    #pragma unroll
    for (int j = 0; j < 32; j += 8)
        tile[ty + j][tx] = in[(size_t)(r0 + ty + j) * C + c0 + tx];
    __syncthreads();
    #pragma unroll
    for (int j = 0; j < 32; j += 8)
        out[(size_t)(c0 + ty + j) * R + r0 + tx] = __float2half(tile[tx][ty + j]);
}

// RoPE + fp16 convert (+ optional pre-scale): fp32 in -> fp16 out
__global__ void rope_half_kernel(const float* __restrict__ in,
                                 __half* __restrict__ out,
                                 const float* __restrict__ cs,
                                 const float* __restrict__ sn,
                                 int H, int rowstride, float mul, int total)
{
    int idx = blockIdx.x * blockDim.x + threadIdx.x;
    if (idx >= total) return;
    int i = idx & 63;
    int tmp = idx >> 6;
    int h = tmp % H;
    int s = tmp / H;
    float c = cs[s * 64 + i];
    float si = sn[s * 64 + i];
    const float* p = in + (size_t)s * rowstride + h * HD + 2 * i;
    float re = p[0], im = p[1];
    __half2 hh = __floats2half2_rn((re * c - im * si) * mul,
                                   (re * si + im * c) * mul);
    *(uint32_t*)&out[(size_t)s * rowstride + h * HD + 2 * i] = *(uint32_t*)&hh;
}

// ---------------------------------------------------------------------------
// FP16 GEMM: C[M,N] = A[M,K] @ BT[N,K]^T, fp32 accumulate.
// A, BT fp16 K-major. CTA 128x128, K-chunk 64, 4 warps, warp tile 64x64,
// mma.m16n8k16, cp.async 2-stage.
// ---------------------------------------------------------------------------
#define GBM 128
#define GBN 128
#define GKC 64
#define HSTR 36
#define TILE_WORDS (128 * HSTR)

__global__ __launch_bounds__(128, 2) void gemm_f16_kernel(
    const __half* __restrict__ A, const __half* __restrict__ BT,
    float* __restrict__ C, int M, int N, int K)
{
    extern __shared__ uint32_t smg[];
    uint32_t sbase = (uint32_t)__cvta_generic_to_shared(smg);

    int tid = threadIdx.x;
    int wid = tid >> 5, lane = tid & 31;
    int g = lane >> 2, tg = lane & 3;
    int warp_m = (wid >> 1) * 64;
    int warp_n = (wid & 1) * 64;
    int m0 = blockIdx.y * GBM, n0 = blockIdx.x * GBN;

    float acc[4][8][4];
    #pragma unroll
    for (int mt = 0; mt < 4; mt++)
        #pragma unroll
        for (int nt = 0; nt < 8; nt++)
            #pragma unroll
            for (int i = 0; i < 4; i++) acc[mt][nt][i] = 0.f;

    int niter = K / GKC;

    #define ISSUE_COPY(IT, STG)                                               \
    do {                                                                      \
        uint32_t aOff = sbase + (uint32_t)(STG) * (2 * TILE_WORDS) * 4;       \
        uint32_t bOff = aOff + TILE_WORDS * 4;                                \
        const __half* Ab = A + (size_t)m0 * K + (IT) * GKC;                   \
        const __half* Bb = BT + (size_t)n0 * K + (IT) * GKC;                  \
        _Pragma("unroll")                                                     \
        for (int i = 0; i < 8; i++) {                                         \
            int c = tid + i * 128;                                            \
            int r = c >> 3, cc = c & 7;                                       \
            cpa16(aOff + r * 144 + cc * 16, Ab + (size_t)r * K + cc * 8);     \
        }                                                                     \
        _Pragma("unroll")                                                     \
        for (int i = 0; i < 8; i++) {                                         \
            int c = tid + i * 128;                                            \
            int r = c >> 3, cc = c & 7;                                       \
            cpa16(bOff + r * 144 + cc * 16, Bb + (size_t)r * K + cc * 8);     \
        }                                                                     \
        cpa_commit();                                                         \
    } while (0)

    ISSUE_COPY(0, 0);

    for (int it = 0; it < niter; it++) {
        int cur = it & 1;
        if (it + 1 < niter) {
            ISSUE_COPY(it + 1, (it + 1) & 1);
            cpa_wait<1>();
        } else {
            cpa_wait<0>();
        }
        __syncthreads();

        const uint32_t* As = smg + (size_t)cur * 2 * TILE_WORDS;
        const uint32_t* Bs = As + TILE_WORDS;

        #pragma unroll
        for (int ks = 0; ks < 4; ks++) {
            int k0 = ks * 8;
            uint32_t aR[4][4];
            #pragma unroll
            for (int mt = 0; mt < 4; mt++) {
                int m = warp_m + mt * 16 + g;
                aR[mt][0] = As[m * HSTR + k0 + tg];
                aR[mt][1] = As[(m + 8) * HSTR + k0 + tg];
                aR[mt][2] = As[m * HSTR + k0 + tg + 4];
                aR[mt][3] = As[(m + 8) * HSTR + k0 + tg + 4];
            }
            uint32_t bR[8][2];
            #pragma unroll
            for (int nt = 0; nt < 8; nt++) {
                int n = warp_n + nt * 8 + g;
                bR[nt][0] = Bs[n * HSTR + k0 + tg];
                bR[nt][1] = Bs[n * HSTR + k0 + tg + 4];
            }
            #pragma unroll
            for (int mt = 0; mt < 4; mt++)
                #pragma unroll
                for (int nt = 0; nt < 8; nt++)
                    mma_f16(acc[mt][nt], aR[mt], bR[nt]);
        }
        __syncthreads();
    }

    #pragma unroll
    for (int mt = 0; mt < 4; mt++) {
        int m = m0 + warp_m + mt * 16 + g;
        #pragma unroll
        for (int nt = 0; nt < 8; nt++) {
            int n = n0 + warp_n + nt * 8 + 2 * tg;
            *(float2*)&C[(size_t)m * N + n] =
                make_float2(acc[mt][nt][0], acc[mt][nt][1]);
            *(float2*)&C[(size_t)(m + 8) * N + n] =
                make_float2(acc[mt][nt][2], acc[mt][nt][3]);
        }
    }
}

// ---------------------------------------------------------------------------
// Flash attention, all-fp16 operands: S = QK^T and O += P@V via m16n8k16.
// Q/K pre-roped fp16; V pre-transposed fp16 [KVDIM][SEQ]; P fp16 in smem.
// smem: region0 = Qh (64x68 w) overlaid by Ps16 (64x36 w);
//       region1 = Kh (64x68 w) overlaid by VtS (128x36 w).
// ---------------------------------------------------------------------------
#define FBR 64
#define QKSTR 68     // Q/K row: 64 words (128 halfs) + 4 pad
#define P16STR 36    // P row: 32 words (64 halfs) + 4 pad
#define VSTR 36      // Vt row: 32 words (64 halfs) + 4 pad
#define REGION0_W (64 * QKSTR)                  // 4352
#define REGION1_W (128 * VSTR)                  // 4608 = max(64*68, 128*36)
#define FLASH_SMEM_W (REGION0_W + REGION1_W)    // 8960 words = 35840 B

__global__ __launch_bounds__(128, 2) void flash_kernel(
    const __half* __restrict__ Q16, const __half* __restrict__ K16,
    const __half* __restrict__ Vt, __half* __restrict__ O)
{
    extern __shared__ uint32_t smu[];
    uint32_t* Qh   = smu;                   // fp16 Q tile
    uint32_t* Ps16 = smu;                   // fp16 P tile (overlays Qh)
    uint32_t* Kh   = smu + REGION0_W;       // fp16 K tile
    uint32_t* VtS  = smu + REGION0_W;       // fp16 V^T tile (overlays Kh)

    int tid = threadIdx.x;
    int w = tid >> 5, lane = tid & 31;
    int g = lane >> 2, tg = lane & 3;
    int r0 = blockIdx.x * FBR;
    int h = blockIdx.y, kvh = h >> 2;

    // Stage Q tile (already roped+scaled fp16): 64 rows x 16 uint4
    for (int t = tid; t < FBR * 16; t += 128) {
        int row = t >> 4, c = t & 15;
        *(uint4*)&Qh[row * QKSTR + c * 4] =
            *(const uint4*)&Q16[(size_t)(r0 + row) * DIM + h * HD + c * 8];
    }
    __syncthreads();

    // Cache Q a-fragments (8 k16-steps), loop-invariant
    uint32_t qa[8][4];
    {
        int mrow = (16 * w + g) * QKSTR;
        #pragma unroll
        for (int ks = 0; ks < 8; ks++) {
            int k0 = ks * 8;
            qa[ks][0] = Qh[mrow + k0 + tg];
            qa[ks][1] = Qh[mrow + 8 * QKSTR + k0 + tg];
            qa[ks][2] = Qh[mrow + k0 + tg + 4];
            qa[ks][3] = Qh[mrow + 8 * QKSTR + k0 + tg + 4];
        }
    }
    __syncthreads();   // Qh dead; Ps16 may overlay

    float m0 = -1e30f, m1 = -1e30f, l0 = 0.f, l1 = 0.f;
    float o[16][4];
    #pragma unroll
    for (int nt = 0; nt < 16; nt++)
        #pragma unroll
        for (int i = 0; i < 4; i++) o[nt][i] = 0.f;

    int qrow_g = r0 + 16 * w + g;
    int diag = blockIdx.x;

    for (int kt = 0; kt <= diag; kt++) {
        int c0 = kt * FBR;
        __syncthreads();   // prev PV done with VtS
        // Load K tile (fp16): 64 rows x 16 uint4
        for (int t = tid; t < FBR * 16; t += 128) {
            int row = t >> 4, c = t & 15;
            *(uint4*)&Kh[row * QKSTR + c * 4] =
                *(const uint4*)&K16[(size_t)(c0 + row) * KVDIM + kvh * HD + c * 8];
        }
        __syncthreads();

        // ---- S = Q @ K^T (fp16, 8 k16-steps) ----
        float sacc[8][4];
        #pragma unroll
        for (int nt = 0; nt < 8; nt++)
            #pragma unroll
            for (int i = 0; i < 4; i++) sacc[nt][i] = 0.f;

        #pragma unroll
        for (int ks = 0; ks < 8; ks++) {
            int k0 = ks * 8;
            #pragma unroll
            for (int nt = 0; nt < 8; nt++) {
                uint32_t b[2];
                int nrow = (8 * nt + g) * QKSTR;
                b[0] = Kh[nrow + k0 + tg];
                b[1] = Kh[nrow + k0 + tg + 4];
                mma_f16(sacc[nt], qa[ks], b);
            }
        }

        if (kt == diag) {
            #pragma unroll
            for (int nt = 0; nt < 8; nt++) {
                int col = c0 + 8 * nt + 2 * tg;
                if (col > qrow_g)          sacc[nt][0] = -1e30f;
                if (col + 1 > qrow_g)      sacc[nt][1] = -1e30f;
                if (col > qrow_g + 8)      sacc[nt][2] = -1e30f;
                if (col + 1 > qrow_g + 8)  sacc[nt][3] = -1e30f;
            }
        }

        // ---- online softmax ----
        float mx0 = -1e30f, mx1 = -1e30f;
        #pragma unroll
        for (int nt = 0; nt < 8; nt++) {
            mx0 = fmaxf(mx0, fmaxf(sacc[nt][0], sacc[nt][1]));
            mx1 = fmaxf(mx1, fmaxf(sacc[nt][2], sacc[nt][3]));
        }
        #pragma unroll
        for (int off = 2; off >= 1; off >>= 1) {
            mx0 = fmaxf(mx0, __shfl_xor_sync(0xffffffffu, mx0, off));
            mx1 = fmaxf(mx1, __shfl_xor_sync(0xffffffffu, mx1, off));
        }
        float mn0 = fmaxf(m0, mx0), mn1 = fmaxf(m1, mx1);
        float cor0 = __expf(m0 - mn0), cor1 = __expf(m1 - mn1);
        float ps0 = 0.f, ps1 = 0.f;
        #pragma unroll
        for (int nt = 0; nt < 8; nt++) {
            sacc[nt][0] = __expf(sacc[nt][0] - mn0);
            sacc[nt][1] = __expf(sacc[nt][1] - mn0);
            sacc[nt][2] = __expf(sacc[nt][2] - mn1);
            sacc[nt][3] = __expf(sacc[nt][3] - mn1);
            ps0 += sacc[nt][0] + sacc[nt][1];
            ps1 += sacc[nt][2] + sacc[nt][3];
        }
        #pragma unroll
        for (int off = 2; off >= 1; off >>= 1) {
            ps0 += __shfl_xor_sync(0xffffffffu, ps0, off);
            ps1 += __shfl_xor_sync(0xffffffffu, ps1, off);
        }
        l0 = l0 * cor0 + ps0;  m0 = mn0;
        l1 = l1 * cor1 + ps1;  m1 = mn1;
        #pragma unroll
        for (int nt = 0; nt < 16; nt++) {
            o[nt][0] *= cor0; o[nt][1] *= cor0;
            o[nt][2] *= cor1; o[nt][3] *= cor1;
        }
        // P -> smem as fp16 (own warp's rows only; no cross-warp hazard)
        #pragma unroll
        for (int nt = 0; nt < 8; nt++) {
            __half2 p0 = __floats2half2_rn(sacc[nt][0], sacc[nt][1]);
            __half2 p1 = __floats2half2_rn(sacc[nt][2], sacc[nt][3]);
            Ps16[(16 * w + g) * P16STR + nt * 4 + tg] = *(uint32_t*)&p0;
            Ps16[(16 * w + g + 8) * P16STR + nt * 4 + tg] = *(uint32_t*)&p1;
        }

        __syncthreads();   // all warps done reading Kh; load V^T over it
        // V^T tile: 128 d-rows x 64 t-cols fp16 = 128 x 8 uint4
        for (int t = tid; t < 128 * 8; t += 128) {
            int r = t >> 3, c = t & 7;
            *(uint4*)&VtS[r * VSTR + c * 4] =
                *(const uint4*)&Vt[(size_t)(kvh * HD + r) * SEQ + c0 + c * 8];
        }
        __syncthreads();

        // ---- O += P @ V (fp16, 4 k16-steps x 16 n-blocks) ----
        #pragma unroll
        for (int ks = 0; ks < 4; ks++) {
            int k0 = ks * 8;
            uint32_t a[4];
            int mrow = (16 * w + g) * P16STR;
            a[0] = Ps16[mrow + k0 + tg];
            a[1] = Ps16[mrow + 8 * P16STR + k0 + tg];
            a[2] = Ps16[mrow + k0 + tg + 4];
            a[3] = Ps16[mrow + 8 * P16STR + k0 + tg + 4];
            #pragma unroll
            for (int nt = 0; nt < 16; nt++) {
                uint32_t b[2];
                int nrow = (8 * nt + g) * VSTR;
                b[0] = VtS[nrow + k0 + tg];
                b[1] = VtS[nrow + k0 + tg + 4];
                mma_f16(o[nt], a, b);
            }
        }
    }

    // Finalize; store as fp16 (feeds final fp16 GEMM)
    float i0 = 1.f / l0, i1 = 1.f / l1;
    #pragma unroll
    for (int nt = 0; nt < 16; nt++) {
        int col = h * HD + 8 * nt + 2 * tg;
        __half2 h0 = __floats2half2_rn(o[nt][0] * i0, o[nt][1] * i0);
        __half2 h1 = __floats2half2_rn(o[nt][2] * i1, o[nt][3] * i1);
        *(uint32_t*)&O[(size_t)qrow_g * DIM + col] = *(uint32_t*)&h0;
        *(uint32_t*)&O[(size_t)(qrow_g + 8) * DIM + col] = *(uint32_t*)&h1;
    }
}

// ---------------------------------------------------------------------------
// Launch
// ---------------------------------------------------------------------------
extern "C" void kernel_launch(void* const* d_in, const int* in_sizes, int n_in,
                              void* d_out, int out_size)
{
    const float* x  = (const float*)d_in[0];
    const float* wq = (const float*)d_in[1];
    const float* wk = (const float*)d_in[2];
    const float* wv = (const float*)d_in[3];
    const float* wo = (const float*)d_in[4];
    const float* fc = (const float*)d_in[5];
    const float* fs = (const float*)d_in[6];

    float *Qp, *Kp, *Vp;
    __half *Q16, *K16, *VT, *A16, *X16, *WqT, *WkT, *WvT, *WoT;
    cudaGetSymbolAddress((void**)&Qp, g_Q);
    cudaGetSymbolAddress((void**)&Kp, g_K);
    cudaGetSymbolAddress((void**)&Vp, g_V);
    cudaGetSymbolAddress((void**)&Q16, g_Q16);
    cudaGetSymbolAddress((void**)&K16, g_K16);
    cudaGetSymbolAddress((void**)&VT, g_vT);
    cudaGetSymbolAddress((void**)&A16, g_attn16);
    cudaGetSymbolAddress((void**)&X16, g_x16);
    cudaGetSymbolAddress((void**)&WqT, g_wqT);
    cudaGetSymbolAddress((void**)&WkT, g_wkT);
    cudaGetSymbolAddress((void**)&WvT, g_wvT);
    cudaGetSymbolAddress((void**)&WoT, g_woT);

    // Pre-passes
    convert_half_kernel<<<SEQ * DIM / 4 / 256, 256>>>(x, X16, SEQ * DIM);
    dim3 tb(32, 8);
    transpose_half_kernel<<<dim3(DIM / 32, DIM / 32), tb>>>(wq, WqT, DIM, DIM);
    transpose_half_kernel<<<dim3(KVDIM / 32, DIM / 32), tb>>>(wk, WkT, DIM, KVDIM);
    transpose_half_kernel<<<dim3(KVDIM / 32, DIM / 32), tb>>>(wv, WvT, DIM, KVDIM);
    transpose_half_kernel<<<dim3(DIM / 32, DIM / 32), tb>>>(wo, WoT, DIM, DIM);

    int gsm = 4 * TILE_WORDS * (int)sizeof(uint32_t);
    cudaFuncSetAttribute(gemm_f16_kernel,
                         cudaFuncAttributeMaxDynamicSharedMemorySize, gsm);

    // Projections (fp16 tensor cores)
    gemm_f16_kernel<<<dim3(DIM / GBN, SEQ / GBM), 128, gsm>>>(
        X16, WqT, Qp, SEQ, DIM, DIM);
    gemm_f16_kernel<<<dim3(KVDIM / GBN, SEQ / GBM), 128, gsm>>>(
        X16, WkT, Kp, SEQ, KVDIM, DIM);
    gemm_f16_kernel<<<dim3(KVDIM / GBN, SEQ / GBM), 128, gsm>>>(
        X16, WvT, Vp, SEQ, KVDIM, DIM);

    // RoPE -> fp16 (Q pre-scaled by 1/sqrt(HD)); V -> fp16 transposed
    const float qscale = 0.08838834764831845f;
    int totQ = SEQ * NH * 64, totK = SEQ * NKV * 64;
    rope_half_kernel<<<(totQ + 255) / 256, 256>>>(Qp, Q16, fc, fs, NH, DIM,
                                                  qscale, totQ);
    rope_half_kernel<<<(totK + 255) / 256, 256>>>(Kp, K16, fc, fs, NKV, KVDIM,
                                                  1.0f, totK);
    transpose_half_kernel<<<dim3(KVDIM / 32, SEQ / 32), tb>>>(Vp, VT, SEQ, KVDIM);

    // Flash attention (all-fp16 operands) -> fp16 attn
    int fsm = FLASH_SMEM_W * (int)sizeof(uint32_t);
    cudaFuncSetAttribute(flash_kernel,
                         cudaFuncAttributeMaxDynamicSharedMemorySize, fsm);
    flash_kernel<<<dim3(SEQ / FBR, NH), 128, fsm>>>(Q16, K16, VT, A16);

    // Output projection (fp16) -> d_out (fp32)
    gemm_f16_kernel<<<dim3(DIM / GBN, SEQ / GBM), 128, gsm>>>(
        A16, WoT, (float*)d_out, SEQ, DIM, DIM);
}

// round 11
// speedup vs baseline: 6.9234x; 1.0508x over previous
#include <cuda_runtime.h>
#include <cuda_fp16.h>
#include <math.h>
#include <stdint.h>

#define SEQ 2048
#define DIM 4096
#define NH 32
#define NKV 8
#define HD 128
#define KVDIM 1024

// Scratch (allocation-free rule: device globals)
__device__ float  g_Q[SEQ * DIM];          // fp32 Q projection
__device__ float  g_K[SEQ * KVDIM];        // fp32 K projection
__device__ float  g_V[SEQ * KVDIM];        // fp32 V projection
__device__ __half g_Q16[SEQ * DIM];        // roped+scaled Q, fp16
__device__ __half g_K16[SEQ * KVDIM];      // roped K, fp16
__device__ __half g_vT[KVDIM * SEQ];       // V^T fp16 [KVDIM][SEQ]
__device__ __half g_attn16[SEQ * DIM];     // flash output, fp16
__device__ __half g_x16[SEQ * DIM];        // x, fp16
__device__ __half g_wqT[DIM * DIM];        // Wq^T [N][K] fp16
__device__ __half g_wkT[DIM * KVDIM];
__device__ __half g_wvT[DIM * KVDIM];
__device__ __half g_woT[DIM * DIM];

// ---------------------------------------------------------------------------
// Helpers
// ---------------------------------------------------------------------------
__device__ __forceinline__ void mma_f16(float c[4], const uint32_t a[4],
                                        const uint32_t b[2]) {
    asm volatile(
        "mma.sync.aligned.m16n8k16.row.col.f32.f16.f16.f32 "
        "{%0,%1,%2,%3}, {%4,%5,%6,%7}, {%8,%9}, {%0,%1,%2,%3};"
        : "+f"(c[0]), "+f"(c[1]), "+f"(c[2]), "+f"(c[3])
        : "r"(a[0]), "r"(a[1]), "r"(a[2]), "r"(a[3]), "r"(b[0]), "r"(b[1]));
}

__device__ __forceinline__ void ldsm_x4(uint32_t& r0, uint32_t& r1,
                                        uint32_t& r2, uint32_t& r3,
                                        uint32_t addr) {
    asm volatile(
        "ldmatrix.sync.aligned.m8n8.x4.shared.b16 {%0,%1,%2,%3}, [%4];"
        : "=r"(r0), "=r"(r1), "=r"(r2), "=r"(r3) : "r"(addr));
}

__device__ __forceinline__ void cpa16(uint32_t smem_addr, const void* gptr) {
    asm volatile("cp.async.cg.shared.global [%0], [%1], 16;"
                 :: "r"(smem_addr), "l"(gptr));
}
__device__ __forceinline__ void cpa_commit() {
    asm volatile("cp.async.commit_group;");
}
template <int N>
__device__ __forceinline__ void cpa_wait() {
    asm volatile("cp.async.wait_group %0;" :: "n"(N));
}

// ---------------------------------------------------------------------------
// Pre-passes
// ---------------------------------------------------------------------------
__global__ void convert_half_kernel(const float* __restrict__ in,
                                    __half* __restrict__ out, int n)
{
    int i = (blockIdx.x * blockDim.x + threadIdx.x) * 4;
    if (i >= n) return;
    float4 v = *(const float4*)&in[i];
    __half2 h0 = __floats2half2_rn(v.x, v.y);
    __half2 h1 = __floats2half2_rn(v.z, v.w);
    *(uint2*)&out[i] = make_uint2(*(uint32_t*)&h0, *(uint32_t*)&h1);
}

// in [R][C] fp32 -> out [C][R] fp16
__global__ void transpose_half_kernel(const float* __restrict__ in,
                                      __half* __restrict__ out, int R, int C)
{
    __shared__ float tile[32][33];
    int c0 = blockIdx.x * 32, r0 = blockIdx.y * 32;
    int tx = threadIdx.x, ty = threadIdx.y;
    #pragma unroll
    for (int j = 0; j < 32; j += 8)
        tile[ty + j][tx] = in[(size_t)(r0 + ty + j) * C + c0 + tx];
    __syncthreads();
    #pragma unroll
    for (int j = 0; j < 32; j += 8)
        out[(size_t)(c0 + ty + j) * R + r0 + tx] = __float2half(tile[tx][ty + j]);
}

// RoPE + fp16 convert (+ optional pre-scale): fp32 in -> fp16 out
__global__ void rope_half_kernel(const float* __restrict__ in,
                                 __half* __restrict__ out,
                                 const float* __restrict__ cs,
                                 const float* __restrict__ sn,
                                 int H, int rowstride, float mul, int total)
{
    int idx = blockIdx.x * blockDim.x + threadIdx.x;
    if (idx >= total) return;
    int i = idx & 63;
    int tmp = idx >> 6;
    int h = tmp % H;
    int s = tmp / H;
    float c = cs[s * 64 + i];
    float si = sn[s * 64 + i];
    const float* p = in + (size_t)s * rowstride + h * HD + 2 * i;
    float re = p[0], im = p[1];
    __half2 hh = __floats2half2_rn((re * c - im * si) * mul,
                                   (re * si + im * c) * mul);
    *(uint32_t*)&out[(size_t)s * rowstride + h * HD + 2 * i] = *(uint32_t*)&hh;
}

// ---------------------------------------------------------------------------
// FP16 GEMM: C[M,N] = A[M,K] @ BT[N,K]^T, fp32 accumulate.
// A, BT fp16 K-major. CTA 128x128, K-chunk 64, 4 warps, warp tile 64x64,
// mma.m16n8k16, cp.async 2-stage, ldmatrix fragment loads.
// ---------------------------------------------------------------------------
#define GBM 128
#define GBN 128
#define GKC 64
#define HSTR 36                 // u32 words per row (144 B)
#define TILE_WORDS (128 * HSTR)

__global__ __launch_bounds__(128, 2) void gemm_f16_kernel(
    const __half* __restrict__ A, const __half* __restrict__ BT,
    float* __restrict__ C, int M, int N, int K)
{
    extern __shared__ uint32_t smg[];
    uint32_t sbase = (uint32_t)__cvta_generic_to_shared(smg);

    int tid = threadIdx.x;
    int wid = tid >> 5, lane = tid & 31;
    int g = lane >> 2, tg = lane & 3;
    int warp_m = (wid >> 1) * 64;
    int warp_n = (wid & 1) * 64;
    int m0 = blockIdx.y * GBM, n0 = blockIdx.x * GBN;

    // ldmatrix per-lane address components (byte offsets within a tile)
    uint32_t a_lane = (uint32_t)(lane & 15) * 144 + (uint32_t)(lane >> 4) * 16;
    uint32_t b_lane = ((uint32_t)((lane & 7) + ((lane >> 4) & 1) * 8)) * 144
                    + (uint32_t)((lane >> 3) & 1) * 16;

    float acc[4][8][4];
    #pragma unroll
    for (int mt = 0; mt < 4; mt++)
        #pragma unroll
        for (int nt = 0; nt < 8; nt++)
            #pragma unroll
            for (int i = 0; i < 4; i++) acc[mt][nt][i] = 0.f;

    int niter = K / GKC;

    #define ISSUE_COPY(IT, STG)                                               \
    do {                                                                      \
        uint32_t aOff = sbase + (uint32_t)(STG) * (2 * TILE_WORDS) * 4;       \
        uint32_t bOff = aOff + TILE_WORDS * 4;                                \
        const __half* Ab = A + (size_t)m0 * K + (IT) * GKC;                   \
        const __half* Bb = BT + (size_t)n0 * K + (IT) * GKC;                  \
        _Pragma("unroll")                                                     \
        for (int i = 0; i < 8; i++) {                                         \
            int c = tid + i * 128;                                            \
            int r = c >> 3, cc = c & 7;                                       \
            cpa16(aOff + r * 144 + cc * 16, Ab + (size_t)r * K + cc * 8);     \
        }                                                                     \
        _Pragma("unroll")                                                     \
        for (int i = 0; i < 8; i++) {                                         \
            int c = tid + i * 128;                                            \
            int r = c >> 3, cc = c & 7;                                       \
            cpa16(bOff + r * 144 + cc * 16, Bb + (size_t)r * K + cc * 8);     \
        }                                                                     \
        cpa_commit();                                                         \
    } while (0)

    ISSUE_COPY(0, 0);

    for (int it = 0; it < niter; it++) {
        int cur = it & 1;
        if (it + 1 < niter) {
            ISSUE_COPY(it + 1, (it + 1) & 1);
            cpa_wait<1>();
        } else {
            cpa_wait<0>();
        }
        __syncthreads();

        uint32_t As_sh = sbase + (uint32_t)cur * (2 * TILE_WORDS) * 4;
        uint32_t Bs_sh = As_sh + TILE_WORDS * 4;

        #pragma unroll
        for (int ks = 0; ks < 4; ks++) {
            uint32_t aR[4][4];
            #pragma unroll
            for (int mt = 0; mt < 4; mt++)
                ldsm_x4(aR[mt][0], aR[mt][1], aR[mt][2], aR[mt][3],
                        As_sh + (warp_m + mt * 16) * 144 + ks * 32 + a_lane);
            uint32_t bR[8][2];
            #pragma unroll
            for (int p = 0; p < 4; p++)
                ldsm_x4(bR[2 * p][0], bR[2 * p][1],
                        bR[2 * p + 1][0], bR[2 * p + 1][1],
                        Bs_sh + (warp_n + 16 * p) * 144 + ks * 32 + b_lane);
            #pragma unroll
            for (int mt = 0; mt < 4; mt++)
                #pragma unroll
                for (int nt = 0; nt < 8; nt++)
                    mma_f16(acc[mt][nt], aR[mt], bR[nt]);
        }
        __syncthreads();
    }

    #pragma unroll
    for (int mt = 0; mt < 4; mt++) {
        int m = m0 + warp_m + mt * 16 + g;
        #pragma unroll
        for (int nt = 0; nt < 8; nt++) {
            int n = n0 + warp_n + nt * 8 + 2 * tg;
            *(float2*)&C[(size_t)m * N + n] =
                make_float2(acc[mt][nt][0], acc[mt][nt][1]);
            *(float2*)&C[(size_t)(m + 8) * N + n] =
                make_float2(acc[mt][nt][2], acc[mt][nt][3]);
        }
    }
}

// ---------------------------------------------------------------------------
// Flash attention, all-fp16 operands, ldmatrix fragment loads.
// smem: region0 = Qh (64x68 w) overlaid by Ps16 (64x36 w);
//       region1 = Kh (64x68 w) overlaid by VtS (128x36 w).
// ---------------------------------------------------------------------------
#define FBR 64
#define QKSTR 68     // Q/K row: 64 words + 4 pad (272 B)
#define P16STR 36    // P row: 32 words + 4 pad (144 B)
#define VSTR 36      // Vt row (144 B)
#define REGION0_W (64 * QKSTR)                  // 4352
#define REGION1_W (128 * VSTR)                  // 4608
#define FLASH_SMEM_W (REGION0_W + REGION1_W)    // 8960 words = 35840 B

__global__ __launch_bounds__(128, 2) void flash_kernel(
    const __half* __restrict__ Q16, const __half* __restrict__ K16,
    const __half* __restrict__ Vt, __half* __restrict__ O)
{
    extern __shared__ uint32_t smu[];
    uint32_t* Qh   = smu;                   // fp16 Q tile
    uint32_t* Ps16 = smu;                   // fp16 P tile (overlays Qh)
    uint32_t* Kh   = smu + REGION0_W;       // fp16 K tile
    uint32_t* VtS  = smu + REGION0_W;       // fp16 V^T tile (overlays Kh)
    uint32_t sm_sh  = (uint32_t)__cvta_generic_to_shared(smu);
    uint32_t Ps_sh  = sm_sh;
    uint32_t Kh_sh  = sm_sh + REGION0_W * 4;
    uint32_t VtS_sh = sm_sh + REGION0_W * 4;

    int tid = threadIdx.x;
    int w = tid >> 5, lane = tid & 31;
    int g = lane >> 2, tg = lane & 3;
    int r0 = blockIdx.x * FBR;
    int h = blockIdx.y, kvh = h >> 2;

    // ldmatrix per-lane address components
    uint32_t kb_lane = ((uint32_t)((lane & 7) + ((lane >> 4) & 1) * 8)) * 272
                     + (uint32_t)((lane >> 3) & 1) * 16;      // Kh (272 B rows)
    uint32_t pa_lane = (uint32_t)(lane & 15) * 144
                     + (uint32_t)(lane >> 4) * 16;            // Ps16 A-style
    uint32_t vb_lane = ((uint32_t)((lane & 7) + ((lane >> 4) & 1) * 8)) * 144
                     + (uint32_t)((lane >> 3) & 1) * 16;      // VtS B-style

    // Stage Q tile (already roped+scaled fp16): 64 rows x 16 uint4
    for (int t = tid; t < FBR * 16; t += 128) {
        int row = t >> 4, c = t & 15;
        *(uint4*)&Qh[row * QKSTR + c * 4] =
            *(const uint4*)&Q16[(size_t)(r0 + row) * DIM + h * HD + c * 8];
    }
    __syncthreads();

    // Cache Q a-fragments (8 k16-steps), loop-invariant
    uint32_t qa[8][4];
    {
        int mrow = (16 * w + g) * QKSTR;
        #pragma unroll
        for (int ks = 0; ks < 8; ks++) {
            int k0 = ks * 8;
            qa[ks][0] = Qh[mrow + k0 + tg];
            qa[ks][1] = Qh[mrow + 8 * QKSTR + k0 + tg];
            qa[ks][2] = Qh[mrow + k0 + tg + 4];
            qa[ks][3] = Qh[mrow + 8 * QKSTR + k0 + tg + 4];
        }
    }
    __syncthreads();   // Qh dead; Ps16 may overlay

    float m0 = -1e30f, m1 = -1e30f, l0 = 0.f, l1 = 0.f;
    float o[16][4];
    #pragma unroll
    for (int nt = 0; nt < 16; nt++)
        #pragma unroll
        for (int i = 0; i < 4; i++) o[nt][i] = 0.f;

    int qrow_g = r0 + 16 * w + g;
    int diag = blockIdx.x;

    for (int kt = 0; kt <= diag; kt++) {
        int c0 = kt * FBR;
        __syncthreads();   // prev PV done with VtS
        // Load K tile (fp16): 64 rows x 16 uint4
        for (int t = tid; t < FBR * 16; t += 128) {
            int row = t >> 4, c = t & 15;
            *(uint4*)&Kh[row * QKSTR + c * 4] =
                *(const uint4*)&K16[(size_t)(c0 + row) * KVDIM + kvh * HD + c * 8];
        }
        __syncthreads();

        // ---- S = Q @ K^T (fp16, 8 k16-steps, ldmatrix K-frags) ----
        float sacc[8][4];
        #pragma unroll
        for (int nt = 0; nt < 8; nt++)
            #pragma unroll
            for (int i = 0; i < 4; i++) sacc[nt][i] = 0.f;

        #pragma unroll
        for (int ks = 0; ks < 8; ks++) {
            #pragma unroll
            for (int p = 0; p < 4; p++) {
                uint32_t b0, b1, b2, b3;
                ldsm_x4(b0, b1, b2, b3,
                        Kh_sh + (16 * p) * 272 + ks * 32 + kb_lane);
                uint32_t bb0[2] = { b0, b1 };
                uint32_t bb1[2] = { b2, b3 };
                mma_f16(sacc[2 * p], qa[ks], bb0);
                mma_f16(sacc[2 * p + 1], qa[ks], bb1);
            }
        }

        if (kt == diag) {
            #pragma unroll
            for (int nt = 0; nt < 8; nt++) {
                int col = c0 + 8 * nt + 2 * tg;
                if (col > qrow_g)          sacc[nt][0] = -1e30f;
                if (col + 1 > qrow_g)      sacc[nt][1] = -1e30f;
                if (col > qrow_g + 8)      sacc[nt][2] = -1e30f;
                if (col + 1 > qrow_g + 8)  sacc[nt][3] = -1e30f;
            }
        }

        // ---- online softmax ----
        float mx0 = -1e30f, mx1 = -1e30f;
        #pragma unroll
        for (int nt = 0; nt < 8; nt++) {
            mx0 = fmaxf(mx0, fmaxf(sacc[nt][0], sacc[nt][1]));
            mx1 = fmaxf(mx1, fmaxf(sacc[nt][2], sacc[nt][3]));
        }
        #pragma unroll
        for (int off = 2; off >= 1; off >>= 1) {
            mx0 = fmaxf(mx0, __shfl_xor_sync(0xffffffffu, mx0, off));
            mx1 = fmaxf(mx1, __shfl_xor_sync(0xffffffffu, mx1, off));
        }
        float mn0 = fmaxf(m0, mx0), mn1 = fmaxf(m1, mx1);
        float cor0 = __expf(m0 - mn0), cor1 = __expf(m1 - mn1);
        float ps0 = 0.f, ps1 = 0.f;
        #pragma unroll
        for (int nt = 0; nt < 8; nt++) {
            sacc[nt][0] = __expf(sacc[nt][0] - mn0);
            sacc[nt][1] = __expf(sacc[nt][1] - mn0);
            sacc[nt][2] = __expf(sacc[nt][2] - mn1);
            sacc[nt][3] = __expf(sacc[nt][3] - mn1);
            ps0 += sacc[nt][0] + sacc[nt][1];
            ps1 += sacc[nt][2] + sacc[nt][3];
        }
        #pragma unroll
        for (int off = 2; off >= 1; off >>= 1) {
            ps0 += __shfl_xor_sync(0xffffffffu, ps0, off);
            ps1 += __shfl_xor_sync(0xffffffffu, ps1, off);
        }
        l0 = l0 * cor0 + ps0;  m0 = mn0;
        l1 = l1 * cor1 + ps1;  m1 = mn1;
        #pragma unroll
        for (int nt = 0; nt < 16; nt++) {
            o[nt][0] *= cor0; o[nt][1] *= cor0;
            o[nt][2] *= cor1; o[nt][3] *= cor1;
        }
        // P -> smem as fp16 (own warp's rows only)
        #pragma unroll
        for (int nt = 0; nt < 8; nt++) {
            __half2 p0 = __floats2half2_rn(sacc[nt][0], sacc[nt][1]);
            __half2 p1 = __floats2half2_rn(sacc[nt][2], sacc[nt][3]);
            Ps16[(16 * w + g) * P16STR + nt * 4 + tg] = *(uint32_t*)&p0;
            Ps16[(16 * w + g + 8) * P16STR + nt * 4 + tg] = *(uint32_t*)&p1;
        }

        __syncthreads();   // all warps done reading Kh; load V^T over it
        for (int t = tid; t < 128 * 8; t += 128) {
            int r = t >> 3, c = t & 7;
            *(uint4*)&VtS[r * VSTR + c * 4] =
                *(const uint4*)&Vt[(size_t)(kvh * HD + r) * SEQ + c0 + c * 8];
        }
        __syncthreads();

        // ---- O += P @ V (fp16, 4 k16-steps, ldmatrix P/V frags) ----
        #pragma unroll
        for (int ks = 0; ks < 4; ks++) {
            uint32_t a[4];
            ldsm_x4(a[0], a[1], a[2], a[3],
                    Ps_sh + (16 * w) * 144 + ks * 32 + pa_lane);
            #pragma unroll
            for (int p = 0; p < 8; p++) {
                uint32_t b0, b1, b2, b3;
                ldsm_x4(b0, b1, b2, b3,
                        VtS_sh + (16 * p) * 144 + ks * 32 + vb_lane);
                uint32_t bb0[2] = { b0, b1 };
                uint32_t bb1[2] = { b2, b3 };
                mma_f16(o[2 * p], a, bb0);
                mma_f16(o[2 * p + 1], a, bb1);
            }
        }
    }

    // Finalize; store as fp16 (feeds final fp16 GEMM)
    float i0 = 1.f / l0, i1 = 1.f / l1;
    #pragma unroll
    for (int nt = 0; nt < 16; nt++) {
        int col = h * HD + 8 * nt + 2 * tg;
        __half2 h0 = __floats2half2_rn(o[nt][0] * i0, o[nt][1] * i0);
        __half2 h1 = __floats2half2_rn(o[nt][2] * i1, o[nt][3] * i1);
        *(uint32_t*)&O[(size_t)qrow_g * DIM + col] = *(uint32_t*)&h0;
        *(uint32_t*)&O[(size_t)(qrow_g + 8) * DIM + col] = *(uint32_t*)&h1;
    }
}

// ---------------------------------------------------------------------------
// Launch
// ---------------------------------------------------------------------------
extern "C" void kernel_launch(void* const* d_in, const int* in_sizes, int n_in,
                              void* d_out, int out_size)
{
    const float* x  = (const float*)d_in[0];
    const float* wq = (const float*)d_in[1];
    const float* wk = (const float*)d_in[2];
    const float* wv = (const float*)d_in[3];
    const float* wo = (const float*)d_in[4];
    const float* fc = (const float*)d_in[5];
    const float* fs = (const float*)d_in[6];

    float *Qp, *Kp, *Vp;
    __half *Q16, *K16, *VT, *A16, *X16, *WqT, *WkT, *WvT, *WoT;
    cudaGetSymbolAddress((void**)&Qp, g_Q);
    cudaGetSymbolAddress((void**)&Kp, g_K);
    cudaGetSymbolAddress((void**)&Vp, g_V);
    cudaGetSymbolAddress((void**)&Q16, g_Q16);
    cudaGetSymbolAddress((void**)&K16, g_K16);
    cudaGetSymbolAddress((void**)&VT, g_vT);
    cudaGetSymbolAddress((void**)&A16, g_attn16);
    cudaGetSymbolAddress((void**)&X16, g_x16);
    cudaGetSymbolAddress((void**)&WqT, g_wqT);
    cudaGetSymbolAddress((void**)&WkT, g_wkT);
    cudaGetSymbolAddress((void**)&WvT, g_wvT);
    cudaGetSymbolAddress((void**)&WoT, g_woT);

    // Pre-passes
    convert_half_kernel<<<SEQ * DIM / 4 / 256, 256>>>(x, X16, SEQ * DIM);
    dim3 tb(32, 8);
    transpose_half_kernel<<<dim3(DIM / 32, DIM / 32), tb>>>(wq, WqT, DIM, DIM);
    transpose_half_kernel<<<dim3(KVDIM / 32, DIM / 32), tb>>>(wk, WkT, DIM, KVDIM);
    transpose_half_kernel<<<dim3(KVDIM / 32, DIM / 32), tb>>>(wv, WvT, DIM, KVDIM);
    transpose_half_kernel<<<dim3(DIM / 32, DIM / 32), tb>>>(wo, WoT, DIM, DIM);

    int gsm = 4 * TILE_WORDS * (int)sizeof(uint32_t);
    cudaFuncSetAttribute(gemm_f16_kernel,
                         cudaFuncAttributeMaxDynamicSharedMemorySize, gsm);

    // Projections (fp16 tensor cores)
    gemm_f16_kernel<<<dim3(DIM / GBN, SEQ / GBM), 128, gsm>>>(
        X16, WqT, Qp, SEQ, DIM, DIM);
    gemm_f16_kernel<<<dim3(KVDIM / GBN, SEQ / GBM), 128, gsm>>>(
        X16, WkT, Kp, SEQ, KVDIM, DIM);
    gemm_f16_kernel<<<dim3(KVDIM / GBN, SEQ / GBM), 128, gsm>>>(
        X16, WvT, Vp, SEQ, KVDIM, DIM);

    // RoPE -> fp16 (Q pre-scaled by 1/sqrt(HD)); V -> fp16 transposed
    const float qscale = 0.08838834764831845f;
    int totQ = SEQ * NH * 64, totK = SEQ * NKV * 64;
    rope_half_kernel<<<(totQ + 255) / 256, 256>>>(Qp, Q16, fc, fs, NH, DIM,
                                                  qscale, totQ);
    rope_half_kernel<<<(totK + 255) / 256, 256>>>(Kp, K16, fc, fs, NKV, KVDIM,
                                                  1.0f, totK);
    transpose_half_kernel<<<dim3(KVDIM / 32, SEQ / 32), tb>>>(Vp, VT, SEQ, KVDIM);

    // Flash attention (all-fp16 operands) -> fp16 attn
    int fsm = FLASH_SMEM_W * (int)sizeof(uint32_t);
    cudaFuncSetAttribute(flash_kernel,
                         cudaFuncAttributeMaxDynamicSharedMemorySize, fsm);
    flash_kernel<<<dim3(SEQ / FBR, NH), 128, fsm>>>(Q16, K16, VT, A16);

    // Output projection (fp16) -> d_out (fp32)
    gemm_f16_kernel<<<dim3(DIM / GBN, SEQ / GBM), 128, gsm>>>(
        A16, WoT, (float*)d_out, SEQ, DIM, DIM);
}

// round 12
// speedup vs baseline: 7.1182x; 1.0281x over previous
#include <cuda_runtime.h>
#include <cuda_fp16.h>
#include <math.h>
#include <stdint.h>

#define SEQ 2048
#define DIM 4096
#define NH 32
#define NKV 8
#define HD 128
#define KVDIM 1024

// Scratch (allocation-free rule: device globals)
__device__ __half g_Q16[SEQ * DIM];        // roped+scaled Q, fp16
__device__ __half g_K16[SEQ * KVDIM];      // roped K, fp16
__device__ __half g_V16[SEQ * KVDIM];      // V, fp16
__device__ __half g_vT[KVDIM * SEQ];       // V^T fp16 [KVDIM][SEQ]
__device__ __half g_attn16[SEQ * DIM];     // flash output, fp16
__device__ __half g_x16[SEQ * DIM];        // x, fp16
__device__ __half g_wqT[DIM * DIM];        // Wq^T [N][K] fp16
__device__ __half g_wkvT[2 * KVDIM * DIM]; // [Wk^T ; Wv^T] fp16 [2048][4096]
__device__ __half g_woT[DIM * DIM];

// ---------------------------------------------------------------------------
// Helpers
// ---------------------------------------------------------------------------
__device__ __forceinline__ void mma_f16(float c[4], const uint32_t a[4],
                                        const uint32_t b[2]) {
    asm volatile(
        "mma.sync.aligned.m16n8k16.row.col.f32.f16.f16.f32 "
        "{%0,%1,%2,%3}, {%4,%5,%6,%7}, {%8,%9}, {%0,%1,%2,%3};"
        : "+f"(c[0]), "+f"(c[1]), "+f"(c[2]), "+f"(c[3])
        : "r"(a[0]), "r"(a[1]), "r"(a[2]), "r"(a[3]), "r"(b[0]), "r"(b[1]));
}

__device__ __forceinline__ void ldsm_x4(uint32_t& r0, uint32_t& r1,
                                        uint32_t& r2, uint32_t& r3,
                                        uint32_t addr) {
    asm volatile(
        "ldmatrix.sync.aligned.m8n8.x4.shared.b16 {%0,%1,%2,%3}, [%4];"
        : "=r"(r0), "=r"(r1), "=r"(r2), "=r"(r3) : "r"(addr));
}

__device__ __forceinline__ void cpa16(uint32_t smem_addr, const void* gptr) {
    asm volatile("cp.async.cg.shared.global [%0], [%1], 16;"
                 :: "r"(smem_addr), "l"(gptr));
}
__device__ __forceinline__ void cpa_commit() {
    asm volatile("cp.async.commit_group;");
}
template <int N>
__device__ __forceinline__ void cpa_wait() {
    asm volatile("cp.async.wait_group %0;" :: "n"(N));
}

// ---------------------------------------------------------------------------
// Pre-passes
// ---------------------------------------------------------------------------
__global__ void convert_half_kernel(const float* __restrict__ in,
                                    __half* __restrict__ out, int n)
{
    int i = (blockIdx.x * blockDim.x + threadIdx.x) * 4;
    if (i >= n) return;
    float4 v = *(const float4*)&in[i];
    __half2 h0 = __floats2half2_rn(v.x, v.y);
    __half2 h1 = __floats2half2_rn(v.z, v.w);
    *(uint2*)&out[i] = make_uint2(*(uint32_t*)&h0, *(uint32_t*)&h1);
}

// in [R][C] fp32 -> out [C][R] fp16
__global__ void transpose_half_kernel(const float* __restrict__ in,
                                      __half* __restrict__ out, int R, int C)
{
    __shared__ float tile[32][33];
    int c0 = blockIdx.x * 32, r0 = blockIdx.y * 32;
    int tx = threadIdx.x, ty = threadIdx.y;
    #pragma unroll
    for (int j = 0; j < 32; j += 8)
        tile[ty + j][tx] = in[(size_t)(r0 + ty + j) * C + c0 + tx];
    __syncthreads();
    #pragma unroll
    for (int j = 0; j < 32; j += 8)
        out[(size_t)(c0 + ty + j) * R + r0 + tx] = __float2half(tile[tx][ty + j]);
}

// in [R][C] fp16 -> out [C][R] fp16
__global__ void transpose_h2h_kernel(const __half* __restrict__ in,
                                     __half* __restrict__ out, int R, int C)
{
    __shared__ __half tile[32][34];
    int c0 = blockIdx.x * 32, r0 = blockIdx.y * 32;
    int tx = threadIdx.x, ty = threadIdx.y;
    #pragma unroll
    for (int j = 0; j < 32; j += 8)
        tile[ty + j][tx] = in[(size_t)(r0 + ty + j) * C + c0 + tx];
    __syncthreads();
    #pragma unroll
    for (int j = 0; j < 32; j += 8)
        out[(size_t)(c0 + ty + j) * R + r0 + tx] = tile[tx][ty + j];
}

// ---------------------------------------------------------------------------
// FP16 GEMM with fused epilogues.
// MODE 0: C32 = A @ BT^T (fp32 out)                       [O projection]
// MODE 1: O16a = rope(A @ BT^T) * mul, fp16, ld=DIM       [Q projection]
// MODE 2: N=2048 fused K|V: n<1024 -> O16a = rope(.), ld=KVDIM (K)
//                           n>=1024 -> O16b = fp16(.), ld=KVDIM (V)
// CTA 128x128, K-chunk 64, 4 warps, warp tile 64x64, cp.async 2-stage,
// ldmatrix fragment loads.
// ---------------------------------------------------------------------------
#define GBM 128
#define GBN 128
#define GKC 64
#define HSTR 36                 // u32 words per row (144 B)
#define TILE_WORDS (128 * HSTR)

template <int MODE>
__global__ __launch_bounds__(128, 2) void gemm_epi_kernel(
    const __half* __restrict__ A, const __half* __restrict__ BT,
    float* __restrict__ C32, __half* __restrict__ O16a,
    __half* __restrict__ O16b,
    const float* __restrict__ cs, const float* __restrict__ sn,
    int M, int N, int K, float mul)
{
    extern __shared__ uint32_t smg[];
    uint32_t sbase = (uint32_t)__cvta_generic_to_shared(smg);

    int tid = threadIdx.x;
    int wid = tid >> 5, lane = tid & 31;
    int g = lane >> 2, tg = lane & 3;
    int warp_m = (wid >> 1) * 64;
    int warp_n = (wid & 1) * 64;
    int m0 = blockIdx.y * GBM, n0 = blockIdx.x * GBN;

    uint32_t a_lane = (uint32_t)(lane & 15) * 144 + (uint32_t)(lane >> 4) * 16;
    uint32_t b_lane = ((uint32_t)((lane & 7) + ((lane >> 4) & 1) * 8)) * 144
                    + (uint32_t)((lane >> 3) & 1) * 16;

    float acc[4][8][4];
    #pragma unroll
    for (int mt = 0; mt < 4; mt++)
        #pragma unroll
        for (int nt = 0; nt < 8; nt++)
            #pragma unroll
            for (int i = 0; i < 4; i++) acc[mt][nt][i] = 0.f;

    int niter = K / GKC;

    #define ISSUE_COPY(IT, STG)                                               \
    do {                                                                      \
        uint32_t aOff = sbase + (uint32_t)(STG) * (2 * TILE_WORDS) * 4;       \
        uint32_t bOff = aOff + TILE_WORDS * 4;                                \
        const __half* Ab = A + (size_t)m0 * K + (IT) * GKC;                   \
        const __half* Bb = BT + (size_t)n0 * K + (IT) * GKC;                  \
        _Pragma("unroll")                                                     \
        for (int i = 0; i < 8; i++) {                                         \
            int c = tid + i * 128;                                            \
            int r = c >> 3, cc = c & 7;                                       \
            cpa16(aOff + r * 144 + cc * 16, Ab + (size_t)r * K + cc * 8);     \
        }                                                                     \
        _Pragma("unroll")                                                     \
        for (int i = 0; i < 8; i++) {                                         \
            int c = tid + i * 128;                                            \
            int r = c >> 3, cc = c & 7;                                       \
            cpa16(bOff + r * 144 + cc * 16, Bb + (size_t)r * K + cc * 8);     \
        }                                                                     \
        cpa_commit();                                                         \
    } while (0)

    ISSUE_COPY(0, 0);

    for (int it = 0; it < niter; it++) {
        int cur = it & 1;
        if (it + 1 < niter) {
            ISSUE_COPY(it + 1, (it + 1) & 1);
            cpa_wait<1>();
        } else {
            cpa_wait<0>();
        }
        __syncthreads();

        uint32_t As_sh = sbase + (uint32_t)cur * (2 * TILE_WORDS) * 4;
        uint32_t Bs_sh = As_sh + TILE_WORDS * 4;

        #pragma unroll
        for (int ks = 0; ks < 4; ks++) {
            uint32_t aR[4][4];
            #pragma unroll
            for (int mt = 0; mt < 4; mt++)
                ldsm_x4(aR[mt][0], aR[mt][1], aR[mt][2], aR[mt][3],
                        As_sh + (warp_m + mt * 16) * 144 + ks * 32 + a_lane);
            uint32_t bR[8][2];
            #pragma unroll
            for (int p = 0; p < 4; p++)
                ldsm_x4(bR[2 * p][0], bR[2 * p][1],
                        bR[2 * p + 1][0], bR[2 * p + 1][1],
                        Bs_sh + (warp_n + 16 * p) * 144 + ks * 32 + b_lane);
            #pragma unroll
            for (int mt = 0; mt < 4; mt++)
                #pragma unroll
                for (int nt = 0; nt < 8; nt++)
                    mma_f16(acc[mt][nt], aR[mt], bR[nt]);
        }
        __syncthreads();
    }

    if (MODE == 0) {
        #pragma unroll
        for (int mt = 0; mt < 4; mt++) {
            int m = m0 + warp_m + mt * 16 + g;
            #pragma unroll
            for (int nt = 0; nt < 8; nt++) {
                int n = n0 + warp_n + nt * 8 + 2 * tg;
                *(float2*)&C32[(size_t)m * N + n] =
                    make_float2(acc[mt][nt][0], acc[mt][nt][1]);
                *(float2*)&C32[(size_t)(m + 8) * N + n] =
                    make_float2(acc[mt][nt][2], acc[mt][nt][3]);
            }
        }
    } else {
        bool vhalf = (MODE == 2) && (n0 >= KVDIM);   // CTA-uniform
        const int ld = (MODE == 1) ? DIM : KVDIM;
        #pragma unroll
        for (int mt = 0; mt < 4; mt++) {
            int m = m0 + warp_m + mt * 16 + g;
            #pragma unroll
            for (int nt = 0; nt < 8; nt++) {
                int n = n0 + warp_n + nt * 8 + 2 * tg;
                if (vhalf) {
                    __half2 h0 = __floats2half2_rn(acc[mt][nt][0], acc[mt][nt][1]);
                    __half2 h1 = __floats2half2_rn(acc[mt][nt][2], acc[mt][nt][3]);
                    *(uint32_t*)&O16b[(size_t)m * KVDIM + n - KVDIM] =
                        *(uint32_t*)&h0;
                    *(uint32_t*)&O16b[(size_t)(m + 8) * KVDIM + n - KVDIM] =
                        *(uint32_t*)&h1;
                } else {
                    int i = (n & 127) >> 1;
                    float c0v = cs[m * 64 + i],       s0v = sn[m * 64 + i];
                    float c1v = cs[(m + 8) * 64 + i], s1v = sn[(m + 8) * 64 + i];
                    float re0 = acc[mt][nt][0] * c0v - acc[mt][nt][1] * s0v;
                    float im0 = acc[mt][nt][0] * s0v + acc[mt][nt][1] * c0v;
                    float re1 = acc[mt][nt][2] * c1v - acc[mt][nt][3] * s1v;
                    float im1 = acc[mt][nt][2] * s1v + acc[mt][nt][3] * c1v;
                    __half2 h0 = __floats2half2_rn(re0 * mul, im0 * mul);
                    __half2 h1 = __floats2half2_rn(re1 * mul, im1 * mul);
                    *(uint32_t*)&O16a[(size_t)m * ld + n] = *(uint32_t*)&h0;
                    *(uint32_t*)&O16a[(size_t)(m + 8) * ld + n] = *(uint32_t*)&h1;
                }
            }
        }
    }
}

// ---------------------------------------------------------------------------
// Flash attention, all-fp16 operands, ldmatrix fragment loads (round 11).
// ---------------------------------------------------------------------------
#define FBR 64
#define QKSTR 68     // Q/K row: 64 words + 4 pad (272 B)
#define P16STR 36    // P row: 32 words + 4 pad (144 B)
#define VSTR 36      // Vt row (144 B)
#define REGION0_W (64 * QKSTR)                  // 4352
#define REGION1_W (128 * VSTR)                  // 4608
#define FLASH_SMEM_W (REGION0_W + REGION1_W)    // 8960 words = 35840 B

__global__ __launch_bounds__(128, 2) void flash_kernel(
    const __half* __restrict__ Q16, const __half* __restrict__ K16,
    const __half* __restrict__ Vt, __half* __restrict__ O)
{
    extern __shared__ uint32_t smu[];
    uint32_t* Qh   = smu;
    uint32_t* Ps16 = smu;
    uint32_t* Kh   = smu + REGION0_W;
    uint32_t* VtS  = smu + REGION0_W;
    uint32_t sm_sh  = (uint32_t)__cvta_generic_to_shared(smu);
    uint32_t Ps_sh  = sm_sh;
    uint32_t Kh_sh  = sm_sh + REGION0_W * 4;
    uint32_t VtS_sh = sm_sh + REGION0_W * 4;

    int tid = threadIdx.x;
    int w = tid >> 5, lane = tid & 31;
    int g = lane >> 2, tg = lane & 3;
    int r0 = blockIdx.x * FBR;
    int h = blockIdx.y, kvh = h >> 2;

    uint32_t kb_lane = ((uint32_t)((lane & 7) + ((lane >> 4) & 1) * 8)) * 272
                     + (uint32_t)((lane >> 3) & 1) * 16;
    uint32_t pa_lane = (uint32_t)(lane & 15) * 144
                     + (uint32_t)(lane >> 4) * 16;
    uint32_t vb_lane = ((uint32_t)((lane & 7) + ((lane >> 4) & 1) * 8)) * 144
                     + (uint32_t)((lane >> 3) & 1) * 16;

    for (int t = tid; t < FBR * 16; t += 128) {
        int row = t >> 4, c = t & 15;
        *(uint4*)&Qh[row * QKSTR + c * 4] =
            *(const uint4*)&Q16[(size_t)(r0 + row) * DIM + h * HD + c * 8];
    }
    __syncthreads();

    uint32_t qa[8][4];
    {
        int mrow = (16 * w + g) * QKSTR;
        #pragma unroll
        for (int ks = 0; ks < 8; ks++) {
            int k0 = ks * 8;
            qa[ks][0] = Qh[mrow + k0 + tg];
            qa[ks][1] = Qh[mrow + 8 * QKSTR + k0 + tg];
            qa[ks][2] = Qh[mrow + k0 + tg + 4];
            qa[ks][3] = Qh[mrow + 8 * QKSTR + k0 + tg + 4];
        }
    }
    __syncthreads();

    float m0 = -1e30f, m1 = -1e30f, l0 = 0.f, l1 = 0.f;
    float o[16][4];
    #pragma unroll
    for (int nt = 0; nt < 16; nt++)
        #pragma unroll
        for (int i = 0; i < 4; i++) o[nt][i] = 0.f;

    int qrow_g = r0 + 16 * w + g;
    int diag = blockIdx.x;

    for (int kt = 0; kt <= diag; kt++) {
        int c0 = kt * FBR;
        __syncthreads();
        for (int t = tid; t < FBR * 16; t += 128) {
            int row = t >> 4, c = t & 15;
            *(uint4*)&Kh[row * QKSTR + c * 4] =
                *(const uint4*)&K16[(size_t)(c0 + row) * KVDIM + kvh * HD + c * 8];
        }
        __syncthreads();

        float sacc[8][4];
        #pragma unroll
        for (int nt = 0; nt < 8; nt++)
            #pragma unroll
            for (int i = 0; i < 4; i++) sacc[nt][i] = 0.f;

        #pragma unroll
        for (int ks = 0; ks < 8; ks++) {
            #pragma unroll
            for (int p = 0; p < 4; p++) {
                uint32_t b0, b1, b2, b3;
                ldsm_x4(b0, b1, b2, b3,
                        Kh_sh + (16 * p) * 272 + ks * 32 + kb_lane);
                uint32_t bb0[2] = { b0, b1 };
                uint32_t bb1[2] = { b2, b3 };
                mma_f16(sacc[2 * p], qa[ks], bb0);
                mma_f16(sacc[2 * p + 1], qa[ks], bb1);
            }
        }

        if (kt == diag) {
            #pragma unroll
            for (int nt = 0; nt < 8; nt++) {
                int col = c0 + 8 * nt + 2 * tg;
                if (col > qrow_g)          sacc[nt][0] = -1e30f;
                if (col + 1 > qrow_g)      sacc[nt][1] = -1e30f;
                if (col > qrow_g + 8)      sacc[nt][2] = -1e30f;
                if (col + 1 > qrow_g + 8)  sacc[nt][3] = -1e30f;
            }
        }

        float mx0 = -1e30f, mx1 = -1e30f;
        #pragma unroll
        for (int nt = 0; nt < 8; nt++) {
            mx0 = fmaxf(mx0, fmaxf(sacc[nt][0], sacc[nt][1]));
            mx1 = fmaxf(mx1, fmaxf(sacc[nt][2], sacc[nt][3]));
        }
        #pragma unroll
        for (int off = 2; off >= 1; off >>= 1) {
            mx0 = fmaxf(mx0, __shfl_xor_sync(0xffffffffu, mx0, off));
            mx1 = fmaxf(mx1, __shfl_xor_sync(0xffffffffu, mx1, off));
        }
        float mn0 = fmaxf(m0, mx0), mn1 = fmaxf(m1, mx1);
        float cor0 = __expf(m0 - mn0), cor1 = __expf(m1 - mn1);
        float ps0 = 0.f, ps1 = 0.f;
        #pragma unroll
        for (int nt = 0; nt < 8; nt++) {
            sacc[nt][0] = __expf(sacc[nt][0] - mn0);
            sacc[nt][1] = __expf(sacc[nt][1] - mn0);
            sacc[nt][2] = __expf(sacc[nt][2] - mn1);
            sacc[nt][3] = __expf(sacc[nt][3] - mn1);
            ps0 += sacc[nt][0] + sacc[nt][1];
            ps1 += sacc[nt][2] + sacc[nt][3];
        }
        #pragma unroll
        for (int off = 2; off >= 1; off >>= 1) {
            ps0 += __shfl_xor_sync(0xffffffffu, ps0, off);
            ps1 += __shfl_xor_sync(0xffffffffu, ps1, off);
        }
        l0 = l0 * cor0 + ps0;  m0 = mn0;
        l1 = l1 * cor1 + ps1;  m1 = mn1;
        #pragma unroll
        for (int nt = 0; nt < 16; nt++) {
            o[nt][0] *= cor0; o[nt][1] *= cor0;
            o[nt][2] *= cor1; o[nt][3] *= cor1;
        }
        #pragma unroll
        for (int nt = 0; nt < 8; nt++) {
            __half2 p0 = __floats2half2_rn(sacc[nt][0], sacc[nt][1]);
            __half2 p1 = __floats2half2_rn(sacc[nt][2], sacc[nt][3]);
            Ps16[(16 * w + g) * P16STR + nt * 4 + tg] = *(uint32_t*)&p0;
            Ps16[(16 * w + g + 8) * P16STR + nt * 4 + tg] = *(uint32_t*)&p1;
        }

        __syncthreads();
        for (int t = tid; t < 128 * 8; t += 128) {
            int r = t >> 3, c = t & 7;
            *(uint4*)&VtS[r * VSTR + c * 4] =
                *(const uint4*)&Vt[(size_t)(kvh * HD + r) * SEQ + c0 + c * 8];
        }
        __syncthreads();

        #pragma unroll
        for (int ks = 0; ks < 4; ks++) {
            uint32_t a[4];
            ldsm_x4(a[0], a[1], a[2], a[3],
                    Ps_sh + (16 * w) * 144 + ks * 32 + pa_lane);
            #pragma unroll
            for (int p = 0; p < 8; p++) {
                uint32_t b0, b1, b2, b3;
                ldsm_x4(b0, b1, b2, b3,
                        VtS_sh + (16 * p) * 144 + ks * 32 + vb_lane);
                uint32_t bb0[2] = { b0, b1 };
                uint32_t bb1[2] = { b2, b3 };
                mma_f16(o[2 * p], a, bb0);
                mma_f16(o[2 * p + 1], a, bb1);
            }
        }
    }

    float i0 = 1.f / l0, i1 = 1.f / l1;
    #pragma unroll
    for (int nt = 0; nt < 16; nt++) {
        int col = h * HD + 8 * nt + 2 * tg;
        __half2 h0 = __floats2half2_rn(o[nt][0] * i0, o[nt][1] * i0);
        __half2 h1 = __floats2half2_rn(o[nt][2] * i1, o[nt][3] * i1);
        *(uint32_t*)&O[(size_t)qrow_g * DIM + col] = *(uint32_t*)&h0;
        *(uint32_t*)&O[(size_t)(qrow_g + 8) * DIM + col] = *(uint32_t*)&h1;
    }
}

// ---------------------------------------------------------------------------
// Launch
// ---------------------------------------------------------------------------
extern "C" void kernel_launch(void* const* d_in, const int* in_sizes, int n_in,
                              void* d_out, int out_size)
{
    const float* x  = (const float*)d_in[0];
    const float* wq = (const float*)d_in[1];
    const float* wk = (const float*)d_in[2];
    const float* wv = (const float*)d_in[3];
    const float* wo = (const float*)d_in[4];
    const float* fc = (const float*)d_in[5];
    const float* fs = (const float*)d_in[6];

    __half *Q16, *K16, *V16, *VT, *A16, *X16, *WqT, *WkvT, *WoT;
    cudaGetSymbolAddress((void**)&Q16, g_Q16);
    cudaGetSymbolAddress((void**)&K16, g_K16);
    cudaGetSymbolAddress((void**)&V16, g_V16);
    cudaGetSymbolAddress((void**)&VT, g_vT);
    cudaGetSymbolAddress((void**)&A16, g_attn16);
    cudaGetSymbolAddress((void**)&X16, g_x16);
    cudaGetSymbolAddress((void**)&WqT, g_wqT);
    cudaGetSymbolAddress((void**)&WkvT, g_wkvT);
    cudaGetSymbolAddress((void**)&WoT, g_woT);

    // Pre-passes
    convert_half_kernel<<<SEQ * DIM / 4 / 256, 256>>>(x, X16, SEQ * DIM);
    dim3 tb(32, 8);
    transpose_half_kernel<<<dim3(DIM / 32, DIM / 32), tb>>>(wq, WqT, DIM, DIM);
    transpose_half_kernel<<<dim3(KVDIM / 32, DIM / 32), tb>>>(wk, WkvT, DIM, KVDIM);
    transpose_half_kernel<<<dim3(KVDIM / 32, DIM / 32), tb>>>(
        wv, WkvT + (size_t)KVDIM * DIM, DIM, KVDIM);
    transpose_half_kernel<<<dim3(DIM / 32, DIM / 32), tb>>>(wo, WoT, DIM, DIM);

    int gsm = 4 * TILE_WORDS * (int)sizeof(uint32_t);
    cudaFuncSetAttribute(gemm_epi_kernel<0>,
                         cudaFuncAttributeMaxDynamicSharedMemorySize, gsm);
    cudaFuncSetAttribute(gemm_epi_kernel<1>,
                         cudaFuncAttributeMaxDynamicSharedMemorySize, gsm);
    cudaFuncSetAttribute(gemm_epi_kernel<2>,
                         cudaFuncAttributeMaxDynamicSharedMemorySize, gsm);

    const float qscale = 0.08838834764831845f;   // 1/sqrt(128)

    // Q projection + rope + scale -> fp16
    gemm_epi_kernel<1><<<dim3(DIM / GBN, SEQ / GBM), 128, gsm>>>(
        X16, WqT, nullptr, Q16, nullptr, fc, fs, SEQ, DIM, DIM, qscale);
    // Fused K|V projection; K roped -> K16, V -> V16
    gemm_epi_kernel<2><<<dim3(2 * KVDIM / GBN, SEQ / GBM), 128, gsm>>>(
        X16, WkvT, nullptr, K16, V16, fc, fs, SEQ, 2 * KVDIM, DIM, 1.0f);

    // V -> V^T (fp16)
    transpose_h2h_kernel<<<dim3(KVDIM / 32, SEQ / 32), tb>>>(V16, VT, SEQ, KVDIM);

    // Flash attention (all-fp16 operands) -> fp16 attn
    int fsm = FLASH_SMEM_W * (int)sizeof(uint32_t);
    cudaFuncSetAttribute(flash_kernel,
                         cudaFuncAttributeMaxDynamicSharedMemorySize, fsm);
    flash_kernel<<<dim3(SEQ / FBR, NH), 128, fsm>>>(Q16, K16, VT, A16);

    // Output projection -> d_out (fp32)
    gemm_epi_kernel<0><<<dim3(DIM / GBN, SEQ / GBM), 128, gsm>>>(
        A16, WoT, (float*)d_out, nullptr, nullptr, nullptr, nullptr,
        SEQ, DIM, DIM, 1.0f);
}

// round 13
// speedup vs baseline: 7.5654x; 1.0628x over previous
#include <cuda_runtime.h>
#include <cuda_fp16.h>
#include <math.h>
#include <stdint.h>

#define SEQ 2048
#define DIM 4096
#define NH 32
#define NKV 8
#define HD 128
#define KVDIM 1024
#define NQKV (DIM + 2 * KVDIM)    // 6144 fused projection width

// Scratch (allocation-free rule: device globals)
__device__ __half g_Q16[SEQ * DIM];         // roped+scaled Q, fp16
__device__ __half g_K16[SEQ * KVDIM];       // roped K, fp16
__device__ __half g_V16[SEQ * KVDIM];       // V, fp16
__device__ __half g_vT[KVDIM * SEQ];        // V^T fp16 [KVDIM][SEQ]
__device__ __half g_attn16[SEQ * DIM];      // flash output, fp16
__device__ __half g_x16[SEQ * DIM];         // x, fp16
__device__ __half g_wqkvT[NQKV * DIM];      // [Wq^T; Wk^T; Wv^T] fp16 [6144][4096]
__device__ __half g_woT[DIM * DIM];

// ---------------------------------------------------------------------------
// Helpers
// ---------------------------------------------------------------------------
__device__ __forceinline__ void mma_f16(float c[4], const uint32_t a[4],
                                        const uint32_t b[2]) {
    asm volatile(
        "mma.sync.aligned.m16n8k16.row.col.f32.f16.f16.f32 "
        "{%0,%1,%2,%3}, {%4,%5,%6,%7}, {%8,%9}, {%0,%1,%2,%3};"
        : "+f"(c[0]), "+f"(c[1]), "+f"(c[2]), "+f"(c[3])
        : "r"(a[0]), "r"(a[1]), "r"(a[2]), "r"(a[3]), "r"(b[0]), "r"(b[1]));
}

__device__ __forceinline__ void ldsm_x4(uint32_t& r0, uint32_t& r1,
                                        uint32_t& r2, uint32_t& r3,
                                        uint32_t addr) {
    asm volatile(
        "ldmatrix.sync.aligned.m8n8.x4.shared.b16 {%0,%1,%2,%3}, [%4];"
        : "=r"(r0), "=r"(r1), "=r"(r2), "=r"(r3) : "r"(addr));
}

__device__ __forceinline__ void cpa16(uint32_t smem_addr, const void* gptr) {
    asm volatile("cp.async.cg.shared.global [%0], [%1], 16;"
                 :: "r"(smem_addr), "l"(gptr));
}
__device__ __forceinline__ void cpa_commit() {
    asm volatile("cp.async.commit_group;");
}
template <int N>
__device__ __forceinline__ void cpa_wait() {
    asm volatile("cp.async.wait_group %0;" :: "n"(N));
}

// ---------------------------------------------------------------------------
// Pre-passes
// ---------------------------------------------------------------------------
__global__ void convert_half_kernel(const float* __restrict__ in,
                                    __half* __restrict__ out, int n)
{
    int i = (blockIdx.x * blockDim.x + threadIdx.x) * 4;
    if (i >= n) return;
    float4 v = *(const float4*)&in[i];
    __half2 h0 = __floats2half2_rn(v.x, v.y);
    __half2 h1 = __floats2half2_rn(v.z, v.w);
    *(uint2*)&out[i] = make_uint2(*(uint32_t*)&h0, *(uint32_t*)&h1);
}

// in [R][C] fp32 -> out [C][R] fp16
__global__ void transpose_half_kernel(const float* __restrict__ in,
                                      __half* __restrict__ out, int R, int C)
{
    __shared__ float tile[32][33];
    int c0 = blockIdx.x * 32, r0 = blockIdx.y * 32;
    int tx = threadIdx.x, ty = threadIdx.y;
    #pragma unroll
    for (int j = 0; j < 32; j += 8)
        tile[ty + j][tx] = in[(size_t)(r0 + ty + j) * C + c0 + tx];
    __syncthreads();
    #pragma unroll
    for (int j = 0; j < 32; j += 8)
        out[(size_t)(c0 + ty + j) * R + r0 + tx] = __float2half(tile[tx][ty + j]);
}

// in [R][C] fp16 -> out [C][R] fp16
__global__ void transpose_h2h_kernel(const __half* __restrict__ in,
                                     __half* __restrict__ out, int R, int C)
{
    __shared__ __half tile[32][34];
    int c0 = blockIdx.x * 32, r0 = blockIdx.y * 32;
    int tx = threadIdx.x, ty = threadIdx.y;
    #pragma unroll
    for (int j = 0; j < 32; j += 8)
        tile[ty + j][tx] = in[(size_t)(r0 + ty + j) * C + c0 + tx];
    __syncthreads();
    #pragma unroll
    for (int j = 0; j < 32; j += 8)
        out[(size_t)(c0 + ty + j) * R + r0 + tx] = tile[tx][ty + j];
}

// ---------------------------------------------------------------------------
// FP16 GEMM with fused epilogues.
// MODE 0: C32 = A @ BT^T (fp32 out)                         [O projection]
// MODE 3: merged QKV, N=6144:
//   n0 <  4096            -> Q16 = rope(.) * mul, ld=DIM
//   4096 <= n0 < 5120     -> K16 = rope(.),       ld=KVDIM
//   n0 >= 5120            -> V16 = fp16(.),       ld=KVDIM
// CTA 128x128, K-chunk 64, 4 warps, warp tile 64x64, cp.async 2-stage,
// ldmatrix fragment loads.
// ---------------------------------------------------------------------------
#define GBM 128
#define GBN 128
#define GKC 64
#define HSTR 36                 // u32 words per row (144 B)
#define TILE_WORDS (128 * HSTR)

template <int MODE>
__global__ __launch_bounds__(128, 2) void gemm_epi_kernel(
    const __half* __restrict__ A, const __half* __restrict__ BT,
    float* __restrict__ C32, __half* __restrict__ Qo,
    __half* __restrict__ Ko, __half* __restrict__ Vo,
    const float* __restrict__ cs, const float* __restrict__ sn,
    int M, int N, int K, float mul)
{
    extern __shared__ uint32_t smg[];
    uint32_t sbase = (uint32_t)__cvta_generic_to_shared(smg);

    int tid = threadIdx.x;
    int wid = tid >> 5, lane = tid & 31;
    int g = lane >> 2, tg = lane & 3;
    int warp_m = (wid >> 1) * 64;
    int warp_n = (wid & 1) * 64;
    int m0 = blockIdx.y * GBM, n0 = blockIdx.x * GBN;

    uint32_t a_lane = (uint32_t)(lane & 15) * 144 + (uint32_t)(lane >> 4) * 16;
    uint32_t b_lane = ((uint32_t)((lane & 7) + ((lane >> 4) & 1) * 8)) * 144
                    + (uint32_t)((lane >> 3) & 1) * 16;

    float acc[4][8][4];
    #pragma unroll
    for (int mt = 0; mt < 4; mt++)
        #pragma unroll
        for (int nt = 0; nt < 8; nt++)
            #pragma unroll
            for (int i = 0; i < 4; i++) acc[mt][nt][i] = 0.f;

    int niter = K / GKC;

    #define ISSUE_COPY(IT, STG)                                               \
    do {                                                                      \
        uint32_t aOff = sbase + (uint32_t)(STG) * (2 * TILE_WORDS) * 4;       \
        uint32_t bOff = aOff + TILE_WORDS * 4;                                \
        const __half* Ab = A + (size_t)m0 * K + (IT) * GKC;                   \
        const __half* Bb = BT + (size_t)n0 * K + (IT) * GKC;                  \
        _Pragma("unroll")                                                     \
        for (int i = 0; i < 8; i++) {                                         \
            int c = tid + i * 128;                                            \
            int r = c >> 3, cc = c & 7;                                       \
            cpa16(aOff + r * 144 + cc * 16, Ab + (size_t)r * K + cc * 8);     \
        }                                                                     \
        _Pragma("unroll")                                                     \
        for (int i = 0; i < 8; i++) {                                         \
            int c = tid + i * 128;                                            \
            int r = c >> 3, cc = c & 7;                                       \
            cpa16(bOff + r * 144 + cc * 16, Bb + (size_t)r * K + cc * 8);     \
        }                                                                     \
        cpa_commit();                                                         \
    } while (0)

    ISSUE_COPY(0, 0);

    for (int it = 0; it < niter; it++) {
        int cur = it & 1;
        if (it + 1 < niter) {
            ISSUE_COPY(it + 1, (it + 1) & 1);
            cpa_wait<1>();
        } else {
            cpa_wait<0>();
        }
        __syncthreads();

        uint32_t As_sh = sbase + (uint32_t)cur * (2 * TILE_WORDS) * 4;
        uint32_t Bs_sh = As_sh + TILE_WORDS * 4;

        #pragma unroll
        for (int ks = 0; ks < 4; ks++) {
            uint32_t aR[4][4];
            #pragma unroll
            for (int mt = 0; mt < 4; mt++)
                ldsm_x4(aR[mt][0], aR[mt][1], aR[mt][2], aR[mt][3],
                        As_sh + (warp_m + mt * 16) * 144 + ks * 32 + a_lane);
            uint32_t bR[8][2];
            #pragma unroll
            for (int p = 0; p < 4; p++)
                ldsm_x4(bR[2 * p][0], bR[2 * p][1],
                        bR[2 * p + 1][0], bR[2 * p + 1][1],
                        Bs_sh + (warp_n + 16 * p) * 144 + ks * 32 + b_lane);
            #pragma unroll
            for (int mt = 0; mt < 4; mt++)
                #pragma unroll
                for (int nt = 0; nt < 8; nt++)
                    mma_f16(acc[mt][nt], aR[mt], bR[nt]);
        }
        __syncthreads();
    }

    if (MODE == 0) {
        #pragma unroll
        for (int mt = 0; mt < 4; mt++) {
            int m = m0 + warp_m + mt * 16 + g;
            #pragma unroll
            for (int nt = 0; nt < 8; nt++) {
                int n = n0 + warp_n + nt * 8 + 2 * tg;
                *(float2*)&C32[(size_t)m * N + n] =
                    make_float2(acc[mt][nt][0], acc[mt][nt][1]);
                *(float2*)&C32[(size_t)(m + 8) * N + n] =
                    make_float2(acc[mt][nt][2], acc[mt][nt][3]);
            }
        }
    } else {
        // CTA-uniform projection selector
        int sel = (n0 < DIM) ? 0 : ((n0 < DIM + KVDIM) ? 1 : 2);
        __half* outp = (sel == 0) ? Qo : ((sel == 1) ? Ko : Vo);
        int ld = (sel == 0) ? DIM : KVDIM;
        int nbase = (sel == 0) ? 0 : ((sel == 1) ? DIM : DIM + KVDIM);
        float mm = (sel == 0) ? mul : 1.0f;
        #pragma unroll
        for (int mt = 0; mt < 4; mt++) {
            int m = m0 + warp_m + mt * 16 + g;
            #pragma unroll
            for (int nt = 0; nt < 8; nt++) {
                int n = n0 + warp_n + nt * 8 + 2 * tg;
                int nc = n - nbase;
                if (sel == 2) {
                    __half2 h0 = __floats2half2_rn(acc[mt][nt][0], acc[mt][nt][1]);
                    __half2 h1 = __floats2half2_rn(acc[mt][nt][2], acc[mt][nt][3]);
                    *(uint32_t*)&outp[(size_t)m * ld + nc] = *(uint32_t*)&h0;
                    *(uint32_t*)&outp[(size_t)(m + 8) * ld + nc] = *(uint32_t*)&h1;
                } else {
                    int i = (nc & 127) >> 1;
                    float c0v = cs[m * 64 + i],       s0v = sn[m * 64 + i];
                    float c1v = cs[(m + 8) * 64 + i], s1v = sn[(m + 8) * 64 + i];
                    float re0 = acc[mt][nt][0] * c0v - acc[mt][nt][1] * s0v;
                    float im0 = acc[mt][nt][0] * s0v + acc[mt][nt][1] * c0v;
                    float re1 = acc[mt][nt][2] * c1v - acc[mt][nt][3] * s1v;
                    float im1 = acc[mt][nt][2] * s1v + acc[mt][nt][3] * c1v;
                    __half2 h0 = __floats2half2_rn(re0 * mm, im0 * mm);
                    __half2 h1 = __floats2half2_rn(re1 * mm, im1 * mm);
                    *(uint32_t*)&outp[(size_t)m * ld + nc] = *(uint32_t*)&h0;
                    *(uint32_t*)&outp[(size_t)(m + 8) * ld + nc] = *(uint32_t*)&h1;
                }
            }
        }
    }
}

// ---------------------------------------------------------------------------
// Flash attention, all-fp16 operands, ldmatrix fragment loads. Occ 3/SM.
// ---------------------------------------------------------------------------
#define FBR 64
#define QKSTR 68     // Q/K row: 64 words + 4 pad (272 B)
#define P16STR 36    // P row: 32 words + 4 pad (144 B)
#define VSTR 36      // Vt row (144 B)
#define REGION0_W (64 * QKSTR)                  // 4352
#define REGION1_W (128 * VSTR)                  // 4608
#define FLASH_SMEM_W (REGION0_W + REGION1_W)    // 8960 words = 35840 B

__global__ __launch_bounds__(128, 3) void flash_kernel(
    const __half* __restrict__ Q16, const __half* __restrict__ K16,
    const __half* __restrict__ Vt, __half* __restrict__ O)
{
    extern __shared__ uint32_t smu[];
    uint32_t* Qh   = smu;
    uint32_t* Ps16 = smu;
    uint32_t* Kh   = smu + REGION0_W;
    uint32_t* VtS  = smu + REGION0_W;
    uint32_t sm_sh  = (uint32_t)__cvta_generic_to_shared(smu);
    uint32_t Ps_sh  = sm_sh;
    uint32_t Kh_sh  = sm_sh + REGION0_W * 4;
    uint32_t VtS_sh = sm_sh + REGION0_W * 4;

    int tid = threadIdx.x;
    int w = tid >> 5, lane = tid & 31;
    int g = lane >> 2, tg = lane & 3;
    int r0 = blockIdx.x * FBR;
    int h = blockIdx.y, kvh = h >> 2;

    uint32_t kb_lane = ((uint32_t)((lane & 7) + ((lane >> 4) & 1) * 8)) * 272
                     + (uint32_t)((lane >> 3) & 1) * 16;
    uint32_t pa_lane = (uint32_t)(lane & 15) * 144
                     + (uint32_t)(lane >> 4) * 16;
    uint32_t vb_lane = ((uint32_t)((lane & 7) + ((lane >> 4) & 1) * 8)) * 144
                     + (uint32_t)((lane >> 3) & 1) * 16;

    for (int t = tid; t < FBR * 16; t += 128) {
        int row = t >> 4, c = t & 15;
        *(uint4*)&Qh[row * QKSTR + c * 4] =
            *(const uint4*)&Q16[(size_t)(r0 + row) * DIM + h * HD + c * 8];
    }
    __syncthreads();

    uint32_t qa[8][4];
    {
        int mrow = (16 * w + g) * QKSTR;
        #pragma unroll
        for (int ks = 0; ks < 8; ks++) {
            int k0 = ks * 8;
            qa[ks][0] = Qh[mrow + k0 + tg];
            qa[ks][1] = Qh[mrow + 8 * QKSTR + k0 + tg];
            qa[ks][2] = Qh[mrow + k0 + tg + 4];
            qa[ks][3] = Qh[mrow + 8 * QKSTR + k0 + tg + 4];
        }
    }
    __syncthreads();

    float m0 = -1e30f, m1 = -1e30f, l0 = 0.f, l1 = 0.f;
    float o[16][4];
    #pragma unroll
    for (int nt = 0; nt < 16; nt++)
        #pragma unroll
        for (int i = 0; i < 4; i++) o[nt][i] = 0.f;

    int qrow_g = r0 + 16 * w + g;
    int diag = blockIdx.x;

    for (int kt = 0; kt <= diag; kt++) {
        int c0 = kt * FBR;
        __syncthreads();
        for (int t = tid; t < FBR * 16; t += 128) {
            int row = t >> 4, c = t & 15;
            *(uint4*)&Kh[row * QKSTR + c * 4] =
                *(const uint4*)&K16[(size_t)(c0 + row) * KVDIM + kvh * HD + c * 8];
        }
        __syncthreads();

        float sacc[8][4];
        #pragma unroll
        for (int nt = 0; nt < 8; nt++)
            #pragma unroll
            for (int i = 0; i < 4; i++) sacc[nt][i] = 0.f;

        #pragma unroll
        for (int ks = 0; ks < 8; ks++) {
            #pragma unroll
            for (int p = 0; p < 4; p++) {
                uint32_t b0, b1, b2, b3;
                ldsm_x4(b0, b1, b2, b3,
                        Kh_sh + (16 * p) * 272 + ks * 32 + kb_lane);
                uint32_t bb0[2] = { b0, b1 };
                uint32_t bb1[2] = { b2, b3 };
                mma_f16(sacc[2 * p], qa[ks], bb0);
                mma_f16(sacc[2 * p + 1], qa[ks], bb1);
            }
        }

        if (kt == diag) {
            #pragma unroll
            for (int nt = 0; nt < 8; nt++) {
                int col = c0 + 8 * nt + 2 * tg;
                if (col > qrow_g)          sacc[nt][0] = -1e30f;
                if (col + 1 > qrow_g)      sacc[nt][1] = -1e30f;
                if (col > qrow_g + 8)      sacc[nt][2] = -1e30f;
                if (col + 1 > qrow_g + 8)  sacc[nt][3] = -1e30f;
            }
        }

        float mx0 = -1e30f, mx1 = -1e30f;
        #pragma unroll
        for (int nt = 0; nt < 8; nt++) {
            mx0 = fmaxf(mx0, fmaxf(sacc[nt][0], sacc[nt][1]));
            mx1 = fmaxf(mx1, fmaxf(sacc[nt][2], sacc[nt][3]));
        }
        #pragma unroll
        for (int off = 2; off >= 1; off >>= 1) {
            mx0 = fmaxf(mx0, __shfl_xor_sync(0xffffffffu, mx0, off));
            mx1 = fmaxf(mx1, __shfl_xor_sync(0xffffffffu, mx1, off));
        }
        float mn0 = fmaxf(m0, mx0), mn1 = fmaxf(m1, mx1);
        float cor0 = __expf(m0 - mn0), cor1 = __expf(m1 - mn1);
        float ps0 = 0.f, ps1 = 0.f;
        #pragma unroll
        for (int nt = 0; nt < 8; nt++) {
            sacc[nt][0] = __expf(sacc[nt][0] - mn0);
            sacc[nt][1] = __expf(sacc[nt][1] - mn0);
            sacc[nt][2] = __expf(sacc[nt][2] - mn1);
            sacc[nt][3] = __expf(sacc[nt][3] - mn1);
            ps0 += sacc[nt][0] + sacc[nt][1];
            ps1 += sacc[nt][2] + sacc[nt][3];
        }
        #pragma unroll
        for (int off = 2; off >= 1; off >>= 1) {
            ps0 += __shfl_xor_sync(0xffffffffu, ps0, off);
            ps1 += __shfl_xor_sync(0xffffffffu, ps1, off);
        }
        l0 = l0 * cor0 + ps0;  m0 = mn0;
        l1 = l1 * cor1 + ps1;  m1 = mn1;
        #pragma unroll
        for (int nt = 0; nt < 16; nt++) {
            o[nt][0] *= cor0; o[nt][1] *= cor0;
            o[nt][2] *= cor1; o[nt][3] *= cor1;
        }
        #pragma unroll
        for (int nt = 0; nt < 8; nt++) {
            __half2 p0 = __floats2half2_rn(sacc[nt][0], sacc[nt][1]);
            __half2 p1 = __floats2half2_rn(sacc[nt][2], sacc[nt][3]);
            Ps16[(16 * w + g) * P16STR + nt * 4 + tg] = *(uint32_t*)&p0;
            Ps16[(16 * w + g + 8) * P16STR + nt * 4 + tg] = *(uint32_t*)&p1;
        }

        __syncthreads();
        for (int t = tid; t < 128 * 8; t += 128) {
            int r = t >> 3, c = t & 7;
            *(uint4*)&VtS[r * VSTR + c * 4] =
                *(const uint4*)&Vt[(size_t)(kvh * HD + r) * SEQ + c0 + c * 8];
        }
        __syncthreads();

        #pragma unroll
        for (int ks = 0; ks < 4; ks++) {
            uint32_t a[4];
            ldsm_x4(a[0], a[1], a[2], a[3],
                    Ps_sh + (16 * w) * 144 + ks * 32 + pa_lane);
            #pragma unroll
            for (int p = 0; p < 8; p++) {
                uint32_t b0, b1, b2, b3;
                ldsm_x4(b0, b1, b2, b3,
                        VtS_sh + (16 * p) * 144 + ks * 32 + vb_lane);
                uint32_t bb0[2] = { b0, b1 };
                uint32_t bb1[2] = { b2, b3 };
                mma_f16(o[2 * p], a, bb0);
                mma_f16(o[2 * p + 1], a, bb1);
            }
        }
    }

    float i0 = 1.f / l0, i1 = 1.f / l1;
    #pragma unroll
    for (int nt = 0; nt < 16; nt++) {
        int col = h * HD + 8 * nt + 2 * tg;
        __half2 h0 = __floats2half2_rn(o[nt][0] * i0, o[nt][1] * i0);
        __half2 h1 = __floats2half2_rn(o[nt][2] * i1, o[nt][3] * i1);
        *(uint32_t*)&O[(size_t)qrow_g * DIM + col] = *(uint32_t*)&h0;
        *(uint32_t*)&O[(size_t)(qrow_g + 8) * DIM + col] = *(uint32_t*)&h1;
    }
}

// ---------------------------------------------------------------------------
// Launch
// ---------------------------------------------------------------------------
extern "C" void kernel_launch(void* const* d_in, const int* in_sizes, int n_in,
                              void* d_out, int out_size)
{
    const float* x  = (const float*)d_in[0];
    const float* wq = (const float*)d_in[1];
    const float* wk = (const float*)d_in[2];
    const float* wv = (const float*)d_in[3];
    const float* wo = (const float*)d_in[4];
    const float* fc = (const float*)d_in[5];
    const float* fs = (const float*)d_in[6];

    __half *Q16, *K16, *V16, *VT, *A16, *X16, *WqkvT, *WoT;
    cudaGetSymbolAddress((void**)&Q16, g_Q16);
    cudaGetSymbolAddress((void**)&K16, g_K16);
    cudaGetSymbolAddress((void**)&V16, g_V16);
    cudaGetSymbolAddress((void**)&VT, g_vT);
    cudaGetSymbolAddress((void**)&A16, g_attn16);
    cudaGetSymbolAddress((void**)&X16, g_x16);
    cudaGetSymbolAddress((void**)&WqkvT, g_wqkvT);
    cudaGetSymbolAddress((void**)&WoT, g_woT);

    // Pre-passes
    convert_half_kernel<<<SEQ * DIM / 4 / 256, 256>>>(x, X16, SEQ * DIM);
    dim3 tb(32, 8);
    transpose_half_kernel<<<dim3(DIM / 32, DIM / 32), tb>>>(wq, WqkvT, DIM, DIM);
    transpose_half_kernel<<<dim3(KVDIM / 32, DIM / 32), tb>>>(
        wk, WqkvT + (size_t)DIM * DIM, DIM, KVDIM);
    transpose_half_kernel<<<dim3(KVDIM / 32, DIM / 32), tb>>>(
        wv, WqkvT + (size_t)(DIM + KVDIM) * DIM, DIM, KVDIM);
    transpose_half_kernel<<<dim3(DIM / 32, DIM / 32), tb>>>(wo, WoT, DIM, DIM);

    int gsm = 4 * TILE_WORDS * (int)sizeof(uint32_t);
    cudaFuncSetAttribute(gemm_epi_kernel<0>,
                         cudaFuncAttributeMaxDynamicSharedMemorySize, gsm);
    cudaFuncSetAttribute(gemm_epi_kernel<3>,
                         cudaFuncAttributeMaxDynamicSharedMemorySize, gsm);

    const float qscale = 0.08838834764831845f;   // 1/sqrt(128)

    // Fused Q|K|V projection: one launch, 768 CTAs.
    gemm_epi_kernel<3><<<dim3(NQKV / GBN, SEQ / GBM), 128, gsm>>>(
        X16, WqkvT, nullptr, Q16, K16, V16, fc, fs, SEQ, NQKV, DIM, qscale);

    // V -> V^T (fp16)
    transpose_h2h_kernel<<<dim3(KVDIM / 32, SEQ / 32), tb>>>(V16, VT, SEQ, KVDIM);

    // Flash attention (all-fp16 operands) -> fp16 attn
    int fsm = FLASH_SMEM_W * (int)sizeof(uint32_t);
    cudaFuncSetAttribute(flash_kernel,
                         cudaFuncAttributeMaxDynamicSharedMemorySize, fsm);
    flash_kernel<<<dim3(SEQ / FBR, NH), 128, fsm>>>(Q16, K16, VT, A16);

    // Output projection -> d_out (fp32)
    gemm_epi_kernel<0><<<dim3(DIM / GBN, SEQ / GBM), 128, gsm>>>(
        A16, WoT, (float*)d_out, nullptr, nullptr, nullptr, nullptr, nullptr,
        SEQ, DIM, DIM, 1.0f);
}

// round 14
// speedup vs baseline: 7.8412x; 1.0365x over previous
#include <cuda_runtime.h>
#include <cuda_fp16.h>
#include <math.h>
#include <stdint.h>

#define SEQ 2048
#define DIM 4096
#define NH 32
#define NKV 8
#define HD 128
#define KVDIM 1024
#define NQKV (DIM + 2 * KVDIM)    // 6144 fused projection width

// Scratch (allocation-free rule: device globals)
__device__ __half g_Q16[SEQ * DIM];         // roped+scaled Q, fp16
__device__ __half g_K16[SEQ * KVDIM];       // roped K, fp16
__device__ __half g_V16[SEQ * KVDIM];       // V, fp16
__device__ __half g_vT[KVDIM * SEQ];        // V^T fp16 [KVDIM][SEQ]
__device__ __half g_attn16[SEQ * DIM];      // flash output, fp16
__device__ __half g_x16[SEQ * DIM];         // x, fp16
__device__ __half g_wqkvT[NQKV * DIM];      // [Wq^T; Wk^T; Wv^T] fp16
__device__ __half g_woT[DIM * DIM];

// ---------------------------------------------------------------------------
// Helpers
// ---------------------------------------------------------------------------
__device__ __forceinline__ void mma_f16(float c[4], const uint32_t a[4],
                                        const uint32_t b[2]) {
    asm volatile(
        "mma.sync.aligned.m16n8k16.row.col.f32.f16.f16.f32 "
        "{%0,%1,%2,%3}, {%4,%5,%6,%7}, {%8,%9}, {%0,%1,%2,%3};"
        : "+f"(c[0]), "+f"(c[1]), "+f"(c[2]), "+f"(c[3])
        : "r"(a[0]), "r"(a[1]), "r"(a[2]), "r"(a[3]), "r"(b[0]), "r"(b[1]));
}

__device__ __forceinline__ void ldsm_x4(uint32_t& r0, uint32_t& r1,
                                        uint32_t& r2, uint32_t& r3,
                                        uint32_t addr) {
    asm volatile(
        "ldmatrix.sync.aligned.m8n8.x4.shared.b16 {%0,%1,%2,%3}, [%4];"
        : "=r"(r0), "=r"(r1), "=r"(r2), "=r"(r3) : "r"(addr));
}

__device__ __forceinline__ void cpa16(uint32_t smem_addr, const void* gptr) {
    asm volatile("cp.async.cg.shared.global [%0], [%1], 16;"
                 :: "r"(smem_addr), "l"(gptr));
}
__device__ __forceinline__ void cpa_commit() {
    asm volatile("cp.async.commit_group;");
}
template <int N>
__device__ __forceinline__ void cpa_wait() {
    asm volatile("cp.async.wait_group %0;" :: "n"(N));
}

// ---------------------------------------------------------------------------
// Pre-passes
// ---------------------------------------------------------------------------
__global__ void convert_half_kernel(const float* __restrict__ in,
                                    __half* __restrict__ out, int n)
{
    int i = (blockIdx.x * blockDim.x + threadIdx.x) * 4;
    if (i >= n) return;
    float4 v = *(const float4*)&in[i];
    __half2 h0 = __floats2half2_rn(v.x, v.y);
    __half2 h1 = __floats2half2_rn(v.z, v.w);
    *(uint2*)&out[i] = make_uint2(*(uint32_t*)&h0, *(uint32_t*)&h1);
}

// in [R][C] fp32 -> out [C][R] fp16
__global__ void transpose_half_kernel(const float* __restrict__ in,
                                      __half* __restrict__ out, int R, int C)
{
    __shared__ float tile[32][33];
    int c0 = blockIdx.x * 32, r0 = blockIdx.y * 32;
    int tx = threadIdx.x, ty = threadIdx.y;
    #pragma unroll
    for (int j = 0; j < 32; j += 8)
        tile[ty + j][tx] = in[(size_t)(r0 + ty + j) * C + c0 + tx];
    __syncthreads();
    #pragma unroll
    for (int j = 0; j < 32; j += 8)
        out[(size_t)(c0 + ty + j) * R + r0 + tx] = __float2half(tile[tx][ty + j]);
}

// in [R][C] fp16 -> out [C][R] fp16
__global__ void transpose_h2h_kernel(const __half* __restrict__ in,
                                     __half* __restrict__ out, int R, int C)
{
    __shared__ __half tile[32][34];
    int c0 = blockIdx.x * 32, r0 = blockIdx.y * 32;
    int tx = threadIdx.x, ty = threadIdx.y;
    #pragma unroll
    for (int j = 0; j < 32; j += 8)
        tile[ty + j][tx] = in[(size_t)(r0 + ty + j) * C + c0 + tx];
    __syncthreads();
    #pragma unroll
    for (int j = 0; j < 32; j += 8)
        out[(size_t)(c0 + ty + j) * R + r0 + tx] = tile[tx][ty + j];
}

// ---------------------------------------------------------------------------
// FP16 GEMM with fused epilogues (unchanged from round 13).
// MODE 0: C32 = A @ BT^T (fp32 out)                         [O projection]
// MODE 3: merged QKV, N=6144 (Q rope*mul | K rope | V fp16)
// ---------------------------------------------------------------------------
#define GBM 128
#define GBN 128
#define GKC 64
#define HSTR 36
#define TILE_WORDS (128 * HSTR)

template <int MODE>
__global__ __launch_bounds__(128, 2) void gemm_epi_kernel(
    const __half* __restrict__ A, const __half* __restrict__ BT,
    float* __restrict__ C32, __half* __restrict__ Qo,
    __half* __restrict__ Ko, __half* __restrict__ Vo,
    const float* __restrict__ cs, const float* __restrict__ sn,
    int M, int N, int K, float mul)
{
    extern __shared__ uint32_t smg[];
    uint32_t sbase = (uint32_t)__cvta_generic_to_shared(smg);

    int tid = threadIdx.x;
    int wid = tid >> 5, lane = tid & 31;
    int g = lane >> 2, tg = lane & 3;
    int warp_m = (wid >> 1) * 64;
    int warp_n = (wid & 1) * 64;
    int m0 = blockIdx.y * GBM, n0 = blockIdx.x * GBN;

    uint32_t a_lane = (uint32_t)(lane & 15) * 144 + (uint32_t)(lane >> 4) * 16;
    uint32_t b_lane = ((uint32_t)((lane & 7) + ((lane >> 4) & 1) * 8)) * 144
                    + (uint32_t)((lane >> 3) & 1) * 16;

    float acc[4][8][4];
    #pragma unroll
    for (int mt = 0; mt < 4; mt++)
        #pragma unroll
        for (int nt = 0; nt < 8; nt++)
            #pragma unroll
            for (int i = 0; i < 4; i++) acc[mt][nt][i] = 0.f;

    int niter = K / GKC;

    #define ISSUE_COPY(IT, STG)                                               \
    do {                                                                      \
        uint32_t aOff = sbase + (uint32_t)(STG) * (2 * TILE_WORDS) * 4;       \
        uint32_t bOff = aOff + TILE_WORDS * 4;                                \
        const __half* Ab = A + (size_t)m0 * K + (IT) * GKC;                   \
        const __half* Bb = BT + (size_t)n0 * K + (IT) * GKC;                  \
        _Pragma("unroll")                                                     \
        for (int i = 0; i < 8; i++) {                                         \
            int c = tid + i * 128;                                            \
            int r = c >> 3, cc = c & 7;                                       \
            cpa16(aOff + r * 144 + cc * 16, Ab + (size_t)r * K + cc * 8);     \
        }                                                                     \
        _Pragma("unroll")                                                     \
        for (int i = 0; i < 8; i++) {                                         \
            int c = tid + i * 128;                                            \
            int r = c >> 3, cc = c & 7;                                       \
            cpa16(bOff + r * 144 + cc * 16, Bb + (size_t)r * K + cc * 8);     \
        }                                                                     \
        cpa_commit();                                                         \
    } while (0)

    ISSUE_COPY(0, 0);

    for (int it = 0; it < niter; it++) {
        int cur = it & 1;
        if (it + 1 < niter) {
            ISSUE_COPY(it + 1, (it + 1) & 1);
            cpa_wait<1>();
        } else {
            cpa_wait<0>();
        }
        __syncthreads();

        uint32_t As_sh = sbase + (uint32_t)cur * (2 * TILE_WORDS) * 4;
        uint32_t Bs_sh = As_sh + TILE_WORDS * 4;

        #pragma unroll
        for (int ks = 0; ks < 4; ks++) {
            uint32_t aR[4][4];
            #pragma unroll
            for (int mt = 0; mt < 4; mt++)
                ldsm_x4(aR[mt][0], aR[mt][1], aR[mt][2], aR[mt][3],
                        As_sh + (warp_m + mt * 16) * 144 + ks * 32 + a_lane);
            uint32_t bR[8][2];
            #pragma unroll
            for (int p = 0; p < 4; p++)
                ldsm_x4(bR[2 * p][0], bR[2 * p][1],
                        bR[2 * p + 1][0], bR[2 * p + 1][1],
                        Bs_sh + (warp_n + 16 * p) * 144 + ks * 32 + b_lane);
            #pragma unroll
            for (int mt = 0; mt < 4; mt++)
                #pragma unroll
                for (int nt = 0; nt < 8; nt++)
                    mma_f16(acc[mt][nt], aR[mt], bR[nt]);
        }
        __syncthreads();
    }

    if (MODE == 0) {
        #pragma unroll
        for (int mt = 0; mt < 4; mt++) {
            int m = m0 + warp_m + mt * 16 + g;
            #pragma unroll
            for (int nt = 0; nt < 8; nt++) {
                int n = n0 + warp_n + nt * 8 + 2 * tg;
                *(float2*)&C32[(size_t)m * N + n] =
                    make_float2(acc[mt][nt][0], acc[mt][nt][1]);
                *(float2*)&C32[(size_t)(m + 8) * N + n] =
                    make_float2(acc[mt][nt][2], acc[mt][nt][3]);
            }
        }
    } else {
        int sel = (n0 < DIM) ? 0 : ((n0 < DIM + KVDIM) ? 1 : 2);
        __half* outp = (sel == 0) ? Qo : ((sel == 1) ? Ko : Vo);
        int ld = (sel == 0) ? DIM : KVDIM;
        int nbase = (sel == 0) ? 0 : ((sel == 1) ? DIM : DIM + KVDIM);
        float mm = (sel == 0) ? mul : 1.0f;
        #pragma unroll
        for (int mt = 0; mt < 4; mt++) {
            int m = m0 + warp_m + mt * 16 + g;
            #pragma unroll
            for (int nt = 0; nt < 8; nt++) {
                int n = n0 + warp_n + nt * 8 + 2 * tg;
                int nc = n - nbase;
                if (sel == 2) {
                    __half2 h0 = __floats2half2_rn(acc[mt][nt][0], acc[mt][nt][1]);
                    __half2 h1 = __floats2half2_rn(acc[mt][nt][2], acc[mt][nt][3]);
                    *(uint32_t*)&outp[(size_t)m * ld + nc] = *(uint32_t*)&h0;
                    *(uint32_t*)&outp[(size_t)(m + 8) * ld + nc] = *(uint32_t*)&h1;
                } else {
                    int i = (nc & 127) >> 1;
                    float c0v = cs[m * 64 + i],       s0v = sn[m * 64 + i];
                    float c1v = cs[(m + 8) * 64 + i], s1v = sn[(m + 8) * 64 + i];
                    float re0 = acc[mt][nt][0] * c0v - acc[mt][nt][1] * s0v;
                    float im0 = acc[mt][nt][0] * s0v + acc[mt][nt][1] * c0v;
                    float re1 = acc[mt][nt][2] * c1v - acc[mt][nt][3] * s1v;
                    float im1 = acc[mt][nt][2] * s1v + acc[mt][nt][3] * c1v;
                    __half2 h0 = __floats2half2_rn(re0 * mm, im0 * mm);
                    __half2 h1 = __floats2half2_rn(re1 * mm, im1 * mm);
                    *(uint32_t*)&outp[(size_t)m * ld + nc] = *(uint32_t*)&h0;
                    *(uint32_t*)&outp[(size_t)(m + 8) * ld + nc] = *(uint32_t*)&h1;
                }
            }
        }
    }
}

// ---------------------------------------------------------------------------
// Flash attention, all-fp16, cp.async-pipelined K/V, reversed tile order.
// smem (words): P 2304 | K0 4352 | K1 4352 | V 4608  = 15616 w = 62464 B.
// Q stages through K0 before the mainloop (dead after frag cache).
// Per tile: [wait K(kt); sync] [issue V(kt); issue K(kt+1)] S-mma softmax
//           P-write [wait V; sync] PV.   2 syncs/tile, loads hidden.
// ---------------------------------------------------------------------------
#define FBR 64
#define QKSTR 68     // Q/K row stride in words (272 B)
#define P16STR 36    // P row stride in words (144 B)
#define VSTR 36      // Vt row stride (144 B)
#define P_OFF 0
#define K_OFF0 2304
#define K_OFF1 6656
#define V_OFF 11008
#define FLASH_SMEM_W 15616

__global__ __launch_bounds__(128, 3) void flash_kernel(
    const __half* __restrict__ Q16, const __half* __restrict__ K16,
    const __half* __restrict__ Vt, __half* __restrict__ O)
{
    extern __shared__ uint32_t smu[];
    uint32_t* Ps16 = smu + P_OFF;
    uint32_t* Qh   = smu + K_OFF0;          // Q staging (dead after frags)
    uint32_t sm_sh  = (uint32_t)__cvta_generic_to_shared(smu);
    uint32_t Ps_sh  = sm_sh + P_OFF * 4;
    uint32_t K_sh[2] = { sm_sh + K_OFF0 * 4, sm_sh + K_OFF1 * 4 };
    uint32_t V_sh   = sm_sh + V_OFF * 4;

    int tid = threadIdx.x;
    int w = tid >> 5, lane = tid & 31;
    int g = lane >> 2, tg = lane & 3;
    int h = blockIdx.y, kvh = h >> 2;
    int diag = (int)gridDim.x - 1 - (int)blockIdx.x;   // longest CTAs first
    int r0 = diag * FBR;

    uint32_t kb_lane = ((uint32_t)((lane & 7) + ((lane >> 4) & 1) * 8)) * 272
                     + (uint32_t)((lane >> 3) & 1) * 16;
    uint32_t pa_lane = (uint32_t)(lane & 15) * 144
                     + (uint32_t)(lane >> 4) * 16;
    uint32_t vb_lane = ((uint32_t)((lane & 7) + ((lane >> 4) & 1) * 8)) * 144
                     + (uint32_t)((lane >> 3) & 1) * 16;

    // Stage Q tile into K0 region, cache fragments
    for (int t = tid; t < FBR * 16; t += 128) {
        int row = t >> 4, c = t & 15;
        *(uint4*)&Qh[row * QKSTR + c * 4] =
            *(const uint4*)&Q16[(size_t)(r0 + row) * DIM + h * HD + c * 8];
    }
    __syncthreads();

    uint32_t qa[8][4];
    {
        int mrow = (16 * w + g) * QKSTR;
        #pragma unroll
        for (int ks = 0; ks < 8; ks++) {
            int k0 = ks * 8;
            qa[ks][0] = Qh[mrow + k0 + tg];
            qa[ks][1] = Qh[mrow + 8 * QKSTR + k0 + tg];
            qa[ks][2] = Qh[mrow + k0 + tg + 4];
            qa[ks][3] = Qh[mrow + 8 * QKSTR + k0 + tg + 4];
        }
    }
    __syncthreads();   // Qh dead; K0 free for pipeline

    // cp.async tile loaders
    #define ISSUE_K(KT, KSH)                                                  \
    do {                                                                      \
        const __half* Kb = K16 + (size_t)((KT) * FBR) * KVDIM + kvh * HD;     \
        _Pragma("unroll")                                                     \
        for (int i = 0; i < 8; i++) {                                         \
            int c = tid + i * 128;                                            \
            int r = c >> 4, cc = c & 15;                                      \
            cpa16((KSH) + r * 272 + cc * 16, Kb + (size_t)r * KVDIM + cc * 8);\
        }                                                                     \
        cpa_commit();                                                         \
    } while (0)

    #define ISSUE_V(KT)                                                      \
    do {                                                                     \
        const __half* Vb = Vt + (size_t)(kvh * HD) * SEQ + (KT) * FBR;       \
        _Pragma("unroll")                                                    \
        for (int i = 0; i < 8; i++) {                                        \
            int c = tid + i * 128;                                           \
            int r = c >> 3, cc = c & 7;                                      \
            cpa16(V_sh + r * 144 + cc * 16, Vb + (size_t)r * SEQ + cc * 8);  \
        }                                                                    \
        cpa_commit();                                                        \
    } while (0)

    float m0 = -1e30f, m1 = -1e30f, l0 = 0.f, l1 = 0.f;
    float o[16][4];
    #pragma unroll
    for (int nt = 0; nt < 16; nt++)
        #pragma unroll
        for (int i = 0; i < 4; i++) o[nt][i] = 0.f;

    int qrow_g = r0 + 16 * w + g;

    ISSUE_K(0, K_sh[0]);

    for (int kt = 0; kt <= diag; kt++) {
        int c0 = kt * FBR;
        int cur = kt & 1;
        uint32_t Kh_sh = K_sh[cur];

        cpa_wait<0>();     // K(kt) landed (and any stragglers)
        __syncthreads();   // K visible; V buffer free (prev PV done)

        // Hide V(kt) and K(kt+1) under S-mma + softmax
        ISSUE_V(kt);                               // group: V
        if (kt < diag) ISSUE_K(kt + 1, K_sh[cur ^ 1]);   // group: K-next

        // ---- S = Q @ K^T ----
        float sacc[8][4];
        #pragma unroll
        for (int nt = 0; nt < 8; nt++)
            #pragma unroll
            for (int i = 0; i < 4; i++) sacc[nt][i] = 0.f;

        #pragma unroll
        for (int ks = 0; ks < 8; ks++) {
            #pragma unroll
            for (int p = 0; p < 4; p++) {
                uint32_t b0, b1, b2, b3;
                ldsm_x4(b0, b1, b2, b3,
                        Kh_sh + (16 * p) * 272 + ks * 32 + kb_lane);
                uint32_t bb0[2] = { b0, b1 };
                uint32_t bb1[2] = { b2, b3 };
                mma_f16(sacc[2 * p], qa[ks], bb0);
                mma_f16(sacc[2 * p + 1], qa[ks], bb1);
            }
        }

        if (kt == diag) {
            #pragma unroll
            for (int nt = 0; nt < 8; nt++) {
                int col = c0 + 8 * nt + 2 * tg;
                if (col > qrow_g)          sacc[nt][0] = -1e30f;
                if (col + 1 > qrow_g)      sacc[nt][1] = -1e30f;
                if (col > qrow_g + 8)      sacc[nt][2] = -1e30f;
                if (col + 1 > qrow_g + 8)  sacc[nt][3] = -1e30f;
            }
        }

        // ---- online softmax ----
        float mx0 = -1e30f, mx1 = -1e30f;
        #pragma unroll
        for (int nt = 0; nt < 8; nt++) {
            mx0 = fmaxf(mx0, fmaxf(sacc[nt][0], sacc[nt][1]));
            mx1 = fmaxf(mx1, fmaxf(sacc[nt][2], sacc[nt][3]));
        }
        #pragma unroll
        for (int off = 2; off >= 1; off >>= 1) {
            mx0 = fmaxf(mx0, __shfl_xor_sync(0xffffffffu, mx0, off));
            mx1 = fmaxf(mx1, __shfl_xor_sync(0xffffffffu, mx1, off));
        }
        float mn0 = fmaxf(m0, mx0), mn1 = fmaxf(m1, mx1);
        float cor0 = __expf(m0 - mn0), cor1 = __expf(m1 - mn1);
        float ps0 = 0.f, ps1 = 0.f;
        #pragma unroll
        for (int nt = 0; nt < 8; nt++) {
            sacc[nt][0] = __expf(sacc[nt][0] - mn0);
            sacc[nt][1] = __expf(sacc[nt][1] - mn0);
            sacc[nt][2] = __expf(sacc[nt][2] - mn1);
            sacc[nt][3] = __expf(sacc[nt][3] - mn1);
            ps0 += sacc[nt][0] + sacc[nt][1];
            ps1 += sacc[nt][2] + sacc[nt][3];
        }
        #pragma unroll
        for (int off = 2; off >= 1; off >>= 1) {
            ps0 += __shfl_xor_sync(0xffffffffu, ps0, off);
            ps1 += __shfl_xor_sync(0xffffffffu, ps1, off);
        }
        l0 = l0 * cor0 + ps0;  m0 = mn0;
        l1 = l1 * cor1 + ps1;  m1 = mn1;
        #pragma unroll
        for (int nt = 0; nt < 16; nt++) {
            o[nt][0] *= cor0; o[nt][1] *= cor0;
            o[nt][2] *= cor1; o[nt][3] *= cor1;
        }
        // P -> smem as fp16 (own warp's rows only)
        #pragma unroll
        for (int nt = 0; nt < 8; nt++) {
            __half2 p0 = __floats2half2_rn(sacc[nt][0], sacc[nt][1]);
            __half2 p1 = __floats2half2_rn(sacc[nt][2], sacc[nt][3]);
            Ps16[(16 * w + g) * P16STR + nt * 4 + tg] = *(uint32_t*)&p0;
            Ps16[(16 * w + g + 8) * P16STR + nt * 4 + tg] = *(uint32_t*)&p1;
        }

        // V(kt) done (leave K(kt+1) in flight), P visible
        if (kt < diag) cpa_wait<1>(); else cpa_wait<0>();
        __syncthreads();

        // ---- O += P @ V ----
        #pragma unroll
        for (int ks = 0; ks < 4; ks++) {
            uint32_t a[4];
            ldsm_x4(a[0], a[1], a[2], a[3],
                    Ps_sh + (16 * w) * 144 + ks * 32 + pa_lane);
            #pragma unroll
            for (int p = 0; p < 8; p++) {
                uint32_t b0, b1, b2, b3;
                ldsm_x4(b0, b1, b2, b3,
                        V_sh + (16 * p) * 144 + ks * 32 + vb_lane);
                uint32_t bb0[2] = { b0, b1 };
                uint32_t bb1[2] = { b2, b3 };
                mma_f16(o[2 * p], a, bb0);
                mma_f16(o[2 * p + 1], a, bb1);
            }
        }
    }

    float i0 = 1.f / l0, i1 = 1.f / l1;
    #pragma unroll
    for (int nt = 0; nt < 16; nt++) {
        int col = h * HD + 8 * nt + 2 * tg;
        __half2 h0 = __floats2half2_rn(o[nt][0] * i0, o[nt][1] * i0);
        __half2 h1 = __floats2half2_rn(o[nt][2] * i1, o[nt][3] * i1);
        *(uint32_t*)&O[(size_t)qrow_g * DIM + col] = *(uint32_t*)&h0;
        *(uint32_t*)&O[(size_t)(qrow_g + 8) * DIM + col] = *(uint32_t*)&h1;
    }
}

// ---------------------------------------------------------------------------
// Launch
// ---------------------------------------------------------------------------
extern "C" void kernel_launch(void* const* d_in, const int* in_sizes, int n_in,
                              void* d_out, int out_size)
{
    const float* x  = (const float*)d_in[0];
    const float* wq = (const float*)d_in[1];
    const float* wk = (const float*)d_in[2];
    const float* wv = (const float*)d_in[3];
    const float* wo = (const float*)d_in[4];
    const float* fc = (const float*)d_in[5];
    const float* fs = (const float*)d_in[6];

    __half *Q16, *K16, *V16, *VT, *A16, *X16, *WqkvT, *WoT;
    cudaGetSymbolAddress((void**)&Q16, g_Q16);
    cudaGetSymbolAddress((void**)&K16, g_K16);
    cudaGetSymbolAddress((void**)&V16, g_V16);
    cudaGetSymbolAddress((void**)&VT, g_vT);
    cudaGetSymbolAddress((void**)&A16, g_attn16);
    cudaGetSymbolAddress((void**)&X16, g_x16);
    cudaGetSymbolAddress((void**)&WqkvT, g_wqkvT);
    cudaGetSymbolAddress((void**)&WoT, g_woT);

    // Pre-passes
    convert_half_kernel<<<SEQ * DIM / 4 / 256, 256>>>(x, X16, SEQ * DIM);
    dim3 tb(32, 8);
    transpose_half_kernel<<<dim3(DIM / 32, DIM / 32), tb>>>(wq, WqkvT, DIM, DIM);
    transpose_half_kernel<<<dim3(KVDIM / 32, DIM / 32), tb>>>(
        wk, WqkvT + (size_t)DIM * DIM, DIM, KVDIM);
    transpose_half_kernel<<<dim3(KVDIM / 32, DIM / 32), tb>>>(
        wv, WqkvT + (size_t)(DIM + KVDIM) * DIM, DIM, KVDIM);
    transpose_half_kernel<<<dim3(DIM / 32, DIM / 32), tb>>>(wo, WoT, DIM, DIM);

    int gsm = 4 * TILE_WORDS * (int)sizeof(uint32_t);
    cudaFuncSetAttribute(gemm_epi_kernel<0>,
                         cudaFuncAttributeMaxDynamicSharedMemorySize, gsm);
    cudaFuncSetAttribute(gemm_epi_kernel<3>,
                         cudaFuncAttributeMaxDynamicSharedMemorySize, gsm);

    const float qscale = 0.08838834764831845f;   // 1/sqrt(128)

    // Fused Q|K|V projection: one launch, 768 CTAs.
    gemm_epi_kernel<3><<<dim3(NQKV / GBN, SEQ / GBM), 128, gsm>>>(
        X16, WqkvT, nullptr, Q16, K16, V16, fc, fs, SEQ, NQKV, DIM, qscale);

    // V -> V^T (fp16)
    transpose_h2h_kernel<<<dim3(KVDIM / 32, SEQ / 32), tb>>>(V16, VT, SEQ, KVDIM);

    // Flash attention (pipelined) -> fp16 attn
    int fsm = FLASH_SMEM_W * (int)sizeof(uint32_t);
    cudaFuncSetAttribute(flash_kernel,
                         cudaFuncAttributeMaxDynamicSharedMemorySize, fsm);
    flash_kernel<<<dim3(SEQ / FBR, NH), 128, fsm>>>(Q16, K16, VT, A16);

    // Output projection -> d_out (fp32)
    gemm_epi_kernel<0><<<dim3(DIM / GBN, SEQ / GBM), 128, gsm>>>(
        A16, WoT, (float*)d_out, nullptr, nullptr, nullptr, nullptr, nullptr,
        SEQ, DIM, DIM, 1.0f);
}